// round 1
// baseline (speedup 1.0000x reference)
#include <cuda_runtime.h>
#include <math_constants.h>

// Problem constants
#define Bc    2
#define SQc   2048
#define SKVc  2048
#define Dc    1024
#define Hc    1024
#define NHc   16
#define HDc   64
#define Mrows (Bc * SQc)   // 4096

// Scratch (device globals: allocation-free)
__device__ float g_Q[(size_t)Mrows * Hc];
__device__ float g_K[(size_t)Mrows * Hc];
__device__ float g_V[(size_t)Mrows * Hc];
__device__ float g_A[(size_t)Mrows * Hc];
__device__ float g_maskbias[Bc * SKVc];
__device__ int   g_mask_kind;   // 0 = uint8/bool, 1 = int32, 2 = float32

// ---------------------------------------------------------------------------
// Mask dtype detection. We may be handed the bool mask as uint8 (4096 B),
// int32 (16 KB) or float32 (16 KB). Reading the first 4096 bytes is safe in
// all three cases. Byte-position-mod-4 zero patterns disambiguate:
//   int32 0/1   : bytes at p%4 in {1,2,3} are all zero
//   float32 0/1 : bytes at p%4 in {0,1} are all zero (1.0f = 00 00 80 3f)
//   uint8 bool  : nonzero bytes appear at all positions
// ---------------------------------------------------------------------------
__global__ void detect_mask_kernel(const unsigned char* __restrict__ m) {
    __shared__ int nz[4];
    if (threadIdx.x < 4) nz[threadIdx.x] = 0;
    __syncthreads();
    for (int p = threadIdx.x; p < Bc * SKVc; p += blockDim.x) {
        if (m[p]) atomicOr(&nz[p & 3], 1);
    }
    __syncthreads();
    if (threadIdx.x == 0) {
        int kind = 0;
        if (!nz[1] && !nz[2] && !nz[3]) kind = 1;       // int32
        else if (!nz[0] && !nz[1])      kind = 2;       // float32
        g_mask_kind = kind;
    }
}

__global__ void build_maskbias_kernel(const void* __restrict__ m) {
    int i = blockIdx.x * blockDim.x + threadIdx.x;
    if (i >= Bc * SKVc) return;
    int kind = g_mask_kind;
    bool masked;
    if (kind == 1)      masked = ((const int*)m)[i] != 0;
    else if (kind == 2) masked = ((const float*)m)[i] != 0.0f;
    else                masked = ((const unsigned char*)m)[i] != 0;
    g_maskbias[i] = masked ? -CUDART_INF_F : 0.0f;
}

// ---------------------------------------------------------------------------
// SGEMM: C[M,N] = A[M,K] @ W[K,N] + bias[N]
// 128x128 block tile, BK=8, 8x8 per-thread micro-tile, 256 threads.
// ---------------------------------------------------------------------------
__global__ __launch_bounds__(256) void sgemm_bias(
    const float* __restrict__ A, const float* __restrict__ W,
    const float* __restrict__ bias, float* __restrict__ C,
    int M, int N, int K)
{
    const int BM = 128, BN = 128, BK = 8, TM = 8, TN = 8;
    __shared__ float As[BK][BM];
    __shared__ float Bs[BK][BN];

    int tid = threadIdx.x;
    int tx = tid & 15;        // 0..15 -> column group
    int ty = tid >> 4;        // 0..15 -> row group
    int m0 = blockIdx.y * BM;
    int n0 = blockIdx.x * BN;

    float acc[TM][TN];
#pragma unroll
    for (int i = 0; i < TM; i++)
#pragma unroll
        for (int j = 0; j < TN; j++) acc[i][j] = 0.0f;

    int arow = tid >> 1;            // 0..127
    int acol = (tid & 1) * 4;       // {0,4}
    int brow = tid >> 5;            // 0..7
    int bcol = (tid & 31) * 4;      // 0..124

    const float* Ap = A + (size_t)(m0 + arow) * K + acol;
    const float* Wp = W + (size_t)brow * N + n0 + bcol;

    for (int k0 = 0; k0 < K; k0 += BK) {
        float4 av = *(const float4*)(Ap + k0);
        As[acol + 0][arow] = av.x;
        As[acol + 1][arow] = av.y;
        As[acol + 2][arow] = av.z;
        As[acol + 3][arow] = av.w;
        *(float4*)&Bs[brow][bcol] = *(const float4*)(Wp + (size_t)k0 * N);
        __syncthreads();

#pragma unroll
        for (int k = 0; k < BK; k++) {
            float af[TM], bf[TN];
#pragma unroll
            for (int i = 0; i < TM; i += 4) {
                float4 v = *(const float4*)&As[k][ty * TM + i];
                af[i] = v.x; af[i + 1] = v.y; af[i + 2] = v.z; af[i + 3] = v.w;
            }
#pragma unroll
            for (int j = 0; j < TN; j += 4) {
                float4 v = *(const float4*)&Bs[k][tx * TN + j];
                bf[j] = v.x; bf[j + 1] = v.y; bf[j + 2] = v.z; bf[j + 3] = v.w;
            }
#pragma unroll
            for (int i = 0; i < TM; i++)
#pragma unroll
                for (int j = 0; j < TN; j++)
                    acc[i][j] += af[i] * bf[j];
        }
        __syncthreads();
    }

#pragma unroll
    for (int i = 0; i < TM; i++) {
        float* Crow = C + (size_t)(m0 + ty * TM + i) * N + n0 + tx * TN;
#pragma unroll
        for (int j = 0; j < TN; j += 4) {
            float4 r;
            r.x = acc[i][j + 0] + bias[n0 + tx * TN + j + 0];
            r.y = acc[i][j + 1] + bias[n0 + tx * TN + j + 1];
            r.z = acc[i][j + 2] + bias[n0 + tx * TN + j + 2];
            r.w = acc[i][j + 3] + bias[n0 + tx * TN + j + 3];
            *(float4*)(Crow + j) = r;
        }
    }
}

// ---------------------------------------------------------------------------
// Flash-attention style kernel. One block = (128 q-rows, one head, one batch).
// One thread per q-row; q and o accumulator in registers; K/V tiles in smem;
// online softmax with key-padding bias folded in.
// ---------------------------------------------------------------------------
#define BQ  128
#define TKV 32

__global__ __launch_bounds__(128) void attn_kernel(
    const float* __restrict__ Qg, const float* __restrict__ Kg,
    const float* __restrict__ Vg, float* __restrict__ Og)
{
    __shared__ float Ks[TKV][HDc];
    __shared__ float Vs[TKV][HDc];

    int q0 = blockIdx.x * BQ;
    int h  = blockIdx.y;
    int b  = blockIdx.z;
    int r  = threadIdx.x;
    const float scale = 0.125f;   // 1/sqrt(64)

    const float* qp = Qg + (size_t)(b * SQc + q0 + r) * Hc + h * HDc;
    float q[HDc];
#pragma unroll
    for (int d = 0; d < HDc; d += 4) {
        float4 v = *(const float4*)(qp + d);
        q[d] = v.x; q[d + 1] = v.y; q[d + 2] = v.z; q[d + 3] = v.w;
    }

    float o[HDc];
#pragma unroll
    for (int d = 0; d < HDc; d++) o[d] = 0.0f;
    float m = -CUDART_INF_F;
    float l = 0.0f;

    const float* mb = g_maskbias + b * SKVc;

    for (int t0 = 0; t0 < SKVc; t0 += TKV) {
        // cooperative tile load: TKV*HDc/4 = 512 float4, 128 threads -> 4 each
#pragma unroll
        for (int it = 0; it < (TKV * HDc / 4) / 128; it++) {
            int i   = threadIdx.x + it * 128;
            int row = i >> 4;             // HDc/4 = 16 float4 per row
            int c4  = (i & 15) * 4;
            size_t gi = (size_t)(b * SKVc + t0 + row) * Hc + h * HDc + c4;
            *(float4*)&Ks[row][c4] = *(const float4*)(Kg + gi);
            *(float4*)&Vs[row][c4] = *(const float4*)(Vg + gi);
        }
        __syncthreads();

        float s[TKV];
#pragma unroll
        for (int j = 0; j < TKV; j++) {
            float acc = 0.0f;
#pragma unroll
            for (int d = 0; d < HDc; d += 4) {
                float4 kv = *(const float4*)&Ks[j][d];
                acc += q[d] * kv.x + q[d + 1] * kv.y
                     + q[d + 2] * kv.z + q[d + 3] * kv.w;
            }
            s[j] = acc * scale + mb[t0 + j];
        }

        float tm = s[0];
#pragma unroll
        for (int j = 1; j < TKV; j++) tm = fmaxf(tm, s[j]);
        float mn = fmaxf(m, tm);

        if (mn > -CUDART_INF_F) {
            float alpha = __expf(m - mn);   // m = -inf -> 0
            l *= alpha;
#pragma unroll
            for (int d = 0; d < HDc; d++) o[d] *= alpha;
#pragma unroll
            for (int j = 0; j < TKV; j++) {
                float p = __expf(s[j] - mn);
                l += p;
#pragma unroll
                for (int d = 0; d < HDc; d += 4) {
                    float4 vv = *(const float4*)&Vs[j][d];
                    o[d]     += p * vv.x;
                    o[d + 1] += p * vv.y;
                    o[d + 2] += p * vv.z;
                    o[d + 3] += p * vv.w;
                }
            }
            m = mn;
        }
        __syncthreads();
    }

    float inv = 1.0f / l;
    float* op = Og + (size_t)(b * SQc + q0 + r) * Hc + h * HDc;
#pragma unroll
    for (int d = 0; d < HDc; d += 4) {
        float4 v;
        v.x = o[d] * inv; v.y = o[d + 1] * inv;
        v.z = o[d + 2] * inv; v.w = o[d + 3] * inv;
        *(float4*)(op + d) = v;
    }
}

// ---------------------------------------------------------------------------
// Launch
// Input order: 0 query_input, 1 key_value_input, 2 key_padding_mask,
//              3 Wq, 4 bq, 5 Wk, 6 bk, 7 Wv, 8 bv, 9 Wo, 10 bo
// ---------------------------------------------------------------------------
extern "C" void kernel_launch(void* const* d_in, const int* in_sizes, int n_in,
                              void* d_out, int out_size)
{
    (void)in_sizes; (void)n_in; (void)out_size;

    float *Qb, *Kb, *Vb, *Ab;
    cudaGetSymbolAddress((void**)&Qb, g_Q);
    cudaGetSymbolAddress((void**)&Kb, g_K);
    cudaGetSymbolAddress((void**)&Vb, g_V);
    cudaGetSymbolAddress((void**)&Ab, g_A);

    const float* Xq  = (const float*)d_in[0];
    const float* Xkv = (const float*)d_in[1];

    detect_mask_kernel<<<1, 256>>>((const unsigned char*)d_in[2]);
    build_maskbias_kernel<<<(Bc * SKVc + 255) / 256, 256>>>(d_in[2]);

    dim3 ggrid(Hc / 128, Mrows / 128);   // (8, 32)
    sgemm_bias<<<ggrid, 256>>>(Xq,  (const float*)d_in[3], (const float*)d_in[4],
                               Qb, Mrows, Hc, Dc);
    sgemm_bias<<<ggrid, 256>>>(Xkv, (const float*)d_in[5], (const float*)d_in[6],
                               Kb, Mrows, Hc, Dc);
    sgemm_bias<<<ggrid, 256>>>(Xkv, (const float*)d_in[7], (const float*)d_in[8],
                               Vb, Mrows, Hc, Dc);

    attn_kernel<<<dim3(SQc / BQ, NHc, Bc), 128>>>(Qb, Kb, Vb, Ab);

    dim3 ogrid(Dc / 128, Mrows / 128);   // (8, 32)
    sgemm_bias<<<ogrid, 256>>>(Ab, (const float*)d_in[9], (const float*)d_in[10],
                               (float*)d_out, Mrows, Dc, Hc);
}

// round 2
// speedup vs baseline: 2.8536x; 2.8536x over previous
#include <cuda_runtime.h>
#include <cuda_bf16.h>
#include <math_constants.h>
#include <cstdint>

#define Bc    2
#define SQc   2048
#define SKVc  2048
#define Dc    1024
#define Hc    1024
#define NHc   16
#define HDc   64
#define Mrows 4096

typedef __nv_bfloat16 bf16;

// ---------------- scratch (device globals, allocation-free) ----------------
__device__ bf16 g_Xq_h[(size_t)Mrows * Dc],  g_Xq_l[(size_t)Mrows * Dc];
__device__ bf16 g_Xkv_h[(size_t)Mrows * Dc], g_Xkv_l[(size_t)Mrows * Dc];
__device__ bf16 g_Wq_h[(size_t)Dc * Hc], g_Wq_l[(size_t)Dc * Hc];
__device__ bf16 g_Wk_h[(size_t)Dc * Hc], g_Wk_l[(size_t)Dc * Hc];
__device__ bf16 g_Wv_h[(size_t)Dc * Hc], g_Wv_l[(size_t)Dc * Hc];
__device__ bf16 g_Wo_h[(size_t)Hc * Dc], g_Wo_l[(size_t)Hc * Dc];
__device__ bf16 g_Q_h[(size_t)Mrows * Hc], g_Q_l[(size_t)Mrows * Hc];
__device__ bf16 g_K_h[(size_t)Mrows * Hc], g_K_l[(size_t)Mrows * Hc];
__device__ bf16 g_V_h[(size_t)Mrows * Hc], g_V_l[(size_t)Mrows * Hc];
__device__ bf16 g_A_h[(size_t)Mrows * Hc], g_A_l[(size_t)Mrows * Hc];
__device__ float g_maskbias[Bc * SKVc];
__device__ int   g_mask_kind;

// ---------------- small helpers ----------------
__device__ __forceinline__ uint32_t smem_u32(const void* p) {
    return (uint32_t)__cvta_generic_to_shared(p);
}
__device__ __forceinline__ void cpa16(void* dst, const void* src) {
    asm volatile("cp.async.cg.shared.global [%0], [%1], 16;\n"
                 :: "r"(smem_u32(dst)), "l"(src));
}
__device__ __forceinline__ void cp_commit() { asm volatile("cp.async.commit_group;\n"); }
template <int N> __device__ __forceinline__ void cp_wait() {
    asm volatile("cp.async.wait_group %0;\n" :: "n"(N));
}
__device__ __forceinline__ void ldm4(uint32_t r[4], const void* p) {
    asm volatile("ldmatrix.sync.aligned.m8n8.x4.shared.b16 {%0,%1,%2,%3}, [%4];\n"
                 : "=r"(r[0]), "=r"(r[1]), "=r"(r[2]), "=r"(r[3]) : "r"(smem_u32(p)));
}
__device__ __forceinline__ void ldm4t(uint32_t r[4], const void* p) {
    asm volatile("ldmatrix.sync.aligned.m8n8.x4.trans.shared.b16 {%0,%1,%2,%3}, [%4];\n"
                 : "=r"(r[0]), "=r"(r[1]), "=r"(r[2]), "=r"(r[3]) : "r"(smem_u32(p)));
}
__device__ __forceinline__ void mma16816(float c[4], const uint32_t a[4], const uint32_t b[2]) {
    asm volatile("mma.sync.aligned.m16n8k16.row.col.f32.bf16.bf16.f32 "
                 "{%0,%1,%2,%3}, {%4,%5,%6,%7}, {%8,%9}, {%0,%1,%2,%3};\n"
                 : "+f"(c[0]), "+f"(c[1]), "+f"(c[2]), "+f"(c[3])
                 : "r"(a[0]), "r"(a[1]), "r"(a[2]), "r"(a[3]), "r"(b[0]), "r"(b[1]));
}
__device__ __forceinline__ uint32_t b2u(__nv_bfloat162 v) {
    return *reinterpret_cast<uint32_t*>(&v);
}
__device__ __forceinline__ uint32_t packbf(float a, float b) {
    __nv_bfloat162 t = __floats2bfloat162_rn(a, b);
    return b2u(t);
}

// ---------------- mask detection (unchanged logic, -1e30 bias) ----------------
__global__ void detect_mask_kernel(const unsigned char* __restrict__ m) {
    __shared__ int nz[4];
    if (threadIdx.x < 4) nz[threadIdx.x] = 0;
    __syncthreads();
    for (int p = threadIdx.x; p < Bc * SKVc; p += blockDim.x)
        if (m[p]) atomicOr(&nz[p & 3], 1);
    __syncthreads();
    if (threadIdx.x == 0) {
        int kind = 0;
        if (!nz[1] && !nz[2] && !nz[3]) kind = 1;       // int32
        else if (!nz[0] && !nz[1])      kind = 2;       // float32
        g_mask_kind = kind;
    }
}
__global__ void build_maskbias_kernel(const void* __restrict__ m) {
    int i = blockIdx.x * blockDim.x + threadIdx.x;
    if (i >= Bc * SKVc) return;
    int kind = g_mask_kind;
    bool masked;
    if (kind == 1)      masked = ((const int*)m)[i] != 0;
    else if (kind == 2) masked = ((const float*)m)[i] != 0.0f;
    else                masked = ((const unsigned char*)m)[i] != 0;
    g_maskbias[i] = masked ? -1e30f : 0.0f;
}

// ---------------- fp32 -> (hi, lo) bf16 split ----------------
__global__ void split_kernel(const float* __restrict__ x,
                             bf16* __restrict__ hi, bf16* __restrict__ lo, int n) {
    int i = blockIdx.x * blockDim.x + threadIdx.x;
    if (i >= n) return;
    float v = x[i];
    bf16 h = __float2bfloat16(v);
    hi[i] = h;
    lo[i] = __float2bfloat16(v - __bfloat162float(h));
}

// ---------------- split-bf16 GEMM: C = A@W + bias ----------------
// BM=128, BN=128, BK=32, 256 threads (8 warps, 2x4 warp grid, 64x32 warp tile)
#define G_AST 40
#define G_BST 136
#define GEMM_SMEM ((2*128*G_AST*2 + 2*32*G_BST*2) * (int)sizeof(bf16))

__global__ __launch_bounds__(256) void gemm_split(
    const bf16* __restrict__ Ah, const bf16* __restrict__ Al,
    const bf16* __restrict__ Wh, const bf16* __restrict__ Wl,
    const float* __restrict__ bias,
    bf16* __restrict__ Ch, bf16* __restrict__ Cl, float* __restrict__ Cf,
    int M, int N, int K)
{
    extern __shared__ char sm[];
    bf16* Ash = (bf16*)sm;                 // [2][128][G_AST]
    bf16* Asl = Ash + 2 * 128 * G_AST;
    bf16* Bsh = Asl + 2 * 128 * G_AST;     // [2][32][G_BST]
    bf16* Bsl = Bsh + 2 * 32 * G_BST;

    int tid = threadIdx.x, lane = tid & 31, wid = tid >> 5;
    int wm = wid & 1, wn = wid >> 1;
    int m0 = blockIdx.y * 128, n0 = blockIdx.x * 128;

    float acc[4][4][4];
#pragma unroll
    for (int i = 0; i < 4; i++)
#pragma unroll
        for (int j = 0; j < 4; j++)
#pragma unroll
            for (int e = 0; e < 4; e++) acc[i][j][e] = 0.0f;

    auto load_tiles = [&](int it, int buf) {
        int k0 = it * 32;
#pragma unroll
        for (int c = tid; c < 512; c += 256) {
            int r = c >> 2, kc = (c & 3) * 8;
            size_t src = (size_t)(m0 + r) * K + k0 + kc;
            cpa16(&Ash[(buf * 128 + r) * G_AST + kc], Ah + src);
            cpa16(&Asl[(buf * 128 + r) * G_AST + kc], Al + src);
        }
#pragma unroll
        for (int c = tid; c < 512; c += 256) {
            int r = c >> 4, nc = (c & 15) * 8;
            size_t src = (size_t)(k0 + r) * N + n0 + nc;
            cpa16(&Bsh[(buf * 32 + r) * G_BST + nc], Wh + src);
            cpa16(&Bsl[(buf * 32 + r) * G_BST + nc], Wl + src);
        }
    };

    int NIT = K / 32;
    load_tiles(0, 0);
    cp_commit();

    for (int it = 0; it < NIT; ++it) {
        int buf = it & 1;
        if (it + 1 < NIT) { load_tiles(it + 1, buf ^ 1); cp_commit(); cp_wait<1>(); }
        else              { cp_wait<0>(); }
        __syncthreads();

#pragma unroll
        for (int kk = 0; kk < 2; ++kk) {
            uint32_t ah[4][4], al[4][4], bh[2][4], bl[2][4];
#pragma unroll
            for (int mt = 0; mt < 4; ++mt) {
                int idx = (buf * 128 + wm * 64 + mt * 16 + (lane & 15)) * G_AST
                        + kk * 16 + (lane >> 4) * 8;
                ldm4(ah[mt], &Ash[idx]);
                ldm4(al[mt], &Asl[idx]);
            }
#pragma unroll
            for (int g = 0; g < 2; ++g) {
                int idx = (buf * 32 + kk * 16 + (lane & 15)) * G_BST
                        + wn * 32 + g * 16 + (lane >> 4) * 8;
                ldm4t(bh[g], &Bsh[idx]);
                ldm4t(bl[g], &Bsl[idx]);
            }
#pragma unroll
            for (int mt = 0; mt < 4; ++mt)
#pragma unroll
                for (int g = 0; g < 2; ++g) {
                    uint32_t bh0[2] = { bh[g][0], bh[g][1] }, bh1[2] = { bh[g][2], bh[g][3] };
                    uint32_t bl0[2] = { bl[g][0], bl[g][1] }, bl1[2] = { bl[g][2], bl[g][3] };
                    mma16816(acc[mt][2 * g],     ah[mt], bh0);
                    mma16816(acc[mt][2 * g],     ah[mt], bl0);
                    mma16816(acc[mt][2 * g],     al[mt], bh0);
                    mma16816(acc[mt][2 * g + 1], ah[mt], bh1);
                    mma16816(acc[mt][2 * g + 1], ah[mt], bl1);
                    mma16816(acc[mt][2 * g + 1], al[mt], bh1);
                }
        }
        __syncthreads();
    }

    // epilogue
#pragma unroll
    for (int mt = 0; mt < 4; ++mt)
#pragma unroll
        for (int nt = 0; nt < 4; ++nt) {
            int row = m0 + wm * 64 + mt * 16 + (lane >> 2);
            int col = n0 + wn * 32 + nt * 8 + (lane & 3) * 2;
            float b0 = bias[col], b1 = bias[col + 1];
            float v00 = acc[mt][nt][0] + b0, v01 = acc[mt][nt][1] + b1;
            float v10 = acc[mt][nt][2] + b0, v11 = acc[mt][nt][3] + b1;
            size_t i0 = (size_t)row * N + col;
            size_t i1 = (size_t)(row + 8) * N + col;
            if (Cf) {
                *(float2*)(Cf + i0) = make_float2(v00, v01);
                *(float2*)(Cf + i1) = make_float2(v10, v11);
            } else {
                __nv_bfloat162 h0 = __floats2bfloat162_rn(v00, v01);
                __nv_bfloat162 h1 = __floats2bfloat162_rn(v10, v11);
                *(uint32_t*)(Ch + i0) = b2u(h0);
                *(uint32_t*)(Ch + i1) = b2u(h1);
                *(uint32_t*)(Cl + i0) = packbf(v00 - __low2float(h0), v01 - __high2float(h0));
                *(uint32_t*)(Cl + i1) = packbf(v10 - __low2float(h1), v11 - __high2float(h1));
            }
        }
}

// ---------------- split-bf16 flash attention ----------------
// BQ=128 (8 warps x 16 rows), TKV=64, HD=64, online softmax.
#define A_QST 72
#define A_KST 72
#define ATTN_SMEM ((2*128*A_QST + 4*2*64*A_KST) * (int)sizeof(bf16) + 2*64*(int)sizeof(float))

__global__ __launch_bounds__(256) void attn_mma(
    const bf16* __restrict__ Qh, const bf16* __restrict__ Ql,
    const bf16* __restrict__ Kh, const bf16* __restrict__ Kl,
    const bf16* __restrict__ Vh, const bf16* __restrict__ Vl,
    bf16* __restrict__ Ah, bf16* __restrict__ Al)
{
    extern __shared__ char sm[];
    bf16* Qs_h = (bf16*)sm;                     // [128][A_QST]
    bf16* Qs_l = Qs_h + 128 * A_QST;
    bf16* Ks_h = Qs_l + 128 * A_QST;            // [2][64][A_KST]
    bf16* Ks_l = Ks_h + 2 * 64 * A_KST;
    bf16* Vs_h = Ks_l + 2 * 64 * A_KST;
    bf16* Vs_l = Vs_h + 2 * 64 * A_KST;
    float* mbs = (float*)(Vs_l + 2 * 64 * A_KST);  // [2][64]

    int tid = threadIdx.x, lane = tid & 31, wid = tid >> 5;
    int q0 = blockIdx.x * 128, h = blockIdx.y, b = blockIdx.z;

    // stage Q tile
#pragma unroll
    for (int c = tid; c < 1024; c += 256) {
        int r = c >> 3, col = (c & 7) * 8;
        size_t src = (size_t)(b * SQc + q0 + r) * Hc + h * HDc + col;
        cpa16(&Qs_h[r * A_QST + col], Qh + src);
        cpa16(&Qs_l[r * A_QST + col], Ql + src);
    }
    cp_commit();

    auto load_kv = [&](int it, int buf) {
        int t0 = it * 64;
#pragma unroll
        for (int c = tid; c < 512; c += 256) {
            int r = c >> 3, col = (c & 7) * 8;
            size_t src = (size_t)(b * SKVc + t0 + r) * Hc + h * HDc + col;
            cpa16(&Ks_h[(buf * 64 + r) * A_KST + col], Kh + src);
            cpa16(&Ks_l[(buf * 64 + r) * A_KST + col], Kl + src);
            cpa16(&Vs_h[(buf * 64 + r) * A_KST + col], Vh + src);
            cpa16(&Vs_l[(buf * 64 + r) * A_KST + col], Vl + src);
        }
        if (tid < 16)
            cpa16(&mbs[buf * 64 + tid * 4], g_maskbias + b * SKVc + t0 + tid * 4);
    };

    load_kv(0, 0);
    cp_commit();
    cp_wait<1>();
    __syncthreads();

    // Q fragments (register-resident for whole kernel)
    uint32_t qh[4][4], ql[4][4];
    {
        int r = wid * 16 + (lane & 15);
#pragma unroll
        for (int kk = 0; kk < 4; ++kk) {
            int idx = r * A_QST + kk * 16 + (lane >> 4) * 8;
            ldm4(qh[kk], &Qs_h[idx]);
            ldm4(ql[kk], &Qs_l[idx]);
        }
    }

    float o[8][4];
#pragma unroll
    for (int i = 0; i < 8; i++)
#pragma unroll
        for (int j = 0; j < 4; j++) o[i][j] = 0.0f;
    float m0r = -CUDART_INF_F, m1r = -CUDART_INF_F;
    float l0r = 0.0f, l1r = 0.0f;

    const int NT = SKVc / 64;
    for (int it = 0; it < NT; ++it) {
        int buf = it & 1;
        if (it + 1 < NT) { load_kv(it + 1, buf ^ 1); cp_commit(); cp_wait<1>(); }
        else             { cp_wait<0>(); }
        __syncthreads();

        // ---- S = Q K^T (3-term split) ----
        float s[8][4];
#pragma unroll
        for (int i = 0; i < 8; i++)
#pragma unroll
            for (int j = 0; j < 4; j++) s[i][j] = 0.0f;

#pragma unroll
        for (int kk = 0; kk < 4; ++kk) {
#pragma unroll
            for (int g = 0; g < 4; ++g) {
                uint32_t kh[4], kl[4];
                int idx = (buf * 64 + g * 16 + (lane & 15)) * A_KST
                        + kk * 16 + (lane >> 4) * 8;
                ldm4(kh, &Ks_h[idx]);
                ldm4(kl, &Ks_l[idx]);
                uint32_t b0h[2] = { kh[0], kh[2] }, b1h[2] = { kh[1], kh[3] };
                uint32_t b0l[2] = { kl[0], kl[2] }, b1l[2] = { kl[1], kl[3] };
                mma16816(s[2 * g],     qh[kk], b0h);
                mma16816(s[2 * g],     qh[kk], b0l);
                mma16816(s[2 * g],     ql[kk], b0h);
                mma16816(s[2 * g + 1], qh[kk], b1h);
                mma16816(s[2 * g + 1], qh[kk], b1l);
                mma16816(s[2 * g + 1], ql[kk], b1h);
            }
        }

        // ---- scale + mask + online softmax ----
        float tm0 = -CUDART_INF_F, tm1 = -CUDART_INF_F;
#pragma unroll
        for (int nt = 0; nt < 8; ++nt) {
            int cb = nt * 8 + (lane & 3) * 2;
            float mb0 = mbs[buf * 64 + cb], mb1 = mbs[buf * 64 + cb + 1];
            s[nt][0] = s[nt][0] * 0.125f + mb0;
            s[nt][1] = s[nt][1] * 0.125f + mb1;
            s[nt][2] = s[nt][2] * 0.125f + mb0;
            s[nt][3] = s[nt][3] * 0.125f + mb1;
            tm0 = fmaxf(tm0, fmaxf(s[nt][0], s[nt][1]));
            tm1 = fmaxf(tm1, fmaxf(s[nt][2], s[nt][3]));
        }
        tm0 = fmaxf(tm0, __shfl_xor_sync(0xffffffffu, tm0, 1));
        tm0 = fmaxf(tm0, __shfl_xor_sync(0xffffffffu, tm0, 2));
        tm1 = fmaxf(tm1, __shfl_xor_sync(0xffffffffu, tm1, 1));
        tm1 = fmaxf(tm1, __shfl_xor_sync(0xffffffffu, tm1, 2));
        float mn0 = fmaxf(m0r, tm0), mn1 = fmaxf(m1r, tm1);
        float al0 = __expf(m0r - mn0), al1 = __expf(m1r - mn1);
        m0r = mn0; m1r = mn1;

        float rs0 = 0.0f, rs1 = 0.0f;
#pragma unroll
        for (int nt = 0; nt < 8; ++nt) {
            s[nt][0] = __expf(s[nt][0] - mn0);
            s[nt][1] = __expf(s[nt][1] - mn0);
            s[nt][2] = __expf(s[nt][2] - mn1);
            s[nt][3] = __expf(s[nt][3] - mn1);
            rs0 += s[nt][0] + s[nt][1];
            rs1 += s[nt][2] + s[nt][3];
        }
        rs0 += __shfl_xor_sync(0xffffffffu, rs0, 1);
        rs0 += __shfl_xor_sync(0xffffffffu, rs0, 2);
        rs1 += __shfl_xor_sync(0xffffffffu, rs1, 1);
        rs1 += __shfl_xor_sync(0xffffffffu, rs1, 2);
        l0r = l0r * al0 + rs0;
        l1r = l1r * al1 + rs1;

#pragma unroll
        for (int dn = 0; dn < 8; ++dn) {
            o[dn][0] *= al0; o[dn][1] *= al0;
            o[dn][2] *= al1; o[dn][3] *= al1;
        }

        // ---- O += P V (3-term split; P split in registers) ----
#pragma unroll
        for (int kt = 0; kt < 4; ++kt) {
            float x0 = s[2 * kt][0], x1 = s[2 * kt][1], x2 = s[2 * kt][2], x3 = s[2 * kt][3];
            float y0 = s[2 * kt + 1][0], y1 = s[2 * kt + 1][1];
            float y2 = s[2 * kt + 1][2], y3 = s[2 * kt + 1][3];
            __nv_bfloat162 hx0 = __floats2bfloat162_rn(x0, x1);
            __nv_bfloat162 hx1 = __floats2bfloat162_rn(x2, x3);
            __nv_bfloat162 hy0 = __floats2bfloat162_rn(y0, y1);
            __nv_bfloat162 hy1 = __floats2bfloat162_rn(y2, y3);
            uint32_t pah[4] = { b2u(hx0), b2u(hx1), b2u(hy0), b2u(hy1) };
            uint32_t pal[4] = {
                packbf(x0 - __low2float(hx0), x1 - __high2float(hx0)),
                packbf(x2 - __low2float(hx1), x3 - __high2float(hx1)),
                packbf(y0 - __low2float(hy0), y1 - __high2float(hy0)),
                packbf(y2 - __low2float(hy1), y3 - __high2float(hy1))
            };
#pragma unroll
            for (int dg = 0; dg < 4; ++dg) {
                uint32_t vh[4], vl[4];
                int idx = (buf * 64 + kt * 16 + (lane & 15)) * A_KST
                        + dg * 16 + (lane >> 4) * 8;
                ldm4t(vh, &Vs_h[idx]);
                ldm4t(vl, &Vs_l[idx]);
                uint32_t b0h[2] = { vh[0], vh[1] }, b1h[2] = { vh[2], vh[3] };
                uint32_t b0l[2] = { vl[0], vl[1] }, b1l[2] = { vl[2], vl[3] };
                mma16816(o[2 * dg],     pah, b0h);
                mma16816(o[2 * dg],     pah, b0l);
                mma16816(o[2 * dg],     pal, b0h);
                mma16816(o[2 * dg + 1], pah, b1h);
                mma16816(o[2 * dg + 1], pah, b1l);
                mma16816(o[2 * dg + 1], pal, b1h);
            }
        }
        __syncthreads();
    }

    // ---- epilogue: normalize and write hi/lo bf16 ----
    float inv0 = 1.0f / l0r, inv1 = 1.0f / l1r;
#pragma unroll
    for (int dn = 0; dn < 8; ++dn) {
        int row = q0 + wid * 16 + (lane >> 2);
        int col = h * HDc + dn * 8 + (lane & 3) * 2;
        float v00 = o[dn][0] * inv0, v01 = o[dn][1] * inv0;
        float v10 = o[dn][2] * inv1, v11 = o[dn][3] * inv1;
        size_t i0 = (size_t)(b * SQc + row) * Hc + col;
        size_t i1 = (size_t)(b * SQc + row + 8) * Hc + col;
        __nv_bfloat162 h0 = __floats2bfloat162_rn(v00, v01);
        __nv_bfloat162 h1 = __floats2bfloat162_rn(v10, v11);
        *(uint32_t*)(Ah + i0) = b2u(h0);
        *(uint32_t*)(Ah + i1) = b2u(h1);
        *(uint32_t*)(Al + i0) = packbf(v00 - __low2float(h0), v01 - __high2float(h0));
        *(uint32_t*)(Al + i1) = packbf(v10 - __low2float(h1), v11 - __high2float(h1));
    }
}

// ---------------- launch ----------------
extern "C" void kernel_launch(void* const* d_in, const int* in_sizes, int n_in,
                              void* d_out, int out_size)
{
    (void)in_sizes; (void)n_in; (void)out_size;

    bf16 *Xq_h, *Xq_l, *Xkv_h, *Xkv_l;
    bf16 *Wq_h, *Wq_l, *Wk_h, *Wk_l, *Wv_h, *Wv_l, *Wo_h, *Wo_l;
    bf16 *Q_h, *Q_l, *K_h, *K_l, *V_h, *V_l, *A_h, *A_l;
    cudaGetSymbolAddress((void**)&Xq_h, g_Xq_h);   cudaGetSymbolAddress((void**)&Xq_l, g_Xq_l);
    cudaGetSymbolAddress((void**)&Xkv_h, g_Xkv_h); cudaGetSymbolAddress((void**)&Xkv_l, g_Xkv_l);
    cudaGetSymbolAddress((void**)&Wq_h, g_Wq_h);   cudaGetSymbolAddress((void**)&Wq_l, g_Wq_l);
    cudaGetSymbolAddress((void**)&Wk_h, g_Wk_h);   cudaGetSymbolAddress((void**)&Wk_l, g_Wk_l);
    cudaGetSymbolAddress((void**)&Wv_h, g_Wv_h);   cudaGetSymbolAddress((void**)&Wv_l, g_Wv_l);
    cudaGetSymbolAddress((void**)&Wo_h, g_Wo_h);   cudaGetSymbolAddress((void**)&Wo_l, g_Wo_l);
    cudaGetSymbolAddress((void**)&Q_h, g_Q_h);     cudaGetSymbolAddress((void**)&Q_l, g_Q_l);
    cudaGetSymbolAddress((void**)&K_h, g_K_h);     cudaGetSymbolAddress((void**)&K_l, g_K_l);
    cudaGetSymbolAddress((void**)&V_h, g_V_h);     cudaGetSymbolAddress((void**)&V_l, g_V_l);
    cudaGetSymbolAddress((void**)&A_h, g_A_h);     cudaGetSymbolAddress((void**)&A_l, g_A_l);

    cudaFuncSetAttribute(gemm_split, cudaFuncAttributeMaxDynamicSharedMemorySize, GEMM_SMEM);
    cudaFuncSetAttribute(attn_mma,   cudaFuncAttributeMaxDynamicSharedMemorySize, ATTN_SMEM);

    detect_mask_kernel<<<1, 256>>>((const unsigned char*)d_in[2]);
    build_maskbias_kernel<<<(Bc * SKVc + 255) / 256, 256>>>(d_in[2]);

    const int nX = Mrows * Dc;     // 4M
    const int nW = Dc * Hc;        // 1M
    split_kernel<<<(nX + 255) / 256, 256>>>((const float*)d_in[0], Xq_h, Xq_l, nX);
    split_kernel<<<(nX + 255) / 256, 256>>>((const float*)d_in[1], Xkv_h, Xkv_l, nX);
    split_kernel<<<(nW + 255) / 256, 256>>>((const float*)d_in[3], Wq_h, Wq_l, nW);
    split_kernel<<<(nW + 255) / 256, 256>>>((const float*)d_in[5], Wk_h, Wk_l, nW);
    split_kernel<<<(nW + 255) / 256, 256>>>((const float*)d_in[7], Wv_h, Wv_l, nW);
    split_kernel<<<(nW + 255) / 256, 256>>>((const float*)d_in[9], Wo_h, Wo_l, nW);

    dim3 pg(Hc / 128, Mrows / 128);   // (8, 32)
    gemm_split<<<pg, 256, GEMM_SMEM>>>(Xq_h, Xq_l, Wq_h, Wq_l, (const float*)d_in[4],
                                       Q_h, Q_l, nullptr, Mrows, Hc, Dc);
    gemm_split<<<pg, 256, GEMM_SMEM>>>(Xkv_h, Xkv_l, Wk_h, Wk_l, (const float*)d_in[6],
                                       K_h, K_l, nullptr, Mrows, Hc, Dc);
    gemm_split<<<pg, 256, GEMM_SMEM>>>(Xkv_h, Xkv_l, Wv_h, Wv_l, (const float*)d_in[8],
                                       V_h, V_l, nullptr, Mrows, Hc, Dc);

    attn_mma<<<dim3(SQc / 128, NHc, Bc), 256, ATTN_SMEM>>>(Q_h, Q_l, K_h, K_l,
                                                           V_h, V_l, A_h, A_l);

    dim3 og(Dc / 128, Mrows / 128);   // (8, 32)
    gemm_split<<<og, 256, GEMM_SMEM>>>(A_h, A_l, Wo_h, Wo_l, (const float*)d_in[10],
                                       nullptr, nullptr, (float*)d_out, Mrows, Dc, Hc);
}

// round 5
// speedup vs baseline: 2.8913x; 1.0132x over previous
#include <cuda_runtime.h>
#include <cuda_bf16.h>
#include <math_constants.h>
#include <cstdint>

#define Bc    2
#define SQc   2048
#define SKVc  2048
#define Dc    1024
#define Hc    1024
#define NHc   16
#define HDc   64
#define Mrows 4096

typedef __nv_bfloat16 bf16;

// ---------------- scratch (device globals, allocation-free) ----------------
__device__ bf16 g_Xq_h[(size_t)Mrows * Dc],  g_Xq_l[(size_t)Mrows * Dc];
__device__ bf16 g_Xkv_h[(size_t)Mrows * Dc], g_Xkv_l[(size_t)Mrows * Dc];
__device__ bf16 g_Wq_h[(size_t)Dc * Hc], g_Wq_l[(size_t)Dc * Hc];
__device__ bf16 g_Wk_h[(size_t)Dc * Hc], g_Wk_l[(size_t)Dc * Hc];
__device__ bf16 g_Wv_h[(size_t)Dc * Hc], g_Wv_l[(size_t)Dc * Hc];
__device__ bf16 g_Wo_h[(size_t)Hc * Dc], g_Wo_l[(size_t)Hc * Dc];
__device__ bf16 g_Q_h[(size_t)Mrows * Hc], g_Q_l[(size_t)Mrows * Hc];
__device__ bf16 g_K_h[(size_t)Mrows * Hc], g_K_l[(size_t)Mrows * Hc];
__device__ bf16 g_V_h[(size_t)Mrows * Hc], g_V_l[(size_t)Mrows * Hc];
__device__ bf16 g_A_h[(size_t)Mrows * Hc], g_A_l[(size_t)Mrows * Hc];
__device__ float g_maskbias[Bc * SKVc];

// ---------------- small helpers ----------------
__device__ __forceinline__ uint32_t smem_u32(const void* p) {
    return (uint32_t)__cvta_generic_to_shared(p);
}
__device__ __forceinline__ void cpa16(void* dst, const void* src) {
    asm volatile("cp.async.cg.shared.global [%0], [%1], 16;\n"
                 :: "r"(smem_u32(dst)), "l"(src));
}
__device__ __forceinline__ void cp_commit() { asm volatile("cp.async.commit_group;\n"); }
template <int N> __device__ __forceinline__ void cp_wait() {
    asm volatile("cp.async.wait_group %0;\n" :: "n"(N) : "memory");
}
__device__ __forceinline__ void ldm4(uint32_t r[4], const void* p) {
    asm volatile("ldmatrix.sync.aligned.m8n8.x4.shared.b16 {%0,%1,%2,%3}, [%4];\n"
                 : "=r"(r[0]), "=r"(r[1]), "=r"(r[2]), "=r"(r[3]) : "r"(smem_u32(p)));
}
__device__ __forceinline__ void ldm4t(uint32_t r[4], const void* p) {
    asm volatile("ldmatrix.sync.aligned.m8n8.x4.trans.shared.b16 {%0,%1,%2,%3}, [%4];\n"
                 : "=r"(r[0]), "=r"(r[1]), "=r"(r[2]), "=r"(r[3]) : "r"(smem_u32(p)));
}
__device__ __forceinline__ void mma16816(float c[4], const uint32_t a[4], const uint32_t b[2]) {
    asm volatile("mma.sync.aligned.m16n8k16.row.col.f32.bf16.bf16.f32 "
                 "{%0,%1,%2,%3}, {%4,%5,%6,%7}, {%8,%9}, {%0,%1,%2,%3};\n"
                 : "+f"(c[0]), "+f"(c[1]), "+f"(c[2]), "+f"(c[3])
                 : "r"(a[0]), "r"(a[1]), "r"(a[2]), "r"(a[3]), "r"(b[0]), "r"(b[1]));
}
__device__ __forceinline__ uint32_t b2u(__nv_bfloat162 v) {
    return *reinterpret_cast<uint32_t*>(&v);
}
__device__ __forceinline__ uint32_t packbf(float a, float b) {
    __nv_bfloat162 t = __floats2bfloat162_rn(a, b);
    return b2u(t);
}

// ---------------- fused mask detect + bias build (single block) ----------------
__global__ void mask_kernel(const unsigned char* __restrict__ m) {
    __shared__ int nz[4];
    int tid = threadIdx.x;
    if (tid < 4) nz[tid] = 0;
    __syncthreads();
    for (int p = tid; p < Bc * SKVc; p += blockDim.x)
        if (m[p]) atomicOr(&nz[p & 3], 1);
    __syncthreads();
    int kind = 0;
    if (!nz[1] && !nz[2] && !nz[3]) kind = 1;       // int32 0/1
    else if (!nz[0] && !nz[1])      kind = 2;       // float32 0/1
    for (int i = tid; i < Bc * SKVc; i += blockDim.x) {
        bool mk;
        if (kind == 1)      mk = ((const int*)m)[i] != 0;
        else if (kind == 2) mk = ((const float*)m)[i] != 0.0f;
        else                mk = m[i] != 0;
        g_maskbias[i] = mk ? -1e30f : 0.0f;
    }
}

// ---------------- fused split: all 6 tensors in one launch (z-sliced) ----------
struct SplitArgs {
    const float* src[6];
    bf16* hi[6];
    bf16* lo[6];
    int   n4[6];     // element count / 4
};
__global__ __launch_bounds__(256) void split_all(SplitArgs a) {
    int z = blockIdx.y;
    int i4 = blockIdx.x * 256 + threadIdx.x;
    if (i4 >= a.n4[z]) return;
    float4 v = ((const float4*)a.src[z])[i4];
    __nv_bfloat162 h0 = __floats2bfloat162_rn(v.x, v.y);
    __nv_bfloat162 h1 = __floats2bfloat162_rn(v.z, v.w);
    uint32_t l0 = packbf(v.x - __low2float(h0), v.y - __high2float(h0));
    uint32_t l1 = packbf(v.z - __low2float(h1), v.w - __high2float(h1));
    ((uint2*)a.hi[z])[i4] = make_uint2(b2u(h0), b2u(h1));
    ((uint2*)a.lo[z])[i4] = make_uint2(l0, l1);
}

// ---------------- split-bf16 GEMM: C = A@W + bias ----------------
// BM=128, BN=128, BK=64, 2 stages, 256 threads (8 warps, 2x4 grid, 64x32 tile)
#define G_AST 72
#define G_BST 136
#define GEMM_SMEM ((2*128*G_AST*2 + 2*64*G_BST*2) * (int)sizeof(bf16))

__global__ __launch_bounds__(256) void gemm_split(
    const bf16* __restrict__ Ah, const bf16* __restrict__ Al,
    const bf16* __restrict__ Wh, const bf16* __restrict__ Wl,
    const float* __restrict__ bias,
    bf16* __restrict__ Ch, bf16* __restrict__ Cl, float* __restrict__ Cf,
    int M, int N, int K)
{
    extern __shared__ char sm[];
    bf16* Ash = (bf16*)sm;                    // [2][128][G_AST]
    bf16* Asl = Ash + 2 * 128 * G_AST;
    bf16* Bsh = Asl + 2 * 128 * G_AST;        // [2][64][G_BST]
    bf16* Bsl = Bsh + 2 * 64 * G_BST;

    int tid = threadIdx.x, lane = tid & 31, wid = tid >> 5;
    int wm = wid & 1, wn = wid >> 1;
    int m0 = blockIdx.y * 128, n0 = blockIdx.x * 128;

    float acc[4][4][4];
#pragma unroll
    for (int i = 0; i < 4; i++)
#pragma unroll
        for (int j = 0; j < 4; j++)
#pragma unroll
            for (int e = 0; e < 4; e++) acc[i][j][e] = 0.0f;

    auto load_tiles = [&](int it, int s) {
        int k0 = it * 64;
#pragma unroll
        for (int x = tid; x < 2048; x += 256) {       // A hi/lo: 128 rows x 64 cols
            int mat = x >> 10, i = x & 1023;
            int r = i >> 3, kc = (i & 7) * 8;
            const bf16* src = (mat ? Al : Ah) + (size_t)(m0 + r) * K + k0 + kc;
            bf16* dst = (mat ? Asl : Ash) + (s * 128 + r) * G_AST + kc;
            cpa16(dst, src);
        }
#pragma unroll
        for (int x = tid; x < 2048; x += 256) {       // B hi/lo: 64 rows x 128 cols
            int mat = x >> 10, i = x & 1023;
            int r = i >> 4, nc = (i & 15) * 8;
            const bf16* src = (mat ? Wl : Wh) + (size_t)(k0 + r) * N + n0 + nc;
            bf16* dst = (mat ? Bsl : Bsh) + (s * 64 + r) * G_BST + nc;
            cpa16(dst, src);
        }
    };

    int NIT = K / 64;
    load_tiles(0, 0);
    cp_commit();

    for (int it = 0; it < NIT; ++it) {
        int buf = it & 1;
        if (it + 1 < NIT) { load_tiles(it + 1, buf ^ 1); cp_commit(); cp_wait<1>(); }
        else              { cp_wait<0>(); }
        __syncthreads();

#pragma unroll
        for (int kk = 0; kk < 4; ++kk) {
            uint32_t ah[4][4], al[4][4], bh[2][4], bl[2][4];
#pragma unroll
            for (int mt = 0; mt < 4; ++mt) {
                int idx = (buf * 128 + wm * 64 + mt * 16 + (lane & 15)) * G_AST
                        + kk * 16 + (lane >> 4) * 8;
                ldm4(ah[mt], &Ash[idx]);
                ldm4(al[mt], &Asl[idx]);
            }
#pragma unroll
            for (int g = 0; g < 2; ++g) {
                int idx = (buf * 64 + kk * 16 + (lane & 15)) * G_BST
                        + wn * 32 + g * 16 + (lane >> 4) * 8;
                ldm4t(bh[g], &Bsh[idx]);
                ldm4t(bl[g], &Bsl[idx]);
            }
#pragma unroll
            for (int mt = 0; mt < 4; ++mt)
#pragma unroll
                for (int g = 0; g < 2; ++g) {
                    uint32_t bh0[2] = { bh[g][0], bh[g][1] }, bh1[2] = { bh[g][2], bh[g][3] };
                    uint32_t bl0[2] = { bl[g][0], bl[g][1] }, bl1[2] = { bl[g][2], bl[g][3] };
                    mma16816(acc[mt][2 * g],     ah[mt], bh0);
                    mma16816(acc[mt][2 * g],     ah[mt], bl0);
                    mma16816(acc[mt][2 * g],     al[mt], bh0);
                    mma16816(acc[mt][2 * g + 1], ah[mt], bh1);
                    mma16816(acc[mt][2 * g + 1], ah[mt], bl1);
                    mma16816(acc[mt][2 * g + 1], al[mt], bh1);
                }
        }
        __syncthreads();
    }

    // epilogue
#pragma unroll
    for (int mt = 0; mt < 4; ++mt)
#pragma unroll
        for (int nt = 0; nt < 4; ++nt) {
            int row = m0 + wm * 64 + mt * 16 + (lane >> 2);
            int col = n0 + wn * 32 + nt * 8 + (lane & 3) * 2;
            float b0 = bias[col], b1 = bias[col + 1];
            float v00 = acc[mt][nt][0] + b0, v01 = acc[mt][nt][1] + b1;
            float v10 = acc[mt][nt][2] + b0, v11 = acc[mt][nt][3] + b1;
            size_t i0 = (size_t)row * N + col;
            size_t i1 = (size_t)(row + 8) * N + col;
            if (Cf) {
                *(float2*)(Cf + i0) = make_float2(v00, v01);
                *(float2*)(Cf + i1) = make_float2(v10, v11);
            } else {
                __nv_bfloat162 h0 = __floats2bfloat162_rn(v00, v01);
                __nv_bfloat162 h1 = __floats2bfloat162_rn(v10, v11);
                *(uint32_t*)(Ch + i0) = b2u(h0);
                *(uint32_t*)(Ch + i1) = b2u(h1);
                *(uint32_t*)(Cl + i0) = packbf(v00 - __low2float(h0), v01 - __high2float(h0));
                *(uint32_t*)(Cl + i1) = packbf(v10 - __low2float(h1), v11 - __high2float(h1));
            }
        }
}

// ---------------- split-bf16 flash attention ----------------
// BQ=128 (8 warps x 16 rows), TKV=64, HD=64, online softmax.
#define A_QST 72
#define A_KST 72
#define ATTN_SMEM ((2*128*A_QST + 4*2*64*A_KST) * (int)sizeof(bf16) + 2*64*(int)sizeof(float))

__global__ __launch_bounds__(256) void attn_mma(
    const bf16* __restrict__ Qh, const bf16* __restrict__ Ql,
    const bf16* __restrict__ Kh, const bf16* __restrict__ Kl,
    const bf16* __restrict__ Vh, const bf16* __restrict__ Vl,
    bf16* __restrict__ Ah, bf16* __restrict__ Al)
{
    extern __shared__ char sm[];
    bf16* Qs_h = (bf16*)sm;
    bf16* Qs_l = Qs_h + 128 * A_QST;
    bf16* Ks_h = Qs_l + 128 * A_QST;
    bf16* Ks_l = Ks_h + 2 * 64 * A_KST;
    bf16* Vs_h = Ks_l + 2 * 64 * A_KST;
    bf16* Vs_l = Vs_h + 2 * 64 * A_KST;
    float* mbs = (float*)(Vs_l + 2 * 64 * A_KST);

    int tid = threadIdx.x, lane = tid & 31, wid = tid >> 5;
    int q0 = blockIdx.x * 128, h = blockIdx.y, b = blockIdx.z;

#pragma unroll
    for (int c = tid; c < 1024; c += 256) {
        int r = c >> 3, col = (c & 7) * 8;
        size_t src = (size_t)(b * SQc + q0 + r) * Hc + h * HDc + col;
        cpa16(&Qs_h[r * A_QST + col], Qh + src);
        cpa16(&Qs_l[r * A_QST + col], Ql + src);
    }
    cp_commit();

    auto load_kv = [&](int it, int buf) {
        int t0 = it * 64;
#pragma unroll
        for (int c = tid; c < 512; c += 256) {
            int r = c >> 3, col = (c & 7) * 8;
            size_t src = (size_t)(b * SKVc + t0 + r) * Hc + h * HDc + col;
            cpa16(&Ks_h[(buf * 64 + r) * A_KST + col], Kh + src);
            cpa16(&Ks_l[(buf * 64 + r) * A_KST + col], Kl + src);
            cpa16(&Vs_h[(buf * 64 + r) * A_KST + col], Vh + src);
            cpa16(&Vs_l[(buf * 64 + r) * A_KST + col], Vl + src);
        }
        if (tid < 16)
            cpa16(&mbs[buf * 64 + tid * 4], g_maskbias + b * SKVc + t0 + tid * 4);
    };

    load_kv(0, 0);
    cp_commit();
    cp_wait<1>();
    __syncthreads();

    uint32_t qh[4][4], ql[4][4];
    {
        int r = wid * 16 + (lane & 15);
#pragma unroll
        for (int kk = 0; kk < 4; ++kk) {
            int idx = r * A_QST + kk * 16 + (lane >> 4) * 8;
            ldm4(qh[kk], &Qs_h[idx]);
            ldm4(ql[kk], &Qs_l[idx]);
        }
    }

    float o[8][4];
#pragma unroll
    for (int i = 0; i < 8; i++)
#pragma unroll
        for (int j = 0; j < 4; j++) o[i][j] = 0.0f;
    float m0r = -CUDART_INF_F, m1r = -CUDART_INF_F;
    float l0r = 0.0f, l1r = 0.0f;

    const int NT = SKVc / 64;
    for (int it = 0; it < NT; ++it) {
        int buf = it & 1;
        if (it + 1 < NT) { load_kv(it + 1, buf ^ 1); cp_commit(); cp_wait<1>(); }
        else             { cp_wait<0>(); }
        __syncthreads();

        float s[8][4];
#pragma unroll
        for (int i = 0; i < 8; i++)
#pragma unroll
            for (int j = 0; j < 4; j++) s[i][j] = 0.0f;

#pragma unroll
        for (int kk = 0; kk < 4; ++kk) {
#pragma unroll
            for (int g = 0; g < 4; ++g) {
                uint32_t kh[4], kl[4];
                int idx = (buf * 64 + g * 16 + (lane & 15)) * A_KST
                        + kk * 16 + (lane >> 4) * 8;
                ldm4(kh, &Ks_h[idx]);
                ldm4(kl, &Ks_l[idx]);
                uint32_t b0h[2] = { kh[0], kh[2] }, b1h[2] = { kh[1], kh[3] };
                uint32_t b0l[2] = { kl[0], kl[2] }, b1l[2] = { kl[1], kl[3] };
                mma16816(s[2 * g],     qh[kk], b0h);
                mma16816(s[2 * g],     qh[kk], b0l);
                mma16816(s[2 * g],     ql[kk], b0h);
                mma16816(s[2 * g + 1], qh[kk], b1h);
                mma16816(s[2 * g + 1], qh[kk], b1l);
                mma16816(s[2 * g + 1], ql[kk], b1h);
            }
        }

        float tm0 = -CUDART_INF_F, tm1 = -CUDART_INF_F;
#pragma unroll
        for (int nt = 0; nt < 8; ++nt) {
            int cb = nt * 8 + (lane & 3) * 2;
            float mb0 = mbs[buf * 64 + cb], mb1 = mbs[buf * 64 + cb + 1];
            s[nt][0] = s[nt][0] * 0.125f + mb0;
            s[nt][1] = s[nt][1] * 0.125f + mb1;
            s[nt][2] = s[nt][2] * 0.125f + mb0;
            s[nt][3] = s[nt][3] * 0.125f + mb1;
            tm0 = fmaxf(tm0, fmaxf(s[nt][0], s[nt][1]));
            tm1 = fmaxf(tm1, fmaxf(s[nt][2], s[nt][3]));
        }
        tm0 = fmaxf(tm0, __shfl_xor_sync(0xffffffffu, tm0, 1));
        tm0 = fmaxf(tm0, __shfl_xor_sync(0xffffffffu, tm0, 2));
        tm1 = fmaxf(tm1, __shfl_xor_sync(0xffffffffu, tm1, 1));
        tm1 = fmaxf(tm1, __shfl_xor_sync(0xffffffffu, tm1, 2));
        float mn0 = fmaxf(m0r, tm0), mn1 = fmaxf(m1r, tm1);
        float al0 = __expf(m0r - mn0), al1 = __expf(m1r - mn1);
        m0r = mn0; m1r = mn1;

        float rs0 = 0.0f, rs1 = 0.0f;
#pragma unroll
        for (int nt = 0; nt < 8; ++nt) {
            s[nt][0] = __expf(s[nt][0] - mn0);
            s[nt][1] = __expf(s[nt][1] - mn0);
            s[nt][2] = __expf(s[nt][2] - mn1);
            s[nt][3] = __expf(s[nt][3] - mn1);
            rs0 += s[nt][0] + s[nt][1];
            rs1 += s[nt][2] + s[nt][3];
        }
        rs0 += __shfl_xor_sync(0xffffffffu, rs0, 1);
        rs0 += __shfl_xor_sync(0xffffffffu, rs0, 2);
        rs1 += __shfl_xor_sync(0xffffffffu, rs1, 1);
        rs1 += __shfl_xor_sync(0xffffffffu, rs1, 2);
        l0r = l0r * al0 + rs0;
        l1r = l1r * al1 + rs1;

#pragma unroll
        for (int dn = 0; dn < 8; ++dn) {
            o[dn][0] *= al0; o[dn][1] *= al0;
            o[dn][2] *= al1; o[dn][3] *= al1;
        }

#pragma unroll
        for (int kt = 0; kt < 4; ++kt) {
            float x0 = s[2 * kt][0], x1 = s[2 * kt][1], x2 = s[2 * kt][2], x3 = s[2 * kt][3];
            float y0 = s[2 * kt + 1][0], y1 = s[2 * kt + 1][1];
            float y2 = s[2 * kt + 1][2], y3 = s[2 * kt + 1][3];
            __nv_bfloat162 hx0 = __floats2bfloat162_rn(x0, x1);
            __nv_bfloat162 hx1 = __floats2bfloat162_rn(x2, x3);
            __nv_bfloat162 hy0 = __floats2bfloat162_rn(y0, y1);
            __nv_bfloat162 hy1 = __floats2bfloat162_rn(y2, y3);
            uint32_t pah[4] = { b2u(hx0), b2u(hx1), b2u(hy0), b2u(hy1) };
            uint32_t pal[4] = {
                packbf(x0 - __low2float(hx0), x1 - __high2float(hx0)),
                packbf(x2 - __low2float(hx1), x3 - __high2float(hx1)),
                packbf(y0 - __low2float(hy0), y1 - __high2float(hy0)),
                packbf(y2 - __low2float(hy1), y3 - __high2float(hy1))
            };
#pragma unroll
            for (int dg = 0; dg < 4; ++dg) {
                uint32_t vh[4], vl[4];
                int idx = (buf * 64 + kt * 16 + (lane & 15)) * A_KST
                        + dg * 16 + (lane >> 4) * 8;
                ldm4t(vh, &Vs_h[idx]);
                ldm4t(vl, &Vs_l[idx]);
                uint32_t b0h[2] = { vh[0], vh[1] }, b1h[2] = { vh[2], vh[3] };
                uint32_t b0l[2] = { vl[0], vl[1] }, b1l[2] = { vl[2], vl[3] };
                mma16816(o[2 * dg],     pah, b0h);
                mma16816(o[2 * dg],     pah, b0l);
                mma16816(o[2 * dg],     pal, b0h);
                mma16816(o[2 * dg + 1], pah, b1h);
                mma16816(o[2 * dg + 1], pah, b1l);
                mma16816(o[2 * dg + 1], pal, b1h);
            }
        }
        __syncthreads();
    }

    float inv0 = 1.0f / l0r, inv1 = 1.0f / l1r;
#pragma unroll
    for (int dn = 0; dn < 8; ++dn) {
        int row = q0 + wid * 16 + (lane >> 2);
        int col = h * HDc + dn * 8 + (lane & 3) * 2;
        float v00 = o[dn][0] * inv0, v01 = o[dn][1] * inv0;
        float v10 = o[dn][2] * inv1, v11 = o[dn][3] * inv1;
        size_t i0 = (size_t)(b * SQc + row) * Hc + col;
        size_t i1 = (size_t)(b * SQc + row + 8) * Hc + col;
        __nv_bfloat162 h0 = __floats2bfloat162_rn(v00, v01);
        __nv_bfloat162 h1 = __floats2bfloat162_rn(v10, v11);
        *(uint32_t*)(Ah + i0) = b2u(h0);
        *(uint32_t*)(Ah + i1) = b2u(h1);
        *(uint32_t*)(Al + i0) = packbf(v00 - __low2float(h0), v01 - __high2float(h0));
        *(uint32_t*)(Al + i1) = packbf(v10 - __low2float(h1), v11 - __high2float(h1));
    }
}

// ---------------- launch ----------------
// Launch order is load-bearing for profiling: mask(1), split_all(2),
// gemm Q(3), K(4), V(5), attn(6) <- ncu -s 5 -c 1 captures this, gemm O(7).
extern "C" void kernel_launch(void* const* d_in, const int* in_sizes, int n_in,
                              void* d_out, int out_size)
{
    (void)in_sizes; (void)n_in; (void)out_size;

    bf16 *Xq_h, *Xq_l, *Xkv_h, *Xkv_l;
    bf16 *Wq_h, *Wq_l, *Wk_h, *Wk_l, *Wv_h, *Wv_l, *Wo_h, *Wo_l;
    bf16 *Q_h, *Q_l, *K_h, *K_l, *V_h, *V_l, *A_h, *A_l;
    cudaGetSymbolAddress((void**)&Xq_h, g_Xq_h);   cudaGetSymbolAddress((void**)&Xq_l, g_Xq_l);
    cudaGetSymbolAddress((void**)&Xkv_h, g_Xkv_h); cudaGetSymbolAddress((void**)&Xkv_l, g_Xkv_l);
    cudaGetSymbolAddress((void**)&Wq_h, g_Wq_h);   cudaGetSymbolAddress((void**)&Wq_l, g_Wq_l);
    cudaGetSymbolAddress((void**)&Wk_h, g_Wk_h);   cudaGetSymbolAddress((void**)&Wk_l, g_Wk_l);
    cudaGetSymbolAddress((void**)&Wv_h, g_Wv_h);   cudaGetSymbolAddress((void**)&Wv_l, g_Wv_l);
    cudaGetSymbolAddress((void**)&Wo_h, g_Wo_h);   cudaGetSymbolAddress((void**)&Wo_l, g_Wo_l);
    cudaGetSymbolAddress((void**)&Q_h, g_Q_h);     cudaGetSymbolAddress((void**)&Q_l, g_Q_l);
    cudaGetSymbolAddress((void**)&K_h, g_K_h);     cudaGetSymbolAddress((void**)&K_l, g_K_l);
    cudaGetSymbolAddress((void**)&V_h, g_V_h);     cudaGetSymbolAddress((void**)&V_l, g_V_l);
    cudaGetSymbolAddress((void**)&A_h, g_A_h);     cudaGetSymbolAddress((void**)&A_l, g_A_l);

    cudaFuncSetAttribute(gemm_split, cudaFuncAttributeMaxDynamicSharedMemorySize, GEMM_SMEM);
    cudaFuncSetAttribute(attn_mma,   cudaFuncAttributeMaxDynamicSharedMemorySize, ATTN_SMEM);

    // (1) mask
    mask_kernel<<<1, 256>>>((const unsigned char*)d_in[2]);

    // (2) all splits in one launch
    SplitArgs sa;
    sa.src[0] = (const float*)d_in[0]; sa.hi[0] = Xq_h;  sa.lo[0] = Xq_l;  sa.n4[0] = Mrows * Dc / 4;
    sa.src[1] = (const float*)d_in[1]; sa.hi[1] = Xkv_h; sa.lo[1] = Xkv_l; sa.n4[1] = Mrows * Dc / 4;
    sa.src[2] = (const float*)d_in[3]; sa.hi[2] = Wq_h;  sa.lo[2] = Wq_l;  sa.n4[2] = Dc * Hc / 4;
    sa.src[3] = (const float*)d_in[5]; sa.hi[3] = Wk_h;  sa.lo[3] = Wk_l;  sa.n4[3] = Dc * Hc / 4;
    sa.src[4] = (const float*)d_in[7]; sa.hi[4] = Wv_h;  sa.lo[4] = Wv_l;  sa.n4[4] = Dc * Hc / 4;
    sa.src[5] = (const float*)d_in[9]; sa.hi[5] = Wo_h;  sa.lo[5] = Wo_l;  sa.n4[5] = Hc * Dc / 4;
    split_all<<<dim3((Mrows * Dc / 4 + 255) / 256, 6), 256>>>(sa);

    // (3,4,5) projections
    dim3 pg(Hc / 128, Mrows / 128);   // (8, 32)
    gemm_split<<<pg, 256, GEMM_SMEM>>>(Xq_h, Xq_l, Wq_h, Wq_l, (const float*)d_in[4],
                                       Q_h, Q_l, nullptr, Mrows, Hc, Dc);
    gemm_split<<<pg, 256, GEMM_SMEM>>>(Xkv_h, Xkv_l, Wk_h, Wk_l, (const float*)d_in[6],
                                       K_h, K_l, nullptr, Mrows, Hc, Dc);
    gemm_split<<<pg, 256, GEMM_SMEM>>>(Xkv_h, Xkv_l, Wv_h, Wv_l, (const float*)d_in[8],
                                       V_h, V_l, nullptr, Mrows, Hc, Dc);

    // (6) attention — profiled slot
    attn_mma<<<dim3(SQc / 128, NHc, Bc), 256, ATTN_SMEM>>>(Q_h, Q_l, K_h, K_l,
                                                           V_h, V_l, A_h, A_l);

    // (7) output projection
    dim3 og(Dc / 128, Mrows / 128);   // (8, 32)
    gemm_split<<<og, 256, GEMM_SMEM>>>(A_h, A_l, Wo_h, Wo_l, (const float*)d_in[10],
                                       nullptr, nullptr, (float*)d_out, Mrows, Dc, Hc);
}

// round 6
// speedup vs baseline: 2.9463x; 1.0190x over previous
#include <cuda_runtime.h>
#include <cuda_bf16.h>
#include <math_constants.h>
#include <cstdint>

#define Bc    2
#define SQc   2048
#define SKVc  2048
#define Dc    1024
#define Hc    1024
#define NHc   16
#define HDc   64
#define Mrows 4096

typedef __nv_bfloat16 bf16;

// ---------------- scratch (device globals, allocation-free) ----------------
__device__ bf16 g_Xq_h[(size_t)Mrows * Dc],  g_Xq_l[(size_t)Mrows * Dc];
__device__ bf16 g_Xkv_h[(size_t)Mrows * Dc], g_Xkv_l[(size_t)Mrows * Dc];
__device__ bf16 g_Wq_h[(size_t)Dc * Hc], g_Wq_l[(size_t)Dc * Hc];
__device__ bf16 g_Wk_h[(size_t)Dc * Hc], g_Wk_l[(size_t)Dc * Hc];
__device__ bf16 g_Wv_h[(size_t)Dc * Hc], g_Wv_l[(size_t)Dc * Hc];
__device__ bf16 g_Wo_h[(size_t)Hc * Dc], g_Wo_l[(size_t)Hc * Dc];
__device__ bf16 g_Q_h[(size_t)Mrows * Hc], g_Q_l[(size_t)Mrows * Hc];
__device__ bf16 g_K_h[(size_t)Mrows * Hc], g_K_l[(size_t)Mrows * Hc];
__device__ bf16 g_V_h[(size_t)Mrows * Hc], g_V_l[(size_t)Mrows * Hc];
__device__ bf16 g_A_h[(size_t)Mrows * Hc], g_A_l[(size_t)Mrows * Hc];
__device__ float g_maskbias[Bc * SKVc];

// ---------------- small helpers ----------------
__device__ __forceinline__ uint32_t smem_u32(const void* p) {
    return (uint32_t)__cvta_generic_to_shared(p);
}
__device__ __forceinline__ void cpa16(void* dst, const void* src) {
    asm volatile("cp.async.cg.shared.global [%0], [%1], 16;\n"
                 :: "r"(smem_u32(dst)), "l"(src));
}
__device__ __forceinline__ void cp_commit() { asm volatile("cp.async.commit_group;\n"); }
template <int N> __device__ __forceinline__ void cp_wait() {
    asm volatile("cp.async.wait_group %0;\n" :: "n"(N) : "memory");
}
__device__ __forceinline__ void ldm4(uint32_t r[4], const void* p) {
    asm volatile("ldmatrix.sync.aligned.m8n8.x4.shared.b16 {%0,%1,%2,%3}, [%4];\n"
                 : "=r"(r[0]), "=r"(r[1]), "=r"(r[2]), "=r"(r[3]) : "r"(smem_u32(p)));
}
__device__ __forceinline__ void ldm4t(uint32_t r[4], const void* p) {
    asm volatile("ldmatrix.sync.aligned.m8n8.x4.trans.shared.b16 {%0,%1,%2,%3}, [%4];\n"
                 : "=r"(r[0]), "=r"(r[1]), "=r"(r[2]), "=r"(r[3]) : "r"(smem_u32(p)));
}
__device__ __forceinline__ void mma16816(float c[4], const uint32_t a[4], const uint32_t b[2]) {
    asm volatile("mma.sync.aligned.m16n8k16.row.col.f32.bf16.bf16.f32 "
                 "{%0,%1,%2,%3}, {%4,%5,%6,%7}, {%8,%9}, {%0,%1,%2,%3};\n"
                 : "+f"(c[0]), "+f"(c[1]), "+f"(c[2]), "+f"(c[3])
                 : "r"(a[0]), "r"(a[1]), "r"(a[2]), "r"(a[3]), "r"(b[0]), "r"(b[1]));
}
__device__ __forceinline__ uint32_t b2u(__nv_bfloat162 v) {
    return *reinterpret_cast<uint32_t*>(&v);
}
__device__ __forceinline__ uint32_t packbf(float a, float b) {
    __nv_bfloat162 t = __floats2bfloat162_rn(a, b);
    return b2u(t);
}

// ---------------- fused mask detect + bias build (single block) ----------------
__global__ void mask_kernel(const unsigned char* __restrict__ m) {
    __shared__ int nz[4];
    int tid = threadIdx.x;
    if (tid < 4) nz[tid] = 0;
    __syncthreads();
    for (int p = tid; p < Bc * SKVc; p += blockDim.x)
        if (m[p]) atomicOr(&nz[p & 3], 1);
    __syncthreads();
    int kind = 0;
    if (!nz[1] && !nz[2] && !nz[3]) kind = 1;       // int32 0/1
    else if (!nz[0] && !nz[1])      kind = 2;       // float32 0/1
    for (int i = tid; i < Bc * SKVc; i += blockDim.x) {
        bool mk;
        if (kind == 1)      mk = ((const int*)m)[i] != 0;
        else if (kind == 2) mk = ((const float*)m)[i] != 0.0f;
        else                mk = m[i] != 0;
        g_maskbias[i] = mk ? -1e30f : 0.0f;
    }
}

// ---------------- fused split: all 6 tensors in one launch (z-sliced) ----------
struct SplitArgs {
    const float* src[6];
    bf16* hi[6];
    bf16* lo[6];
    int   n4[6];     // element count / 4
};
__global__ __launch_bounds__(256) void split_all(SplitArgs a) {
    int z = blockIdx.y;
    int i4 = blockIdx.x * 256 + threadIdx.x;
    if (i4 >= a.n4[z]) return;
    float4 v = ((const float4*)a.src[z])[i4];
    __nv_bfloat162 h0 = __floats2bfloat162_rn(v.x, v.y);
    __nv_bfloat162 h1 = __floats2bfloat162_rn(v.z, v.w);
    uint32_t l0 = packbf(v.x - __low2float(h0), v.y - __high2float(h0));
    uint32_t l1 = packbf(v.z - __low2float(h1), v.w - __high2float(h1));
    ((uint2*)a.hi[z])[i4] = make_uint2(b2u(h0), b2u(h1));
    ((uint2*)a.lo[z])[i4] = make_uint2(l0, l1);
}

// ---------------- split-bf16 GEMM: C = A@W + bias ----------------
// BM=128, BN=128, BK=32, 3 stages, 256 threads, 2 CTAs/SM target.
#define G_AST 40
#define G_BST 136
#define G_STG 3
#define GEMM_SMEM (G_STG * (128 * G_AST + 32 * G_BST) * 2 * (int)sizeof(bf16))

__global__ __launch_bounds__(256, 2) void gemm_split(
    const bf16* __restrict__ Ah, const bf16* __restrict__ Al,
    const bf16* __restrict__ Wh, const bf16* __restrict__ Wl,
    const float* __restrict__ bias,
    bf16* __restrict__ Ch, bf16* __restrict__ Cl, float* __restrict__ Cf,
    int M, int N, int K)
{
    extern __shared__ char sm[];
    bf16* Ash = (bf16*)sm;                            // [3][128][G_AST]
    bf16* Asl = Ash + G_STG * 128 * G_AST;
    bf16* Bsh = Asl + G_STG * 128 * G_AST;            // [3][32][G_BST]
    bf16* Bsl = Bsh + G_STG * 32 * G_BST;

    int tid = threadIdx.x, lane = tid & 31, wid = tid >> 5;
    int wm = wid & 1, wn = wid >> 1;
    int m0 = blockIdx.y * 128, n0 = blockIdx.x * 128;

    float acc[4][4][4];
#pragma unroll
    for (int i = 0; i < 4; i++)
#pragma unroll
        for (int j = 0; j < 4; j++)
#pragma unroll
            for (int e = 0; e < 4; e++) acc[i][j][e] = 0.0f;

    auto load_tiles = [&](int it, int s) {
        int k0 = it * 32;
#pragma unroll
        for (int x = tid; x < 1024; x += 256) {       // A hi/lo: 128 rows x 32 cols
            int mat = x >> 9, i = x & 511;
            int r = i >> 2, kc = (i & 3) * 8;
            const bf16* src = (mat ? Al : Ah) + (size_t)(m0 + r) * K + k0 + kc;
            bf16* dst = (mat ? Asl : Ash) + (s * 128 + r) * G_AST + kc;
            cpa16(dst, src);
        }
#pragma unroll
        for (int x = tid; x < 1024; x += 256) {       // B hi/lo: 32 rows x 128 cols
            int mat = x >> 9, i = x & 511;
            int r = i >> 4, nc = (i & 15) * 8;
            const bf16* src = (mat ? Wl : Wh) + (size_t)(k0 + r) * N + n0 + nc;
            bf16* dst = (mat ? Bsl : Bsh) + (s * 32 + r) * G_BST + nc;
            cpa16(dst, src);
        }
    };

    int NIT = K / 32;                                  // 32
    load_tiles(0, 0); cp_commit();
    load_tiles(1, 1); cp_commit();

    int s = 0, s2 = 2;                                 // s = it%3, s2 = (it+2)%3
    for (int it = 0; it < NIT; ++it) {
        if (it + 2 < NIT) { load_tiles(it + 2, s2); cp_commit(); cp_wait<2>(); }
        else if (it + 1 < NIT) { cp_wait<1>(); }
        else { cp_wait<0>(); }
        __syncthreads();

#pragma unroll
        for (int kk = 0; kk < 2; ++kk) {
            uint32_t ah[4][4], al[4][4], bh[2][4], bl[2][4];
#pragma unroll
            for (int mt = 0; mt < 4; ++mt) {
                int idx = (s * 128 + wm * 64 + mt * 16 + (lane & 15)) * G_AST
                        + kk * 16 + (lane >> 4) * 8;
                ldm4(ah[mt], &Ash[idx]);
                ldm4(al[mt], &Asl[idx]);
            }
#pragma unroll
            for (int g = 0; g < 2; ++g) {
                int idx = (s * 32 + kk * 16 + (lane & 15)) * G_BST
                        + wn * 32 + g * 16 + (lane >> 4) * 8;
                ldm4t(bh[g], &Bsh[idx]);
                ldm4t(bl[g], &Bsl[idx]);
            }
#pragma unroll
            for (int mt = 0; mt < 4; ++mt)
#pragma unroll
                for (int g = 0; g < 2; ++g) {
                    uint32_t bh0[2] = { bh[g][0], bh[g][1] }, bh1[2] = { bh[g][2], bh[g][3] };
                    uint32_t bl0[2] = { bl[g][0], bl[g][1] }, bl1[2] = { bl[g][2], bl[g][3] };
                    mma16816(acc[mt][2 * g],     ah[mt], bh0);
                    mma16816(acc[mt][2 * g],     ah[mt], bl0);
                    mma16816(acc[mt][2 * g],     al[mt], bh0);
                    mma16816(acc[mt][2 * g + 1], ah[mt], bh1);
                    mma16816(acc[mt][2 * g + 1], ah[mt], bl1);
                    mma16816(acc[mt][2 * g + 1], al[mt], bh1);
                }
        }
        __syncthreads();
        s  = (s  == 2) ? 0 : s + 1;
        s2 = (s2 == 2) ? 0 : s2 + 1;
    }

    // epilogue
#pragma unroll
    for (int mt = 0; mt < 4; ++mt)
#pragma unroll
        for (int nt = 0; nt < 4; ++nt) {
            int row = m0 + wm * 64 + mt * 16 + (lane >> 2);
            int col = n0 + wn * 32 + nt * 8 + (lane & 3) * 2;
            float b0 = bias[col], b1 = bias[col + 1];
            float v00 = acc[mt][nt][0] + b0, v01 = acc[mt][nt][1] + b1;
            float v10 = acc[mt][nt][2] + b0, v11 = acc[mt][nt][3] + b1;
            size_t i0 = (size_t)row * N + col;
            size_t i1 = (size_t)(row + 8) * N + col;
            if (Cf) {
                *(float2*)(Cf + i0) = make_float2(v00, v01);
                *(float2*)(Cf + i1) = make_float2(v10, v11);
            } else {
                __nv_bfloat162 h0 = __floats2bfloat162_rn(v00, v01);
                __nv_bfloat162 h1 = __floats2bfloat162_rn(v10, v11);
                *(uint32_t*)(Ch + i0) = b2u(h0);
                *(uint32_t*)(Ch + i1) = b2u(h1);
                *(uint32_t*)(Cl + i0) = packbf(v00 - __low2float(h0), v01 - __high2float(h0));
                *(uint32_t*)(Cl + i1) = packbf(v10 - __low2float(h1), v11 - __high2float(h1));
            }
        }
}

// ---------------- split-bf16 flash attention (unchanged) ----------------
#define A_QST 72
#define A_KST 72
#define ATTN_SMEM ((2*128*A_QST + 4*2*64*A_KST) * (int)sizeof(bf16) + 2*64*(int)sizeof(float))

__global__ __launch_bounds__(256) void attn_mma(
    const bf16* __restrict__ Qh, const bf16* __restrict__ Ql,
    const bf16* __restrict__ Kh, const bf16* __restrict__ Kl,
    const bf16* __restrict__ Vh, const bf16* __restrict__ Vl,
    bf16* __restrict__ Ah, bf16* __restrict__ Al)
{
    extern __shared__ char sm[];
    bf16* Qs_h = (bf16*)sm;
    bf16* Qs_l = Qs_h + 128 * A_QST;
    bf16* Ks_h = Qs_l + 128 * A_QST;
    bf16* Ks_l = Ks_h + 2 * 64 * A_KST;
    bf16* Vs_h = Ks_l + 2 * 64 * A_KST;
    bf16* Vs_l = Vs_h + 2 * 64 * A_KST;
    float* mbs = (float*)(Vs_l + 2 * 64 * A_KST);

    int tid = threadIdx.x, lane = tid & 31, wid = tid >> 5;
    int q0 = blockIdx.x * 128, h = blockIdx.y, b = blockIdx.z;

#pragma unroll
    for (int c = tid; c < 1024; c += 256) {
        int r = c >> 3, col = (c & 7) * 8;
        size_t src = (size_t)(b * SQc + q0 + r) * Hc + h * HDc + col;
        cpa16(&Qs_h[r * A_QST + col], Qh + src);
        cpa16(&Qs_l[r * A_QST + col], Ql + src);
    }
    cp_commit();

    auto load_kv = [&](int it, int buf) {
        int t0 = it * 64;
#pragma unroll
        for (int c = tid; c < 512; c += 256) {
            int r = c >> 3, col = (c & 7) * 8;
            size_t src = (size_t)(b * SKVc + t0 + r) * Hc + h * HDc + col;
            cpa16(&Ks_h[(buf * 64 + r) * A_KST + col], Kh + src);
            cpa16(&Ks_l[(buf * 64 + r) * A_KST + col], Kl + src);
            cpa16(&Vs_h[(buf * 64 + r) * A_KST + col], Vh + src);
            cpa16(&Vs_l[(buf * 64 + r) * A_KST + col], Vl + src);
        }
        if (tid < 16)
            cpa16(&mbs[buf * 64 + tid * 4], g_maskbias + b * SKVc + t0 + tid * 4);
    };

    load_kv(0, 0);
    cp_commit();
    cp_wait<1>();
    __syncthreads();

    uint32_t qh[4][4], ql[4][4];
    {
        int r = wid * 16 + (lane & 15);
#pragma unroll
        for (int kk = 0; kk < 4; ++kk) {
            int idx = r * A_QST + kk * 16 + (lane >> 4) * 8;
            ldm4(qh[kk], &Qs_h[idx]);
            ldm4(ql[kk], &Qs_l[idx]);
        }
    }

    float o[8][4];
#pragma unroll
    for (int i = 0; i < 8; i++)
#pragma unroll
        for (int j = 0; j < 4; j++) o[i][j] = 0.0f;
    float m0r = -CUDART_INF_F, m1r = -CUDART_INF_F;
    float l0r = 0.0f, l1r = 0.0f;

    const int NT = SKVc / 64;
    for (int it = 0; it < NT; ++it) {
        int buf = it & 1;
        if (it + 1 < NT) { load_kv(it + 1, buf ^ 1); cp_commit(); cp_wait<1>(); }
        else             { cp_wait<0>(); }
        __syncthreads();

        float s[8][4];
#pragma unroll
        for (int i = 0; i < 8; i++)
#pragma unroll
            for (int j = 0; j < 4; j++) s[i][j] = 0.0f;

#pragma unroll
        for (int kk = 0; kk < 4; ++kk) {
#pragma unroll
            for (int g = 0; g < 4; ++g) {
                uint32_t kh[4], kl[4];
                int idx = (buf * 64 + g * 16 + (lane & 15)) * A_KST
                        + kk * 16 + (lane >> 4) * 8;
                ldm4(kh, &Ks_h[idx]);
                ldm4(kl, &Ks_l[idx]);
                uint32_t b0h[2] = { kh[0], kh[2] }, b1h[2] = { kh[1], kh[3] };
                uint32_t b0l[2] = { kl[0], kl[2] }, b1l[2] = { kl[1], kl[3] };
                mma16816(s[2 * g],     qh[kk], b0h);
                mma16816(s[2 * g],     qh[kk], b0l);
                mma16816(s[2 * g],     ql[kk], b0h);
                mma16816(s[2 * g + 1], qh[kk], b1h);
                mma16816(s[2 * g + 1], qh[kk], b1l);
                mma16816(s[2 * g + 1], ql[kk], b1h);
            }
        }

        float tm0 = -CUDART_INF_F, tm1 = -CUDART_INF_F;
#pragma unroll
        for (int nt = 0; nt < 8; ++nt) {
            int cb = nt * 8 + (lane & 3) * 2;
            float mb0 = mbs[buf * 64 + cb], mb1 = mbs[buf * 64 + cb + 1];
            s[nt][0] = s[nt][0] * 0.125f + mb0;
            s[nt][1] = s[nt][1] * 0.125f + mb1;
            s[nt][2] = s[nt][2] * 0.125f + mb0;
            s[nt][3] = s[nt][3] * 0.125f + mb1;
            tm0 = fmaxf(tm0, fmaxf(s[nt][0], s[nt][1]));
            tm1 = fmaxf(tm1, fmaxf(s[nt][2], s[nt][3]));
        }
        tm0 = fmaxf(tm0, __shfl_xor_sync(0xffffffffu, tm0, 1));
        tm0 = fmaxf(tm0, __shfl_xor_sync(0xffffffffu, tm0, 2));
        tm1 = fmaxf(tm1, __shfl_xor_sync(0xffffffffu, tm1, 1));
        tm1 = fmaxf(tm1, __shfl_xor_sync(0xffffffffu, tm1, 2));
        float mn0 = fmaxf(m0r, tm0), mn1 = fmaxf(m1r, tm1);
        float al0 = __expf(m0r - mn0), al1 = __expf(m1r - mn1);
        m0r = mn0; m1r = mn1;

        float rs0 = 0.0f, rs1 = 0.0f;
#pragma unroll
        for (int nt = 0; nt < 8; ++nt) {
            s[nt][0] = __expf(s[nt][0] - mn0);
            s[nt][1] = __expf(s[nt][1] - mn0);
            s[nt][2] = __expf(s[nt][2] - mn1);
            s[nt][3] = __expf(s[nt][3] - mn1);
            rs0 += s[nt][0] + s[nt][1];
            rs1 += s[nt][2] + s[nt][3];
        }
        rs0 += __shfl_xor_sync(0xffffffffu, rs0, 1);
        rs0 += __shfl_xor_sync(0xffffffffu, rs0, 2);
        rs1 += __shfl_xor_sync(0xffffffffu, rs1, 1);
        rs1 += __shfl_xor_sync(0xffffffffu, rs1, 2);
        l0r = l0r * al0 + rs0;
        l1r = l1r * al1 + rs1;

#pragma unroll
        for (int dn = 0; dn < 8; ++dn) {
            o[dn][0] *= al0; o[dn][1] *= al0;
            o[dn][2] *= al1; o[dn][3] *= al1;
        }

#pragma unroll
        for (int kt = 0; kt < 4; ++kt) {
            float x0 = s[2 * kt][0], x1 = s[2 * kt][1], x2 = s[2 * kt][2], x3 = s[2 * kt][3];
            float y0 = s[2 * kt + 1][0], y1 = s[2 * kt + 1][1];
            float y2 = s[2 * kt + 1][2], y3 = s[2 * kt + 1][3];
            __nv_bfloat162 hx0 = __floats2bfloat162_rn(x0, x1);
            __nv_bfloat162 hx1 = __floats2bfloat162_rn(x2, x3);
            __nv_bfloat162 hy0 = __floats2bfloat162_rn(y0, y1);
            __nv_bfloat162 hy1 = __floats2bfloat162_rn(y2, y3);
            uint32_t pah[4] = { b2u(hx0), b2u(hx1), b2u(hy0), b2u(hy1) };
            uint32_t pal[4] = {
                packbf(x0 - __low2float(hx0), x1 - __high2float(hx0)),
                packbf(x2 - __low2float(hx1), x3 - __high2float(hx1)),
                packbf(y0 - __low2float(hy0), y1 - __high2float(hy0)),
                packbf(y2 - __low2float(hy1), y3 - __high2float(hy1))
            };
#pragma unroll
            for (int dg = 0; dg < 4; ++dg) {
                uint32_t vh[4], vl[4];
                int idx = (buf * 64 + kt * 16 + (lane & 15)) * A_KST
                        + dg * 16 + (lane >> 4) * 8;
                ldm4t(vh, &Vs_h[idx]);
                ldm4t(vl, &Vs_l[idx]);
                uint32_t b0h[2] = { vh[0], vh[1] }, b1h[2] = { vh[2], vh[3] };
                uint32_t b0l[2] = { vl[0], vl[1] }, b1l[2] = { vl[2], vl[3] };
                mma16816(o[2 * dg],     pah, b0h);
                mma16816(o[2 * dg],     pah, b0l);
                mma16816(o[2 * dg],     pal, b0h);
                mma16816(o[2 * dg + 1], pah, b1h);
                mma16816(o[2 * dg + 1], pah, b1l);
                mma16816(o[2 * dg + 1], pal, b1h);
            }
        }
        __syncthreads();
    }

    float inv0 = 1.0f / l0r, inv1 = 1.0f / l1r;
#pragma unroll
    for (int dn = 0; dn < 8; ++dn) {
        int row = q0 + wid * 16 + (lane >> 2);
        int col = h * HDc + dn * 8 + (lane & 3) * 2;
        float v00 = o[dn][0] * inv0, v01 = o[dn][1] * inv0;
        float v10 = o[dn][2] * inv1, v11 = o[dn][3] * inv1;
        size_t i0 = (size_t)(b * SQc + row) * Hc + col;
        size_t i1 = (size_t)(b * SQc + row + 8) * Hc + col;
        __nv_bfloat162 h0 = __floats2bfloat162_rn(v00, v01);
        __nv_bfloat162 h1 = __floats2bfloat162_rn(v10, v11);
        *(uint32_t*)(Ah + i0) = b2u(h0);
        *(uint32_t*)(Ah + i1) = b2u(h1);
        *(uint32_t*)(Al + i0) = packbf(v00 - __low2float(h0), v01 - __high2float(h0));
        *(uint32_t*)(Al + i1) = packbf(v10 - __low2float(h1), v11 - __high2float(h1));
    }
}

// ---------------- launch ----------------
extern "C" void kernel_launch(void* const* d_in, const int* in_sizes, int n_in,
                              void* d_out, int out_size)
{
    (void)in_sizes; (void)n_in; (void)out_size;

    bf16 *Xq_h, *Xq_l, *Xkv_h, *Xkv_l;
    bf16 *Wq_h, *Wq_l, *Wk_h, *Wk_l, *Wv_h, *Wv_l, *Wo_h, *Wo_l;
    bf16 *Q_h, *Q_l, *K_h, *K_l, *V_h, *V_l, *A_h, *A_l;
    cudaGetSymbolAddress((void**)&Xq_h, g_Xq_h);   cudaGetSymbolAddress((void**)&Xq_l, g_Xq_l);
    cudaGetSymbolAddress((void**)&Xkv_h, g_Xkv_h); cudaGetSymbolAddress((void**)&Xkv_l, g_Xkv_l);
    cudaGetSymbolAddress((void**)&Wq_h, g_Wq_h);   cudaGetSymbolAddress((void**)&Wq_l, g_Wq_l);
    cudaGetSymbolAddress((void**)&Wk_h, g_Wk_h);   cudaGetSymbolAddress((void**)&Wk_l, g_Wk_l);
    cudaGetSymbolAddress((void**)&Wv_h, g_Wv_h);   cudaGetSymbolAddress((void**)&Wv_l, g_Wv_l);
    cudaGetSymbolAddress((void**)&Wo_h, g_Wo_h);   cudaGetSymbolAddress((void**)&Wo_l, g_Wo_l);
    cudaGetSymbolAddress((void**)&Q_h, g_Q_h);     cudaGetSymbolAddress((void**)&Q_l, g_Q_l);
    cudaGetSymbolAddress((void**)&K_h, g_K_h);     cudaGetSymbolAddress((void**)&K_l, g_K_l);
    cudaGetSymbolAddress((void**)&V_h, g_V_h);     cudaGetSymbolAddress((void**)&V_l, g_V_l);
    cudaGetSymbolAddress((void**)&A_h, g_A_h);     cudaGetSymbolAddress((void**)&A_l, g_A_l);

    cudaFuncSetAttribute(gemm_split, cudaFuncAttributeMaxDynamicSharedMemorySize, GEMM_SMEM);
    cudaFuncSetAttribute(attn_mma,   cudaFuncAttributeMaxDynamicSharedMemorySize, ATTN_SMEM);

    // (1) mask
    mask_kernel<<<1, 256>>>((const unsigned char*)d_in[2]);

    // (2) all splits in one launch
    SplitArgs sa;
    sa.src[0] = (const float*)d_in[0]; sa.hi[0] = Xq_h;  sa.lo[0] = Xq_l;  sa.n4[0] = Mrows * Dc / 4;
    sa.src[1] = (const float*)d_in[1]; sa.hi[1] = Xkv_h; sa.lo[1] = Xkv_l; sa.n4[1] = Mrows * Dc / 4;
    sa.src[2] = (const float*)d_in[3]; sa.hi[2] = Wq_h;  sa.lo[2] = Wq_l;  sa.n4[2] = Dc * Hc / 4;
    sa.src[3] = (const float*)d_in[5]; sa.hi[3] = Wk_h;  sa.lo[3] = Wk_l;  sa.n4[3] = Dc * Hc / 4;
    sa.src[4] = (const float*)d_in[7]; sa.hi[4] = Wv_h;  sa.lo[4] = Wv_l;  sa.n4[4] = Dc * Hc / 4;
    sa.src[5] = (const float*)d_in[9]; sa.hi[5] = Wo_h;  sa.lo[5] = Wo_l;  sa.n4[5] = Hc * Dc / 4;
    split_all<<<dim3((Mrows * Dc / 4 + 255) / 256, 6), 256>>>(sa);

    // (3,4,5) projections
    dim3 pg(Hc / 128, Mrows / 128);   // (8, 32)
    gemm_split<<<pg, 256, GEMM_SMEM>>>(Xq_h, Xq_l, Wq_h, Wq_l, (const float*)d_in[4],
                                       Q_h, Q_l, nullptr, Mrows, Hc, Dc);
    gemm_split<<<pg, 256, GEMM_SMEM>>>(Xkv_h, Xkv_l, Wk_h, Wk_l, (const float*)d_in[6],
                                       K_h, K_l, nullptr, Mrows, Hc, Dc);
    gemm_split<<<pg, 256, GEMM_SMEM>>>(Xkv_h, Xkv_l, Wv_h, Wv_l, (const float*)d_in[8],
                                       V_h, V_l, nullptr, Mrows, Hc, Dc);

    // (6) attention
    attn_mma<<<dim3(SQc / 128, NHc, Bc), 256, ATTN_SMEM>>>(Q_h, Q_l, K_h, K_l,
                                                           V_h, V_l, A_h, A_l);

    // (7) output projection
    dim3 og(Dc / 128, Mrows / 128);   // (8, 32)
    gemm_split<<<og, 256, GEMM_SMEM>>>(A_h, A_l, Wo_h, Wo_l, (const float*)d_in[10],
                                       nullptr, nullptr, (float*)d_out, Mrows, Dc, Hc);
}

// round 7
// speedup vs baseline: 2.9707x; 1.0083x over previous
#include <cuda_runtime.h>
#include <cuda_bf16.h>
#include <math_constants.h>
#include <cstdint>

#define Bc    2
#define SQc   2048
#define SKVc  2048
#define Dc    1024
#define Hc    1024
#define NHc   16
#define HDc   64
#define Mrows 4096

typedef __nv_bfloat16 bf16;

// ---------------- scratch (device globals, allocation-free) ----------------
__device__ bf16 g_Xq_h[(size_t)Mrows * Dc],  g_Xq_l[(size_t)Mrows * Dc];
__device__ bf16 g_Xkv_h[(size_t)Mrows * Dc], g_Xkv_l[(size_t)Mrows * Dc];
__device__ bf16 g_Wq_h[(size_t)Dc * Hc], g_Wq_l[(size_t)Dc * Hc];
__device__ bf16 g_Wk_h[(size_t)Dc * Hc], g_Wk_l[(size_t)Dc * Hc];
__device__ bf16 g_Wv_h[(size_t)Dc * Hc], g_Wv_l[(size_t)Dc * Hc];
__device__ bf16 g_Wo_h[(size_t)Hc * Dc], g_Wo_l[(size_t)Hc * Dc];
__device__ bf16 g_Q_h[(size_t)Mrows * Hc], g_Q_l[(size_t)Mrows * Hc];
__device__ bf16 g_K_h[(size_t)Mrows * Hc], g_K_l[(size_t)Mrows * Hc];
__device__ bf16 g_V_h[(size_t)Mrows * Hc], g_V_l[(size_t)Mrows * Hc];
__device__ bf16 g_A_h[(size_t)Mrows * Hc], g_A_l[(size_t)Mrows * Hc];
__device__ float g_maskbias[Bc * SKVc];

// ---------------- small helpers ----------------
__device__ __forceinline__ uint32_t smem_u32(const void* p) {
    return (uint32_t)__cvta_generic_to_shared(p);
}
__device__ __forceinline__ void cpa16(void* dst, const void* src) {
    asm volatile("cp.async.cg.shared.global [%0], [%1], 16;\n"
                 :: "r"(smem_u32(dst)), "l"(src));
}
__device__ __forceinline__ void cp_commit() { asm volatile("cp.async.commit_group;\n"); }
template <int N> __device__ __forceinline__ void cp_wait() {
    asm volatile("cp.async.wait_group %0;\n" :: "n"(N) : "memory");
}
__device__ __forceinline__ void ldm4(uint32_t r[4], const void* p) {
    asm volatile("ldmatrix.sync.aligned.m8n8.x4.shared.b16 {%0,%1,%2,%3}, [%4];\n"
                 : "=r"(r[0]), "=r"(r[1]), "=r"(r[2]), "=r"(r[3]) : "r"(smem_u32(p)));
}
__device__ __forceinline__ void ldm4t(uint32_t r[4], const void* p) {
    asm volatile("ldmatrix.sync.aligned.m8n8.x4.trans.shared.b16 {%0,%1,%2,%3}, [%4];\n"
                 : "=r"(r[0]), "=r"(r[1]), "=r"(r[2]), "=r"(r[3]) : "r"(smem_u32(p)));
}
__device__ __forceinline__ void mma16816(float c[4], const uint32_t a[4], const uint32_t b[2]) {
    asm volatile("mma.sync.aligned.m16n8k16.row.col.f32.bf16.bf16.f32 "
                 "{%0,%1,%2,%3}, {%4,%5,%6,%7}, {%8,%9}, {%0,%1,%2,%3};\n"
                 : "+f"(c[0]), "+f"(c[1]), "+f"(c[2]), "+f"(c[3])
                 : "r"(a[0]), "r"(a[1]), "r"(a[2]), "r"(a[3]), "r"(b[0]), "r"(b[1]));
}
__device__ __forceinline__ uint32_t b2u(__nv_bfloat162 v) {
    return *reinterpret_cast<uint32_t*>(&v);
}
__device__ __forceinline__ uint32_t packbf(float a, float b) {
    __nv_bfloat162 t = __floats2bfloat162_rn(a, b);
    return b2u(t);
}

// ---------------- fused mask detect + bias build (single block) ----------------
__global__ void mask_kernel(const unsigned char* __restrict__ m) {
    __shared__ int nz[4];
    int tid = threadIdx.x;
    if (tid < 4) nz[tid] = 0;
    __syncthreads();
    for (int p = tid; p < Bc * SKVc; p += blockDim.x)
        if (m[p]) atomicOr(&nz[p & 3], 1);
    __syncthreads();
    int kind = 0;
    if (!nz[1] && !nz[2] && !nz[3]) kind = 1;       // int32 0/1
    else if (!nz[0] && !nz[1])      kind = 2;       // float32 0/1
    for (int i = tid; i < Bc * SKVc; i += blockDim.x) {
        bool mk;
        if (kind == 1)      mk = ((const int*)m)[i] != 0;
        else if (kind == 2) mk = ((const float*)m)[i] != 0.0f;
        else                mk = m[i] != 0;
        g_maskbias[i] = mk ? -1e30f : 0.0f;
    }
}

// ---------------- fused split: all 6 tensors in one launch (z-sliced) ----------
struct SplitArgs {
    const float* src[6];
    bf16* hi[6];
    bf16* lo[6];
    int   n4[6];     // element count / 4
};
__global__ __launch_bounds__(256) void split_all(SplitArgs a) {
    int z = blockIdx.y;
    int i4 = blockIdx.x * 256 + threadIdx.x;
    if (i4 >= a.n4[z]) return;
    float4 v = ((const float4*)a.src[z])[i4];
    __nv_bfloat162 h0 = __floats2bfloat162_rn(v.x, v.y);
    __nv_bfloat162 h1 = __floats2bfloat162_rn(v.z, v.w);
    uint32_t l0 = packbf(v.x - __low2float(h0), v.y - __high2float(h0));
    uint32_t l1 = packbf(v.z - __low2float(h1), v.w - __high2float(h1));
    ((uint2*)a.hi[z])[i4] = make_uint2(b2u(h0), b2u(h1));
    ((uint2*)a.lo[z])[i4] = make_uint2(l0, l1);
}

// ---------------- split-bf16 GEMM: C = A@W + bias ----------------
// BM=128, BN=128, BK=32, 3 stages, 256 threads, 2 CTAs/SM,
// SINGLE __syncthreads per mainloop iteration (CUTLASS multistage order).
#define G_AST 40
#define G_BST 136
#define G_STG 3
#define GEMM_SMEM (G_STG * (128 * G_AST + 32 * G_BST) * 2 * (int)sizeof(bf16))

__global__ __launch_bounds__(256, 2) void gemm_split(
    const bf16* __restrict__ Ah, const bf16* __restrict__ Al,
    const bf16* __restrict__ Wh, const bf16* __restrict__ Wl,
    const float* __restrict__ bias,
    bf16* __restrict__ Ch, bf16* __restrict__ Cl, float* __restrict__ Cf,
    int M, int N, int K)
{
    extern __shared__ char sm[];
    bf16* Ash = (bf16*)sm;                            // [3][128][G_AST]
    bf16* Asl = Ash + G_STG * 128 * G_AST;
    bf16* Bsh = Asl + G_STG * 128 * G_AST;            // [3][32][G_BST]
    bf16* Bsl = Bsh + G_STG * 32 * G_BST;

    int tid = threadIdx.x, lane = tid & 31, wid = tid >> 5;
    int wm = wid & 1, wn = wid >> 1;
    int m0 = blockIdx.y * 128, n0 = blockIdx.x * 128;

    float acc[4][4][4];
#pragma unroll
    for (int i = 0; i < 4; i++)
#pragma unroll
        for (int j = 0; j < 4; j++)
#pragma unroll
            for (int e = 0; e < 4; e++) acc[i][j][e] = 0.0f;

    auto load_tiles = [&](int it, int s) {
        int k0 = it * 32;
#pragma unroll
        for (int x = tid; x < 1024; x += 256) {       // A hi/lo: 128 rows x 32 cols
            int mat = x >> 9, i = x & 511;
            int r = i >> 2, kc = (i & 3) * 8;
            const bf16* src = (mat ? Al : Ah) + (size_t)(m0 + r) * K + k0 + kc;
            bf16* dst = (mat ? Asl : Ash) + (s * 128 + r) * G_AST + kc;
            cpa16(dst, src);
        }
#pragma unroll
        for (int x = tid; x < 1024; x += 256) {       // B hi/lo: 32 rows x 128 cols
            int mat = x >> 9, i = x & 511;
            int r = i >> 4, nc = (i & 15) * 8;
            const bf16* src = (mat ? Wl : Wh) + (size_t)(k0 + r) * N + n0 + nc;
            bf16* dst = (mat ? Bsl : Bsh) + (s * 32 + r) * G_BST + nc;
            cpa16(dst, src);
        }
    };

    int NIT = K / 32;                                  // 32
    load_tiles(0, 0); cp_commit();
    load_tiles(1, 1); cp_commit();

    int s = 0, s2 = 2;                                 // s = it%3, s2 = (it+2)%3
    for (int it = 0; it < NIT; ++it) {
        // wait for stage s to land (FIFO: <=1 outstanding => g(it) done)
        if (it + 1 < NIT) cp_wait<1>(); else cp_wait<0>();
        __syncthreads();   // also guarantees stage s2's old readers are done
        if (it + 2 < NIT) { load_tiles(it + 2, s2); cp_commit(); }

#pragma unroll
        for (int kk = 0; kk < 2; ++kk) {
            uint32_t ah[4][4], al[4][4], bh[2][4], bl[2][4];
#pragma unroll
            for (int mt = 0; mt < 4; ++mt) {
                int idx = (s * 128 + wm * 64 + mt * 16 + (lane & 15)) * G_AST
                        + kk * 16 + (lane >> 4) * 8;
                ldm4(ah[mt], &Ash[idx]);
                ldm4(al[mt], &Asl[idx]);
            }
#pragma unroll
            for (int g = 0; g < 2; ++g) {
                int idx = (s * 32 + kk * 16 + (lane & 15)) * G_BST
                        + wn * 32 + g * 16 + (lane >> 4) * 8;
                ldm4t(bh[g], &Bsh[idx]);
                ldm4t(bl[g], &Bsl[idx]);
            }
#pragma unroll
            for (int mt = 0; mt < 4; ++mt)
#pragma unroll
                for (int g = 0; g < 2; ++g) {
                    uint32_t bh0[2] = { bh[g][0], bh[g][1] }, bh1[2] = { bh[g][2], bh[g][3] };
                    uint32_t bl0[2] = { bl[g][0], bl[g][1] }, bl1[2] = { bl[g][2], bl[g][3] };
                    mma16816(acc[mt][2 * g],     ah[mt], bh0);
                    mma16816(acc[mt][2 * g],     ah[mt], bl0);
                    mma16816(acc[mt][2 * g],     al[mt], bh0);
                    mma16816(acc[mt][2 * g + 1], ah[mt], bh1);
                    mma16816(acc[mt][2 * g + 1], ah[mt], bl1);
                    mma16816(acc[mt][2 * g + 1], al[mt], bh1);
                }
        }
        s  = (s  == 2) ? 0 : s + 1;
        s2 = (s2 == 2) ? 0 : s2 + 1;
    }

    // epilogue
#pragma unroll
    for (int mt = 0; mt < 4; ++mt)
#pragma unroll
        for (int nt = 0; nt < 4; ++nt) {
            int row = m0 + wm * 64 + mt * 16 + (lane >> 2);
            int col = n0 + wn * 32 + nt * 8 + (lane & 3) * 2;
            float b0 = bias[col], b1 = bias[col + 1];
            float v00 = acc[mt][nt][0] + b0, v01 = acc[mt][nt][1] + b1;
            float v10 = acc[mt][nt][2] + b0, v11 = acc[mt][nt][3] + b1;
            size_t i0 = (size_t)row * N + col;
            size_t i1 = (size_t)(row + 8) * N + col;
            if (Cf) {
                *(float2*)(Cf + i0) = make_float2(v00, v01);
                *(float2*)(Cf + i1) = make_float2(v10, v11);
            } else {
                __nv_bfloat162 h0 = __floats2bfloat162_rn(v00, v01);
                __nv_bfloat162 h1 = __floats2bfloat162_rn(v10, v11);
                *(uint32_t*)(Ch + i0) = b2u(h0);
                *(uint32_t*)(Ch + i1) = b2u(h1);
                *(uint32_t*)(Cl + i0) = packbf(v00 - __low2float(h0), v01 - __high2float(h0));
                *(uint32_t*)(Cl + i1) = packbf(v10 - __low2float(h1), v11 - __high2float(h1));
            }
        }
}

// ---------------- split-bf16 flash attention ----------------
// BQ=128 (8 warps x 16 rows), TKV=64, online softmax.
// SINGLE __syncthreads per KV iteration.
#define A_QST 72
#define A_KST 72
#define ATTN_SMEM ((2*128*A_QST + 4*2*64*A_KST) * (int)sizeof(bf16) + 2*64*(int)sizeof(float))

__global__ __launch_bounds__(256) void attn_mma(
    const bf16* __restrict__ Qh, const bf16* __restrict__ Ql,
    const bf16* __restrict__ Kh, const bf16* __restrict__ Kl,
    const bf16* __restrict__ Vh, const bf16* __restrict__ Vl,
    bf16* __restrict__ Ah, bf16* __restrict__ Al)
{
    extern __shared__ char sm[];
    bf16* Qs_h = (bf16*)sm;
    bf16* Qs_l = Qs_h + 128 * A_QST;
    bf16* Ks_h = Qs_l + 128 * A_QST;
    bf16* Ks_l = Ks_h + 2 * 64 * A_KST;
    bf16* Vs_h = Ks_l + 2 * 64 * A_KST;
    bf16* Vs_l = Vs_h + 2 * 64 * A_KST;
    float* mbs = (float*)(Vs_l + 2 * 64 * A_KST);

    int tid = threadIdx.x, lane = tid & 31, wid = tid >> 5;
    int q0 = blockIdx.x * 128, h = blockIdx.y, b = blockIdx.z;

#pragma unroll
    for (int c = tid; c < 1024; c += 256) {
        int r = c >> 3, col = (c & 7) * 8;
        size_t src = (size_t)(b * SQc + q0 + r) * Hc + h * HDc + col;
        cpa16(&Qs_h[r * A_QST + col], Qh + src);
        cpa16(&Qs_l[r * A_QST + col], Ql + src);
    }
    cp_commit();

    auto load_kv = [&](int it, int buf) {
        int t0 = it * 64;
#pragma unroll
        for (int c = tid; c < 512; c += 256) {
            int r = c >> 3, col = (c & 7) * 8;
            size_t src = (size_t)(b * SKVc + t0 + r) * Hc + h * HDc + col;
            cpa16(&Ks_h[(buf * 64 + r) * A_KST + col], Kh + src);
            cpa16(&Ks_l[(buf * 64 + r) * A_KST + col], Kl + src);
            cpa16(&Vs_h[(buf * 64 + r) * A_KST + col], Vh + src);
            cpa16(&Vs_l[(buf * 64 + r) * A_KST + col], Vl + src);
        }
        if (tid < 16)
            cpa16(&mbs[buf * 64 + tid * 4], g_maskbias + b * SKVc + t0 + tid * 4);
    };

    load_kv(0, 0);
    cp_commit();
    cp_wait<0>();      // Q and kv0 both resident
    __syncthreads();

    uint32_t qh[4][4], ql[4][4];
    {
        int r = wid * 16 + (lane & 15);
#pragma unroll
        for (int kk = 0; kk < 4; ++kk) {
            int idx = r * A_QST + kk * 16 + (lane >> 4) * 8;
            ldm4(qh[kk], &Qs_h[idx]);
            ldm4(ql[kk], &Qs_l[idx]);
        }
    }

    float o[8][4];
#pragma unroll
    for (int i = 0; i < 8; i++)
#pragma unroll
        for (int j = 0; j < 4; j++) o[i][j] = 0.0f;
    float m0r = -CUDART_INF_F, m1r = -CUDART_INF_F;
    float l0r = 0.0f, l1r = 0.0f;

    const int NT = SKVc / 64;
    for (int it = 0; it < NT; ++it) {
        int buf = it & 1;
        // issue next tile's loads first: its buffer (buf^1) was fully read in
        // it-1, and the single barrier at the bottom of it-1 ordered that.
        if (it + 1 < NT) { load_kv(it + 1, buf ^ 1); cp_commit(); }

        float s[8][4];
#pragma unroll
        for (int i = 0; i < 8; i++)
#pragma unroll
            for (int j = 0; j < 4; j++) s[i][j] = 0.0f;

#pragma unroll
        for (int kk = 0; kk < 4; ++kk) {
#pragma unroll
            for (int g = 0; g < 4; ++g) {
                uint32_t kh[4], kl[4];
                int idx = (buf * 64 + g * 16 + (lane & 15)) * A_KST
                        + kk * 16 + (lane >> 4) * 8;
                ldm4(kh, &Ks_h[idx]);
                ldm4(kl, &Ks_l[idx]);
                uint32_t b0h[2] = { kh[0], kh[2] }, b1h[2] = { kh[1], kh[3] };
                uint32_t b0l[2] = { kl[0], kl[2] }, b1l[2] = { kl[1], kl[3] };
                mma16816(s[2 * g],     qh[kk], b0h);
                mma16816(s[2 * g],     qh[kk], b0l);
                mma16816(s[2 * g],     ql[kk], b0h);
                mma16816(s[2 * g + 1], qh[kk], b1h);
                mma16816(s[2 * g + 1], qh[kk], b1l);
                mma16816(s[2 * g + 1], ql[kk], b1h);
            }
        }

        float tm0 = -CUDART_INF_F, tm1 = -CUDART_INF_F;
#pragma unroll
        for (int nt = 0; nt < 8; ++nt) {
            int cb = nt * 8 + (lane & 3) * 2;
            float mb0 = mbs[buf * 64 + cb], mb1 = mbs[buf * 64 + cb + 1];
            s[nt][0] = s[nt][0] * 0.125f + mb0;
            s[nt][1] = s[nt][1] * 0.125f + mb1;
            s[nt][2] = s[nt][2] * 0.125f + mb0;
            s[nt][3] = s[nt][3] * 0.125f + mb1;
            tm0 = fmaxf(tm0, fmaxf(s[nt][0], s[nt][1]));
            tm1 = fmaxf(tm1, fmaxf(s[nt][2], s[nt][3]));
        }
        tm0 = fmaxf(tm0, __shfl_xor_sync(0xffffffffu, tm0, 1));
        tm0 = fmaxf(tm0, __shfl_xor_sync(0xffffffffu, tm0, 2));
        tm1 = fmaxf(tm1, __shfl_xor_sync(0xffffffffu, tm1, 1));
        tm1 = fmaxf(tm1, __shfl_xor_sync(0xffffffffu, tm1, 2));
        float mn0 = fmaxf(m0r, tm0), mn1 = fmaxf(m1r, tm1);
        float al0 = __expf(m0r - mn0), al1 = __expf(m1r - mn1);
        m0r = mn0; m1r = mn1;

        float rs0 = 0.0f, rs1 = 0.0f;
#pragma unroll
        for (int nt = 0; nt < 8; ++nt) {
            s[nt][0] = __expf(s[nt][0] - mn0);
            s[nt][1] = __expf(s[nt][1] - mn0);
            s[nt][2] = __expf(s[nt][2] - mn1);
            s[nt][3] = __expf(s[nt][3] - mn1);
            rs0 += s[nt][0] + s[nt][1];
            rs1 += s[nt][2] + s[nt][3];
        }
        rs0 += __shfl_xor_sync(0xffffffffu, rs0, 1);
        rs0 += __shfl_xor_sync(0xffffffffu, rs0, 2);
        rs1 += __shfl_xor_sync(0xffffffffu, rs1, 1);
        rs1 += __shfl_xor_sync(0xffffffffu, rs1, 2);
        l0r = l0r * al0 + rs0;
        l1r = l1r * al1 + rs1;

#pragma unroll
        for (int dn = 0; dn < 8; ++dn) {
            o[dn][0] *= al0; o[dn][1] *= al0;
            o[dn][2] *= al1; o[dn][3] *= al1;
        }

#pragma unroll
        for (int kt = 0; kt < 4; ++kt) {
            float x0 = s[2 * kt][0], x1 = s[2 * kt][1], x2 = s[2 * kt][2], x3 = s[2 * kt][3];
            float y0 = s[2 * kt + 1][0], y1 = s[2 * kt + 1][1];
            float y2 = s[2 * kt + 1][2], y3 = s[2 * kt + 1][3];
            __nv_bfloat162 hx0 = __floats2bfloat162_rn(x0, x1);
            __nv_bfloat162 hx1 = __floats2bfloat162_rn(x2, x3);
            __nv_bfloat162 hy0 = __floats2bfloat162_rn(y0, y1);
            __nv_bfloat162 hy1 = __floats2bfloat162_rn(y2, y3);
            uint32_t pah[4] = { b2u(hx0), b2u(hx1), b2u(hy0), b2u(hy1) };
            uint32_t pal[4] = {
                packbf(x0 - __low2float(hx0), x1 - __high2float(hx0)),
                packbf(x2 - __low2float(hx1), x3 - __high2float(hx1)),
                packbf(y0 - __low2float(hy0), y1 - __high2float(hy0)),
                packbf(y2 - __low2float(hy1), y3 - __high2float(hy1))
            };
#pragma unroll
            for (int dg = 0; dg < 4; ++dg) {
                uint32_t vh[4], vl[4];
                int idx = (buf * 64 + kt * 16 + (lane & 15)) * A_KST
                        + dg * 16 + (lane >> 4) * 8;
                ldm4t(vh, &Vs_h[idx]);
                ldm4t(vl, &Vs_l[idx]);
                uint32_t b0h[2] = { vh[0], vh[1] }, b1h[2] = { vh[2], vh[3] };
                uint32_t b0l[2] = { vl[0], vl[1] }, b1l[2] = { vl[2], vl[3] };
                mma16816(o[2 * dg],     pah, b0h);
                mma16816(o[2 * dg],     pah, b0l);
                mma16816(o[2 * dg],     pal, b0h);
                mma16816(o[2 * dg + 1], pah, b1h);
                mma16816(o[2 * dg + 1], pah, b1l);
                mma16816(o[2 * dg + 1], pal, b1h);
            }
        }

        if (it + 1 < NT) {
            cp_wait<0>();      // next tile resident (loads flew under compute)
            __syncthreads();   // single barrier: orders buf reads vs next writes
        }
    }

    float inv0 = 1.0f / l0r, inv1 = 1.0f / l1r;
#pragma unroll
    for (int dn = 0; dn < 8; ++dn) {
        int row = q0 + wid * 16 + (lane >> 2);
        int col = h * HDc + dn * 8 + (lane & 3) * 2;
        float v00 = o[dn][0] * inv0, v01 = o[dn][1] * inv0;
        float v10 = o[dn][2] * inv1, v11 = o[dn][3] * inv1;
        size_t i0 = (size_t)(b * SQc + row) * Hc + col;
        size_t i1 = (size_t)(b * SQc + row + 8) * Hc + col;
        __nv_bfloat162 h0 = __floats2bfloat162_rn(v00, v01);
        __nv_bfloat162 h1 = __floats2bfloat162_rn(v10, v11);
        *(uint32_t*)(Ah + i0) = b2u(h0);
        *(uint32_t*)(Ah + i1) = b2u(h1);
        *(uint32_t*)(Al + i0) = packbf(v00 - __low2float(h0), v01 - __high2float(h0));
        *(uint32_t*)(Al + i1) = packbf(v10 - __low2float(h1), v11 - __high2float(h1));
    }
}

// ---------------- launch ----------------
extern "C" void kernel_launch(void* const* d_in, const int* in_sizes, int n_in,
                              void* d_out, int out_size)
{
    (void)in_sizes; (void)n_in; (void)out_size;

    bf16 *Xq_h, *Xq_l, *Xkv_h, *Xkv_l;
    bf16 *Wq_h, *Wq_l, *Wk_h, *Wk_l, *Wv_h, *Wv_l, *Wo_h, *Wo_l;
    bf16 *Q_h, *Q_l, *K_h, *K_l, *V_h, *V_l, *A_h, *A_l;
    cudaGetSymbolAddress((void**)&Xq_h, g_Xq_h);   cudaGetSymbolAddress((void**)&Xq_l, g_Xq_l);
    cudaGetSymbolAddress((void**)&Xkv_h, g_Xkv_h); cudaGetSymbolAddress((void**)&Xkv_l, g_Xkv_l);
    cudaGetSymbolAddress((void**)&Wq_h, g_Wq_h);   cudaGetSymbolAddress((void**)&Wq_l, g_Wq_l);
    cudaGetSymbolAddress((void**)&Wk_h, g_Wk_h);   cudaGetSymbolAddress((void**)&Wk_l, g_Wk_l);
    cudaGetSymbolAddress((void**)&Wv_h, g_Wv_h);   cudaGetSymbolAddress((void**)&Wv_l, g_Wv_l);
    cudaGetSymbolAddress((void**)&Wo_h, g_Wo_h);   cudaGetSymbolAddress((void**)&Wo_l, g_Wo_l);
    cudaGetSymbolAddress((void**)&Q_h, g_Q_h);     cudaGetSymbolAddress((void**)&Q_l, g_Q_l);
    cudaGetSymbolAddress((void**)&K_h, g_K_h);     cudaGetSymbolAddress((void**)&K_l, g_K_l);
    cudaGetSymbolAddress((void**)&V_h, g_V_h);     cudaGetSymbolAddress((void**)&V_l, g_V_l);
    cudaGetSymbolAddress((void**)&A_h, g_A_h);     cudaGetSymbolAddress((void**)&A_l, g_A_l);

    cudaFuncSetAttribute(gemm_split, cudaFuncAttributeMaxDynamicSharedMemorySize, GEMM_SMEM);
    cudaFuncSetAttribute(attn_mma,   cudaFuncAttributeMaxDynamicSharedMemorySize, ATTN_SMEM);

    // (1) mask
    mask_kernel<<<1, 256>>>((const unsigned char*)d_in[2]);

    // (2) all splits in one launch
    SplitArgs sa;
    sa.src[0] = (const float*)d_in[0]; sa.hi[0] = Xq_h;  sa.lo[0] = Xq_l;  sa.n4[0] = Mrows * Dc / 4;
    sa.src[1] = (const float*)d_in[1]; sa.hi[1] = Xkv_h; sa.lo[1] = Xkv_l; sa.n4[1] = Mrows * Dc / 4;
    sa.src[2] = (const float*)d_in[3]; sa.hi[2] = Wq_h;  sa.lo[2] = Wq_l;  sa.n4[2] = Dc * Hc / 4;
    sa.src[3] = (const float*)d_in[5]; sa.hi[3] = Wk_h;  sa.lo[3] = Wk_l;  sa.n4[3] = Dc * Hc / 4;
    sa.src[4] = (const float*)d_in[7]; sa.hi[4] = Wv_h;  sa.lo[4] = Wv_l;  sa.n4[4] = Dc * Hc / 4;
    sa.src[5] = (const float*)d_in[9]; sa.hi[5] = Wo_h;  sa.lo[5] = Wo_l;  sa.n4[5] = Hc * Dc / 4;
    split_all<<<dim3((Mrows * Dc / 4 + 255) / 256, 6), 256>>>(sa);

    // (3,4,5) projections
    dim3 pg(Hc / 128, Mrows / 128);   // (8, 32)
    gemm_split<<<pg, 256, GEMM_SMEM>>>(Xq_h, Xq_l, Wq_h, Wq_l, (const float*)d_in[4],
                                       Q_h, Q_l, nullptr, Mrows, Hc, Dc);
    gemm_split<<<pg, 256, GEMM_SMEM>>>(Xkv_h, Xkv_l, Wk_h, Wk_l, (const float*)d_in[6],
                                       K_h, K_l, nullptr, Mrows, Hc, Dc);
    gemm_split<<<pg, 256, GEMM_SMEM>>>(Xkv_h, Xkv_l, Wv_h, Wv_l, (const float*)d_in[8],
                                       V_h, V_l, nullptr, Mrows, Hc, Dc);

    // (6) attention
    attn_mma<<<dim3(SQc / 128, NHc, Bc), 256, ATTN_SMEM>>>(Q_h, Q_l, K_h, K_l,
                                                           V_h, V_l, A_h, A_l);

    // (7) output projection
    dim3 og(Dc / 128, Mrows / 128);   // (8, 32)
    gemm_split<<<og, 256, GEMM_SMEM>>>(A_h, A_l, Wo_h, Wo_l, (const float*)d_in[10],
                                       nullptr, nullptr, (float*)d_out, Mrows, Dc, Hc);
}

// round 8
// speedup vs baseline: 3.5995x; 1.2117x over previous
#include <cuda_runtime.h>
#include <cuda_bf16.h>
#include <cuda_fp16.h>
#include <math_constants.h>
#include <cstdint>

#define Bc    2
#define SQc   2048
#define SKVc  2048
#define Dc    1024
#define Hc    1024
#define NHc   16
#define HDc   64
#define Mrows 4096

typedef __nv_bfloat16 bf16;
typedef __half fp16;

// ---------------- scratch (device globals, allocation-free) ----------------
__device__ bf16 g_Xq_h[(size_t)Mrows * Dc],  g_Xq_l[(size_t)Mrows * Dc];
__device__ bf16 g_Xkv_h[(size_t)Mrows * Dc], g_Xkv_l[(size_t)Mrows * Dc];
__device__ bf16 g_Wq_h[(size_t)Dc * Hc], g_Wq_l[(size_t)Dc * Hc];
__device__ bf16 g_Wk_h[(size_t)Dc * Hc], g_Wk_l[(size_t)Dc * Hc];
__device__ bf16 g_Wv_h[(size_t)Dc * Hc], g_Wv_l[(size_t)Dc * Hc];
__device__ bf16 g_Wo_h[(size_t)Hc * Dc], g_Wo_l[(size_t)Hc * Dc];
__device__ fp16 g_Q16[(size_t)Mrows * Hc];                          // Q hi only
__device__ fp16 g_K16h[(size_t)Mrows * Hc], g_K16l[(size_t)Mrows * Hc];
__device__ fp16 g_V16h[(size_t)Mrows * Hc], g_V16l[(size_t)Mrows * Hc];
__device__ bf16 g_A_h[(size_t)Mrows * Hc], g_A_l[(size_t)Mrows * Hc];
__device__ float g_maskbias[Bc * SKVc];

// ---------------- small helpers ----------------
__device__ __forceinline__ uint32_t smem_u32(const void* p) {
    return (uint32_t)__cvta_generic_to_shared(p);
}
__device__ __forceinline__ void cpa16(void* dst, const void* src) {
    asm volatile("cp.async.cg.shared.global [%0], [%1], 16;\n"
                 :: "r"(smem_u32(dst)), "l"(src));
}
__device__ __forceinline__ void cp_commit() { asm volatile("cp.async.commit_group;\n"); }
template <int N> __device__ __forceinline__ void cp_wait() {
    asm volatile("cp.async.wait_group %0;\n" :: "n"(N) : "memory");
}
__device__ __forceinline__ void ldm4(uint32_t r[4], const void* p) {
    asm volatile("ldmatrix.sync.aligned.m8n8.x4.shared.b16 {%0,%1,%2,%3}, [%4];\n"
                 : "=r"(r[0]), "=r"(r[1]), "=r"(r[2]), "=r"(r[3]) : "r"(smem_u32(p)));
}
__device__ __forceinline__ void ldm4t(uint32_t r[4], const void* p) {
    asm volatile("ldmatrix.sync.aligned.m8n8.x4.trans.shared.b16 {%0,%1,%2,%3}, [%4];\n"
                 : "=r"(r[0]), "=r"(r[1]), "=r"(r[2]), "=r"(r[3]) : "r"(smem_u32(p)));
}
__device__ __forceinline__ void mma16816(float c[4], const uint32_t a[4], const uint32_t b[2]) {
    asm volatile("mma.sync.aligned.m16n8k16.row.col.f32.bf16.bf16.f32 "
                 "{%0,%1,%2,%3}, {%4,%5,%6,%7}, {%8,%9}, {%0,%1,%2,%3};\n"
                 : "+f"(c[0]), "+f"(c[1]), "+f"(c[2]), "+f"(c[3])
                 : "r"(a[0]), "r"(a[1]), "r"(a[2]), "r"(a[3]), "r"(b[0]), "r"(b[1]));
}
__device__ __forceinline__ void mma16816h(float c[4], const uint32_t a[4], const uint32_t b[2]) {
    asm volatile("mma.sync.aligned.m16n8k16.row.col.f32.f16.f16.f32 "
                 "{%0,%1,%2,%3}, {%4,%5,%6,%7}, {%8,%9}, {%0,%1,%2,%3};\n"
                 : "+f"(c[0]), "+f"(c[1]), "+f"(c[2]), "+f"(c[3])
                 : "r"(a[0]), "r"(a[1]), "r"(a[2]), "r"(a[3]), "r"(b[0]), "r"(b[1]));
}
__device__ __forceinline__ uint32_t b2u(__nv_bfloat162 v) {
    return *reinterpret_cast<uint32_t*>(&v);
}
__device__ __forceinline__ uint32_t h2u(__half2 v) {
    return *reinterpret_cast<uint32_t*>(&v);
}
__device__ __forceinline__ uint32_t packbf(float a, float b) {
    __nv_bfloat162 t = __floats2bfloat162_rn(a, b);
    return b2u(t);
}
__device__ __forceinline__ uint32_t packhf(float a, float b) {
    __half2 t = __floats2half2_rn(a, b);
    return h2u(t);
}

// ---------------- fused mask detect + bias build (single block) ----------------
__global__ void mask_kernel(const unsigned char* __restrict__ m) {
    __shared__ int nz[4];
    int tid = threadIdx.x;
    if (tid < 4) nz[tid] = 0;
    __syncthreads();
    for (int p = tid; p < Bc * SKVc; p += blockDim.x)
        if (m[p]) atomicOr(&nz[p & 3], 1);
    __syncthreads();
    int kind = 0;
    if (!nz[1] && !nz[2] && !nz[3]) kind = 1;       // int32 0/1
    else if (!nz[0] && !nz[1])      kind = 2;       // float32 0/1
    for (int i = tid; i < Bc * SKVc; i += blockDim.x) {
        bool mk;
        if (kind == 1)      mk = ((const int*)m)[i] != 0;
        else if (kind == 2) mk = ((const float*)m)[i] != 0.0f;
        else                mk = m[i] != 0;
        g_maskbias[i] = mk ? -1e30f : 0.0f;
    }
}

// ---------------- fused split: all 6 tensors in one launch (z-sliced) ----------
struct SplitArgs {
    const float* src[6];
    bf16* hi[6];
    bf16* lo[6];
    int   n4[6];     // element count / 4
};
__global__ __launch_bounds__(256) void split_all(SplitArgs a) {
    int z = blockIdx.y;
    int i4 = blockIdx.x * 256 + threadIdx.x;
    if (i4 >= a.n4[z]) return;
    float4 v = ((const float4*)a.src[z])[i4];
    __nv_bfloat162 h0 = __floats2bfloat162_rn(v.x, v.y);
    __nv_bfloat162 h1 = __floats2bfloat162_rn(v.z, v.w);
    uint32_t l0 = packbf(v.x - __low2float(h0), v.y - __high2float(h0));
    uint32_t l1 = packbf(v.z - __low2float(h1), v.w - __high2float(h1));
    ((uint2*)a.hi[z])[i4] = make_uint2(b2u(h0), b2u(h1));
    ((uint2*)a.lo[z])[i4] = make_uint2(l0, l1);
}

// ---------------- split-bf16 GEMM: C = A@W + bias ----------------
// BM=128, BN=128, BK=32, 3 stages, 256 threads, 2 CTAs/SM.
// Output modes: fp32 (Cf), bf16 hi/lo (Ch/Cl), fp16 hi[/lo] (Hh/Hl).
#define G_AST 40
#define G_BST 136
#define G_STG 3
#define GEMM_SMEM (G_STG * (128 * G_AST + 32 * G_BST) * 2 * (int)sizeof(bf16))

__global__ __launch_bounds__(256, 2) void gemm_split(
    const bf16* __restrict__ Ah, const bf16* __restrict__ Al,
    const bf16* __restrict__ Wh, const bf16* __restrict__ Wl,
    const float* __restrict__ bias,
    bf16* __restrict__ Ch, bf16* __restrict__ Cl, float* __restrict__ Cf,
    fp16* __restrict__ Hh, fp16* __restrict__ Hl,
    int M, int N, int K)
{
    extern __shared__ char sm[];
    bf16* Ash = (bf16*)sm;                            // [3][128][G_AST]
    bf16* Asl = Ash + G_STG * 128 * G_AST;
    bf16* Bsh = Asl + G_STG * 128 * G_AST;            // [3][32][G_BST]
    bf16* Bsl = Bsh + G_STG * 32 * G_BST;

    int tid = threadIdx.x, lane = tid & 31, wid = tid >> 5;
    int wm = wid & 1, wn = wid >> 1;
    int m0 = blockIdx.y * 128, n0 = blockIdx.x * 128;

    float acc[4][4][4];
#pragma unroll
    for (int i = 0; i < 4; i++)
#pragma unroll
        for (int j = 0; j < 4; j++)
#pragma unroll
            for (int e = 0; e < 4; e++) acc[i][j][e] = 0.0f;

    auto load_tiles = [&](int it, int s) {
        int k0 = it * 32;
#pragma unroll
        for (int x = tid; x < 1024; x += 256) {       // A hi/lo: 128 rows x 32 cols
            int mat = x >> 9, i = x & 511;
            int r = i >> 2, kc = (i & 3) * 8;
            const bf16* src = (mat ? Al : Ah) + (size_t)(m0 + r) * K + k0 + kc;
            bf16* dst = (mat ? Asl : Ash) + (s * 128 + r) * G_AST + kc;
            cpa16(dst, src);
        }
#pragma unroll
        for (int x = tid; x < 1024; x += 256) {       // B hi/lo: 32 rows x 128 cols
            int mat = x >> 9, i = x & 511;
            int r = i >> 4, nc = (i & 15) * 8;
            const bf16* src = (mat ? Wl : Wh) + (size_t)(k0 + r) * N + n0 + nc;
            bf16* dst = (mat ? Bsl : Bsh) + (s * 32 + r) * G_BST + nc;
            cpa16(dst, src);
        }
    };

    int NIT = K / 32;                                  // 32
    load_tiles(0, 0); cp_commit();
    load_tiles(1, 1); cp_commit();

    int s = 0, s2 = 2;
    for (int it = 0; it < NIT; ++it) {
        if (it + 1 < NIT) cp_wait<1>(); else cp_wait<0>();
        __syncthreads();
        if (it + 2 < NIT) { load_tiles(it + 2, s2); cp_commit(); }

#pragma unroll
        for (int kk = 0; kk < 2; ++kk) {
            uint32_t ah[4][4], al[4][4], bh[2][4], bl[2][4];
#pragma unroll
            for (int mt = 0; mt < 4; ++mt) {
                int idx = (s * 128 + wm * 64 + mt * 16 + (lane & 15)) * G_AST
                        + kk * 16 + (lane >> 4) * 8;
                ldm4(ah[mt], &Ash[idx]);
                ldm4(al[mt], &Asl[idx]);
            }
#pragma unroll
            for (int g = 0; g < 2; ++g) {
                int idx = (s * 32 + kk * 16 + (lane & 15)) * G_BST
                        + wn * 32 + g * 16 + (lane >> 4) * 8;
                ldm4t(bh[g], &Bsh[idx]);
                ldm4t(bl[g], &Bsl[idx]);
            }
#pragma unroll
            for (int mt = 0; mt < 4; ++mt)
#pragma unroll
                for (int g = 0; g < 2; ++g) {
                    uint32_t bh0[2] = { bh[g][0], bh[g][1] }, bh1[2] = { bh[g][2], bh[g][3] };
                    uint32_t bl0[2] = { bl[g][0], bl[g][1] }, bl1[2] = { bl[g][2], bl[g][3] };
                    mma16816(acc[mt][2 * g],     ah[mt], bh0);
                    mma16816(acc[mt][2 * g],     ah[mt], bl0);
                    mma16816(acc[mt][2 * g],     al[mt], bh0);
                    mma16816(acc[mt][2 * g + 1], ah[mt], bh1);
                    mma16816(acc[mt][2 * g + 1], ah[mt], bl1);
                    mma16816(acc[mt][2 * g + 1], al[mt], bh1);
                }
        }
        s  = (s  == 2) ? 0 : s + 1;
        s2 = (s2 == 2) ? 0 : s2 + 1;
    }

    // epilogue
#pragma unroll
    for (int mt = 0; mt < 4; ++mt)
#pragma unroll
        for (int nt = 0; nt < 4; ++nt) {
            int row = m0 + wm * 64 + mt * 16 + (lane >> 2);
            int col = n0 + wn * 32 + nt * 8 + (lane & 3) * 2;
            float b0 = bias[col], b1 = bias[col + 1];
            float v00 = acc[mt][nt][0] + b0, v01 = acc[mt][nt][1] + b1;
            float v10 = acc[mt][nt][2] + b0, v11 = acc[mt][nt][3] + b1;
            size_t i0 = (size_t)row * N + col;
            size_t i1 = (size_t)(row + 8) * N + col;
            if (Cf) {
                *(float2*)(Cf + i0) = make_float2(v00, v01);
                *(float2*)(Cf + i1) = make_float2(v10, v11);
            } else if (Hh) {
                __half2 h0 = __floats2half2_rn(v00, v01);
                __half2 h1 = __floats2half2_rn(v10, v11);
                *(uint32_t*)(Hh + i0) = h2u(h0);
                *(uint32_t*)(Hh + i1) = h2u(h1);
                if (Hl) {
                    *(uint32_t*)(Hl + i0) = packhf(v00 - __half2float(__low2half(h0)),
                                                   v01 - __half2float(__high2half(h0)));
                    *(uint32_t*)(Hl + i1) = packhf(v10 - __half2float(__low2half(h1)),
                                                   v11 - __half2float(__high2half(h1)));
                }
            } else {
                __nv_bfloat162 h0 = __floats2bfloat162_rn(v00, v01);
                __nv_bfloat162 h1 = __floats2bfloat162_rn(v10, v11);
                *(uint32_t*)(Ch + i0) = b2u(h0);
                *(uint32_t*)(Ch + i1) = b2u(h1);
                *(uint32_t*)(Cl + i0) = packbf(v00 - __low2float(h0), v01 - __high2float(h0));
                *(uint32_t*)(Cl + i1) = packbf(v10 - __low2float(h1), v11 - __high2float(h1));
            }
        }
}

// ---------------- fp16 2-term flash attention ----------------
// S = Qh · (Kh + Kl);  O = Ph · (Vh + Vl).  bf16 hi/lo output for Wo GEMM.
#define A_QST 72
#define A_KST 72
#define ATTN_SMEM ((128*A_QST + 4*2*64*A_KST) * (int)sizeof(fp16) + 2*64*(int)sizeof(float))

__global__ __launch_bounds__(256) void attn_mma(
    const fp16* __restrict__ Qh, const fp16* __restrict__ Kh,
    const fp16* __restrict__ Kl, const fp16* __restrict__ Vh,
    const fp16* __restrict__ Vl,
    bf16* __restrict__ Ah, bf16* __restrict__ Al)
{
    extern __shared__ char sm[];
    fp16* Qs   = (fp16*)sm;                       // [128][A_QST]
    fp16* Ks_h = Qs + 128 * A_QST;                // [2][64][A_KST]
    fp16* Ks_l = Ks_h + 2 * 64 * A_KST;
    fp16* Vs_h = Ks_l + 2 * 64 * A_KST;
    fp16* Vs_l = Vs_h + 2 * 64 * A_KST;
    float* mbs = (float*)(Vs_l + 2 * 64 * A_KST);

    int tid = threadIdx.x, lane = tid & 31, wid = tid >> 5;
    int q0 = blockIdx.x * 128, h = blockIdx.y, b = blockIdx.z;

#pragma unroll
    for (int c = tid; c < 1024; c += 256) {
        int r = c >> 3, col = (c & 7) * 8;
        size_t src = (size_t)(b * SQc + q0 + r) * Hc + h * HDc + col;
        cpa16(&Qs[r * A_QST + col], Qh + src);
    }
    cp_commit();

    auto load_kv = [&](int it, int buf) {
        int t0 = it * 64;
#pragma unroll
        for (int c = tid; c < 512; c += 256) {
            int r = c >> 3, col = (c & 7) * 8;
            size_t src = (size_t)(b * SKVc + t0 + r) * Hc + h * HDc + col;
            cpa16(&Ks_h[(buf * 64 + r) * A_KST + col], Kh + src);
            cpa16(&Ks_l[(buf * 64 + r) * A_KST + col], Kl + src);
            cpa16(&Vs_h[(buf * 64 + r) * A_KST + col], Vh + src);
            cpa16(&Vs_l[(buf * 64 + r) * A_KST + col], Vl + src);
        }
        if (tid < 16)
            cpa16(&mbs[buf * 64 + tid * 4], g_maskbias + b * SKVc + t0 + tid * 4);
    };

    load_kv(0, 0);
    cp_commit();
    cp_wait<0>();
    __syncthreads();

    uint32_t qf[4][4];
    {
        int r = wid * 16 + (lane & 15);
#pragma unroll
        for (int kk = 0; kk < 4; ++kk)
            ldm4(qf[kk], &Qs[r * A_QST + kk * 16 + (lane >> 4) * 8]);
    }

    float o[8][4];
#pragma unroll
    for (int i = 0; i < 8; i++)
#pragma unroll
        for (int j = 0; j < 4; j++) o[i][j] = 0.0f;
    float m0r = -CUDART_INF_F, m1r = -CUDART_INF_F;
    float l0r = 0.0f, l1r = 0.0f;

    const int NT = SKVc / 64;
    for (int it = 0; it < NT; ++it) {
        int buf = it & 1;
        if (it + 1 < NT) { load_kv(it + 1, buf ^ 1); cp_commit(); }

        float s[8][4];
#pragma unroll
        for (int i = 0; i < 8; i++)
#pragma unroll
            for (int j = 0; j < 4; j++) s[i][j] = 0.0f;

#pragma unroll
        for (int kk = 0; kk < 4; ++kk) {
#pragma unroll
            for (int g = 0; g < 4; ++g) {
                uint32_t kh[4], kl[4];
                int idx = (buf * 64 + g * 16 + (lane & 15)) * A_KST
                        + kk * 16 + (lane >> 4) * 8;
                ldm4(kh, &Ks_h[idx]);
                ldm4(kl, &Ks_l[idx]);
                uint32_t b0h[2] = { kh[0], kh[2] }, b1h[2] = { kh[1], kh[3] };
                uint32_t b0l[2] = { kl[0], kl[2] }, b1l[2] = { kl[1], kl[3] };
                mma16816h(s[2 * g],     qf[kk], b0h);
                mma16816h(s[2 * g],     qf[kk], b0l);
                mma16816h(s[2 * g + 1], qf[kk], b1h);
                mma16816h(s[2 * g + 1], qf[kk], b1l);
            }
        }

        float tm0 = -CUDART_INF_F, tm1 = -CUDART_INF_F;
#pragma unroll
        for (int nt = 0; nt < 8; ++nt) {
            int cb = nt * 8 + (lane & 3) * 2;
            float mb0 = mbs[buf * 64 + cb], mb1 = mbs[buf * 64 + cb + 1];
            s[nt][0] = s[nt][0] * 0.125f + mb0;
            s[nt][1] = s[nt][1] * 0.125f + mb1;
            s[nt][2] = s[nt][2] * 0.125f + mb0;
            s[nt][3] = s[nt][3] * 0.125f + mb1;
            tm0 = fmaxf(tm0, fmaxf(s[nt][0], s[nt][1]));
            tm1 = fmaxf(tm1, fmaxf(s[nt][2], s[nt][3]));
        }
        tm0 = fmaxf(tm0, __shfl_xor_sync(0xffffffffu, tm0, 1));
        tm0 = fmaxf(tm0, __shfl_xor_sync(0xffffffffu, tm0, 2));
        tm1 = fmaxf(tm1, __shfl_xor_sync(0xffffffffu, tm1, 1));
        tm1 = fmaxf(tm1, __shfl_xor_sync(0xffffffffu, tm1, 2));
        float mn0 = fmaxf(m0r, tm0), mn1 = fmaxf(m1r, tm1);
        float al0 = __expf(m0r - mn0), al1 = __expf(m1r - mn1);
        m0r = mn0; m1r = mn1;

        float rs0 = 0.0f, rs1 = 0.0f;
#pragma unroll
        for (int nt = 0; nt < 8; ++nt) {
            s[nt][0] = __expf(s[nt][0] - mn0);
            s[nt][1] = __expf(s[nt][1] - mn0);
            s[nt][2] = __expf(s[nt][2] - mn1);
            s[nt][3] = __expf(s[nt][3] - mn1);
            rs0 += s[nt][0] + s[nt][1];
            rs1 += s[nt][2] + s[nt][3];
        }
        rs0 += __shfl_xor_sync(0xffffffffu, rs0, 1);
        rs0 += __shfl_xor_sync(0xffffffffu, rs0, 2);
        rs1 += __shfl_xor_sync(0xffffffffu, rs1, 1);
        rs1 += __shfl_xor_sync(0xffffffffu, rs1, 2);
        l0r = l0r * al0 + rs0;
        l1r = l1r * al1 + rs1;

#pragma unroll
        for (int dn = 0; dn < 8; ++dn) {
            o[dn][0] *= al0; o[dn][1] *= al0;
            o[dn][2] *= al1; o[dn][3] *= al1;
        }

#pragma unroll
        for (int kt = 0; kt < 4; ++kt) {
            uint32_t pah[4] = {
                packhf(s[2 * kt][0],     s[2 * kt][1]),
                packhf(s[2 * kt][2],     s[2 * kt][3]),
                packhf(s[2 * kt + 1][0], s[2 * kt + 1][1]),
                packhf(s[2 * kt + 1][2], s[2 * kt + 1][3])
            };
#pragma unroll
            for (int dg = 0; dg < 4; ++dg) {
                uint32_t vh[4], vl[4];
                int idx = (buf * 64 + kt * 16 + (lane & 15)) * A_KST
                        + dg * 16 + (lane >> 4) * 8;
                ldm4t(vh, &Vs_h[idx]);
                ldm4t(vl, &Vs_l[idx]);
                uint32_t b0h[2] = { vh[0], vh[1] }, b1h[2] = { vh[2], vh[3] };
                uint32_t b0l[2] = { vl[0], vl[1] }, b1l[2] = { vl[2], vl[3] };
                mma16816h(o[2 * dg],     pah, b0h);
                mma16816h(o[2 * dg],     pah, b0l);
                mma16816h(o[2 * dg + 1], pah, b1h);
                mma16816h(o[2 * dg + 1], pah, b1l);
            }
        }

        if (it + 1 < NT) {
            cp_wait<0>();
            __syncthreads();
        }
    }

    float inv0 = 1.0f / l0r, inv1 = 1.0f / l1r;
#pragma unroll
    for (int dn = 0; dn < 8; ++dn) {
        int row = q0 + wid * 16 + (lane >> 2);
        int col = h * HDc + dn * 8 + (lane & 3) * 2;
        float v00 = o[dn][0] * inv0, v01 = o[dn][1] * inv0;
        float v10 = o[dn][2] * inv1, v11 = o[dn][3] * inv1;
        size_t i0 = (size_t)(b * SQc + row) * Hc + col;
        size_t i1 = (size_t)(b * SQc + row + 8) * Hc + col;
        __nv_bfloat162 h0 = __floats2bfloat162_rn(v00, v01);
        __nv_bfloat162 h1 = __floats2bfloat162_rn(v10, v11);
        *(uint32_t*)(Ah + i0) = b2u(h0);
        *(uint32_t*)(Ah + i1) = b2u(h1);
        *(uint32_t*)(Al + i0) = packbf(v00 - __low2float(h0), v01 - __high2float(h0));
        *(uint32_t*)(Al + i1) = packbf(v10 - __low2float(h1), v11 - __high2float(h1));
    }
}

// ---------------- launch ----------------
extern "C" void kernel_launch(void* const* d_in, const int* in_sizes, int n_in,
                              void* d_out, int out_size)
{
    (void)in_sizes; (void)n_in; (void)out_size;

    bf16 *Xq_h, *Xq_l, *Xkv_h, *Xkv_l;
    bf16 *Wq_h, *Wq_l, *Wk_h, *Wk_l, *Wv_h, *Wv_l, *Wo_h, *Wo_l;
    fp16 *Q16, *K16h, *K16l, *V16h, *V16l;
    bf16 *A_h, *A_l;
    cudaGetSymbolAddress((void**)&Xq_h, g_Xq_h);   cudaGetSymbolAddress((void**)&Xq_l, g_Xq_l);
    cudaGetSymbolAddress((void**)&Xkv_h, g_Xkv_h); cudaGetSymbolAddress((void**)&Xkv_l, g_Xkv_l);
    cudaGetSymbolAddress((void**)&Wq_h, g_Wq_h);   cudaGetSymbolAddress((void**)&Wq_l, g_Wq_l);
    cudaGetSymbolAddress((void**)&Wk_h, g_Wk_h);   cudaGetSymbolAddress((void**)&Wk_l, g_Wk_l);
    cudaGetSymbolAddress((void**)&Wv_h, g_Wv_h);   cudaGetSymbolAddress((void**)&Wv_l, g_Wv_l);
    cudaGetSymbolAddress((void**)&Wo_h, g_Wo_h);   cudaGetSymbolAddress((void**)&Wo_l, g_Wo_l);
    cudaGetSymbolAddress((void**)&Q16, g_Q16);
    cudaGetSymbolAddress((void**)&K16h, g_K16h);   cudaGetSymbolAddress((void**)&K16l, g_K16l);
    cudaGetSymbolAddress((void**)&V16h, g_V16h);   cudaGetSymbolAddress((void**)&V16l, g_V16l);
    cudaGetSymbolAddress((void**)&A_h, g_A_h);     cudaGetSymbolAddress((void**)&A_l, g_A_l);

    cudaFuncSetAttribute(gemm_split, cudaFuncAttributeMaxDynamicSharedMemorySize, GEMM_SMEM);
    cudaFuncSetAttribute(attn_mma,   cudaFuncAttributeMaxDynamicSharedMemorySize, ATTN_SMEM);

    // (1) mask
    mask_kernel<<<1, 256>>>((const unsigned char*)d_in[2]);

    // (2) all splits in one launch
    SplitArgs sa;
    sa.src[0] = (const float*)d_in[0]; sa.hi[0] = Xq_h;  sa.lo[0] = Xq_l;  sa.n4[0] = Mrows * Dc / 4;
    sa.src[1] = (const float*)d_in[1]; sa.hi[1] = Xkv_h; sa.lo[1] = Xkv_l; sa.n4[1] = Mrows * Dc / 4;
    sa.src[2] = (const float*)d_in[3]; sa.hi[2] = Wq_h;  sa.lo[2] = Wq_l;  sa.n4[2] = Dc * Hc / 4;
    sa.src[3] = (const float*)d_in[5]; sa.hi[3] = Wk_h;  sa.lo[3] = Wk_l;  sa.n4[3] = Dc * Hc / 4;
    sa.src[4] = (const float*)d_in[7]; sa.hi[4] = Wv_h;  sa.lo[4] = Wv_l;  sa.n4[4] = Dc * Hc / 4;
    sa.src[5] = (const float*)d_in[9]; sa.hi[5] = Wo_h;  sa.lo[5] = Wo_l;  sa.n4[5] = Hc * Dc / 4;
    split_all<<<dim3((Mrows * Dc / 4 + 255) / 256, 6), 256>>>(sa);

    // (3,4,5) projections -> fp16 outputs for attention
    dim3 pg(Hc / 128, Mrows / 128);   // (8, 32)
    gemm_split<<<pg, 256, GEMM_SMEM>>>(Xq_h, Xq_l, Wq_h, Wq_l, (const float*)d_in[4],
                                       nullptr, nullptr, nullptr, Q16, nullptr,
                                       Mrows, Hc, Dc);
    gemm_split<<<pg, 256, GEMM_SMEM>>>(Xkv_h, Xkv_l, Wk_h, Wk_l, (const float*)d_in[6],
                                       nullptr, nullptr, nullptr, K16h, K16l,
                                       Mrows, Hc, Dc);
    gemm_split<<<pg, 256, GEMM_SMEM>>>(Xkv_h, Xkv_l, Wv_h, Wv_l, (const float*)d_in[8],
                                       nullptr, nullptr, nullptr, V16h, V16l,
                                       Mrows, Hc, Dc);

    // (6) attention (fp16 2-term)
    attn_mma<<<dim3(SQc / 128, NHc, Bc), 256, ATTN_SMEM>>>(Q16, K16h, K16l,
                                                           V16h, V16l, A_h, A_l);

    // (7) output projection (bf16 3-term, fp32 out)
    dim3 og(Dc / 128, Mrows / 128);   // (8, 32)
    gemm_split<<<og, 256, GEMM_SMEM>>>(A_h, A_l, Wo_h, Wo_l, (const float*)d_in[10],
                                       nullptr, nullptr, (float*)d_out, nullptr, nullptr,
                                       Mrows, Dc, Hc);
}

// round 9
// speedup vs baseline: 4.1078x; 1.1412x over previous
#include <cuda_runtime.h>
#include <cuda_bf16.h>
#include <cuda_fp16.h>
#include <math_constants.h>
#include <cstdint>

#define Bc    2
#define SQc   2048
#define SKVc  2048
#define Dc    1024
#define Hc    1024
#define NHc   16
#define HDc   64
#define Mrows 4096

typedef __nv_bfloat16 bf16;
typedef __half fp16;

// ---------------- scratch (device globals, allocation-free) ----------------
__device__ fp16 g_Xq16[(size_t)Mrows * Dc];                         // hi only
__device__ fp16 g_Xkv16[(size_t)Mrows * Dc];                        // hi only
__device__ fp16 g_Wq16h[(size_t)Dc * Hc], g_Wq16l[(size_t)Dc * Hc];
__device__ fp16 g_Wk16h[(size_t)Dc * Hc], g_Wk16l[(size_t)Dc * Hc];
__device__ fp16 g_Wv16h[(size_t)Dc * Hc], g_Wv16l[(size_t)Dc * Hc];
__device__ bf16 g_Wo_h[(size_t)Hc * Dc], g_Wo_l[(size_t)Hc * Dc];
__device__ fp16 g_Q16[(size_t)Mrows * Hc];                          // hi only
__device__ fp16 g_K16h[(size_t)Mrows * Hc], g_K16l[(size_t)Mrows * Hc];
__device__ fp16 g_V16h[(size_t)Mrows * Hc], g_V16l[(size_t)Mrows * Hc];
__device__ bf16 g_A_h[(size_t)Mrows * Hc], g_A_l[(size_t)Mrows * Hc];
__device__ float g_maskbias[Bc * SKVc];

// ---------------- small helpers ----------------
__device__ __forceinline__ uint32_t smem_u32(const void* p) {
    return (uint32_t)__cvta_generic_to_shared(p);
}
__device__ __forceinline__ void cpa16(void* dst, const void* src) {
    asm volatile("cp.async.cg.shared.global [%0], [%1], 16;\n"
                 :: "r"(smem_u32(dst)), "l"(src));
}
__device__ __forceinline__ void cp_commit() { asm volatile("cp.async.commit_group;\n"); }
template <int N> __device__ __forceinline__ void cp_wait() {
    asm volatile("cp.async.wait_group %0;\n" :: "n"(N) : "memory");
}
__device__ __forceinline__ void ldm4(uint32_t r[4], const void* p) {
    asm volatile("ldmatrix.sync.aligned.m8n8.x4.shared.b16 {%0,%1,%2,%3}, [%4];\n"
                 : "=r"(r[0]), "=r"(r[1]), "=r"(r[2]), "=r"(r[3]) : "r"(smem_u32(p)));
}
__device__ __forceinline__ void ldm4t(uint32_t r[4], const void* p) {
    asm volatile("ldmatrix.sync.aligned.m8n8.x4.trans.shared.b16 {%0,%1,%2,%3}, [%4];\n"
                 : "=r"(r[0]), "=r"(r[1]), "=r"(r[2]), "=r"(r[3]) : "r"(smem_u32(p)));
}
__device__ __forceinline__ void mma16816(float c[4], const uint32_t a[4], const uint32_t b[2]) {
    asm volatile("mma.sync.aligned.m16n8k16.row.col.f32.bf16.bf16.f32 "
                 "{%0,%1,%2,%3}, {%4,%5,%6,%7}, {%8,%9}, {%0,%1,%2,%3};\n"
                 : "+f"(c[0]), "+f"(c[1]), "+f"(c[2]), "+f"(c[3])
                 : "r"(a[0]), "r"(a[1]), "r"(a[2]), "r"(a[3]), "r"(b[0]), "r"(b[1]));
}
__device__ __forceinline__ void mma16816h(float c[4], const uint32_t a[4], const uint32_t b[2]) {
    asm volatile("mma.sync.aligned.m16n8k16.row.col.f32.f16.f16.f32 "
                 "{%0,%1,%2,%3}, {%4,%5,%6,%7}, {%8,%9}, {%0,%1,%2,%3};\n"
                 : "+f"(c[0]), "+f"(c[1]), "+f"(c[2]), "+f"(c[3])
                 : "r"(a[0]), "r"(a[1]), "r"(a[2]), "r"(a[3]), "r"(b[0]), "r"(b[1]));
}
__device__ __forceinline__ uint32_t b2u(__nv_bfloat162 v) {
    return *reinterpret_cast<uint32_t*>(&v);
}
__device__ __forceinline__ uint32_t h2u(__half2 v) {
    return *reinterpret_cast<uint32_t*>(&v);
}
__device__ __forceinline__ uint32_t packbf(float a, float b) {
    __nv_bfloat162 t = __floats2bfloat162_rn(a, b);
    return b2u(t);
}
__device__ __forceinline__ uint32_t packhf(float a, float b) {
    __half2 t = __floats2half2_rn(a, b);
    return h2u(t);
}

// ---------------- fused mask detect + bias build (single block) ----------------
__global__ void mask_kernel(const unsigned char* __restrict__ m) {
    __shared__ int nz[4];
    int tid = threadIdx.x;
    if (tid < 4) nz[tid] = 0;
    __syncthreads();
    for (int p = tid; p < Bc * SKVc; p += blockDim.x)
        if (m[p]) atomicOr(&nz[p & 3], 1);
    __syncthreads();
    int kind = 0;
    if (!nz[1] && !nz[2] && !nz[3]) kind = 1;       // int32 0/1
    else if (!nz[0] && !nz[1])      kind = 2;       // float32 0/1
    for (int i = tid; i < Bc * SKVc; i += blockDim.x) {
        bool mk;
        if (kind == 1)      mk = ((const int*)m)[i] != 0;
        else if (kind == 2) mk = ((const float*)m)[i] != 0.0f;
        else                mk = m[i] != 0;
        g_maskbias[i] = mk ? -1e30f : 0.0f;
    }
}

// ---------------- fused split (z-sliced, per-slice mode) ----------
// mode 0: bf16 hi/lo   mode 1: fp16 hi/lo   mode 2: fp16 hi only
struct SplitArgs {
    const float* src[6];
    void* hi[6];
    void* lo[6];
    int   n4[6];
    int   mode[6];
};
__global__ __launch_bounds__(256) void split_all(SplitArgs a) {
    int z = blockIdx.y;
    int i4 = blockIdx.x * 256 + threadIdx.x;
    if (i4 >= a.n4[z]) return;
    float4 v = ((const float4*)a.src[z])[i4];
    int mode = a.mode[z];
    if (mode == 0) {
        __nv_bfloat162 h0 = __floats2bfloat162_rn(v.x, v.y);
        __nv_bfloat162 h1 = __floats2bfloat162_rn(v.z, v.w);
        uint32_t l0 = packbf(v.x - __low2float(h0), v.y - __high2float(h0));
        uint32_t l1 = packbf(v.z - __low2float(h1), v.w - __high2float(h1));
        ((uint2*)a.hi[z])[i4] = make_uint2(b2u(h0), b2u(h1));
        ((uint2*)a.lo[z])[i4] = make_uint2(l0, l1);
    } else {
        __half2 h0 = __floats2half2_rn(v.x, v.y);
        __half2 h1 = __floats2half2_rn(v.z, v.w);
        ((uint2*)a.hi[z])[i4] = make_uint2(h2u(h0), h2u(h1));
        if (mode == 1) {
            uint32_t l0 = packhf(v.x - __half2float(__low2half(h0)),
                                 v.y - __half2float(__high2half(h0)));
            uint32_t l1 = packhf(v.z - __half2float(__low2half(h1)),
                                 v.w - __half2float(__high2half(h1)));
            ((uint2*)a.lo[z])[i4] = make_uint2(l0, l1);
        }
    }
}

// ---------------- bf16 3-term GEMM (Wo only): Cf = A@W + bias ----------------
#define G_AST 40
#define G_BST 136
#define G_STG 3
#define GEMM_SMEM (G_STG * (128 * G_AST + 32 * G_BST) * 2 * (int)sizeof(bf16))

__global__ __launch_bounds__(256, 2) void gemm_split(
    const bf16* __restrict__ Ah, const bf16* __restrict__ Al,
    const bf16* __restrict__ Wh, const bf16* __restrict__ Wl,
    const float* __restrict__ bias, float* __restrict__ Cf,
    int M, int N, int K)
{
    extern __shared__ char sm[];
    bf16* Ash = (bf16*)sm;
    bf16* Asl = Ash + G_STG * 128 * G_AST;
    bf16* Bsh = Asl + G_STG * 128 * G_AST;
    bf16* Bsl = Bsh + G_STG * 32 * G_BST;

    int tid = threadIdx.x, lane = tid & 31, wid = tid >> 5;
    int wm = wid & 1, wn = wid >> 1;
    int m0 = blockIdx.y * 128, n0 = blockIdx.x * 128;

    float acc[4][4][4];
#pragma unroll
    for (int i = 0; i < 4; i++)
#pragma unroll
        for (int j = 0; j < 4; j++)
#pragma unroll
            for (int e = 0; e < 4; e++) acc[i][j][e] = 0.0f;

    auto load_tiles = [&](int it, int s) {
        int k0 = it * 32;
#pragma unroll
        for (int x = tid; x < 1024; x += 256) {
            int mat = x >> 9, i = x & 511;
            int r = i >> 2, kc = (i & 3) * 8;
            const bf16* src = (mat ? Al : Ah) + (size_t)(m0 + r) * K + k0 + kc;
            bf16* dst = (mat ? Asl : Ash) + (s * 128 + r) * G_AST + kc;
            cpa16(dst, src);
        }
#pragma unroll
        for (int x = tid; x < 1024; x += 256) {
            int mat = x >> 9, i = x & 511;
            int r = i >> 4, nc = (i & 15) * 8;
            const bf16* src = (mat ? Wl : Wh) + (size_t)(k0 + r) * N + n0 + nc;
            bf16* dst = (mat ? Bsl : Bsh) + (s * 32 + r) * G_BST + nc;
            cpa16(dst, src);
        }
    };

    int NIT = K / 32;
    load_tiles(0, 0); cp_commit();
    load_tiles(1, 1); cp_commit();

    int s = 0, s2 = 2;
    for (int it = 0; it < NIT; ++it) {
        if (it + 1 < NIT) cp_wait<1>(); else cp_wait<0>();
        __syncthreads();
        if (it + 2 < NIT) { load_tiles(it + 2, s2); cp_commit(); }

#pragma unroll
        for (int kk = 0; kk < 2; ++kk) {
            uint32_t ah[4][4], al[4][4], bh[2][4], bl[2][4];
#pragma unroll
            for (int mt = 0; mt < 4; ++mt) {
                int idx = (s * 128 + wm * 64 + mt * 16 + (lane & 15)) * G_AST
                        + kk * 16 + (lane >> 4) * 8;
                ldm4(ah[mt], &Ash[idx]);
                ldm4(al[mt], &Asl[idx]);
            }
#pragma unroll
            for (int g = 0; g < 2; ++g) {
                int idx = (s * 32 + kk * 16 + (lane & 15)) * G_BST
                        + wn * 32 + g * 16 + (lane >> 4) * 8;
                ldm4t(bh[g], &Bsh[idx]);
                ldm4t(bl[g], &Bsl[idx]);
            }
#pragma unroll
            for (int mt = 0; mt < 4; ++mt)
#pragma unroll
                for (int g = 0; g < 2; ++g) {
                    uint32_t bh0[2] = { bh[g][0], bh[g][1] }, bh1[2] = { bh[g][2], bh[g][3] };
                    uint32_t bl0[2] = { bl[g][0], bl[g][1] }, bl1[2] = { bl[g][2], bl[g][3] };
                    mma16816(acc[mt][2 * g],     ah[mt], bh0);
                    mma16816(acc[mt][2 * g],     ah[mt], bl0);
                    mma16816(acc[mt][2 * g],     al[mt], bh0);
                    mma16816(acc[mt][2 * g + 1], ah[mt], bh1);
                    mma16816(acc[mt][2 * g + 1], ah[mt], bl1);
                    mma16816(acc[mt][2 * g + 1], al[mt], bh1);
                }
        }
        s  = (s  == 2) ? 0 : s + 1;
        s2 = (s2 == 2) ? 0 : s2 + 1;
    }

#pragma unroll
    for (int mt = 0; mt < 4; ++mt)
#pragma unroll
        for (int nt = 0; nt < 4; ++nt) {
            int row = m0 + wm * 64 + mt * 16 + (lane >> 2);
            int col = n0 + wn * 32 + nt * 8 + (lane & 3) * 2;
            float b0 = bias[col], b1 = bias[col + 1];
            size_t i0 = (size_t)row * N + col;
            size_t i1 = (size_t)(row + 8) * N + col;
            *(float2*)(Cf + i0) = make_float2(acc[mt][nt][0] + b0, acc[mt][nt][1] + b1);
            *(float2*)(Cf + i1) = make_float2(acc[mt][nt][2] + b0, acc[mt][nt][3] + b1);
        }
}

// ---------------- fp16 2-term GEMM (Q/K/V projections) ----------------
// C = Xh @ (Wh + Wl) + bias; outputs fp16 hi (and optionally lo).
#define F_AST 40
#define F_BST 136
#define F_STG 3
#define GEMM16_SMEM (F_STG * (128 * F_AST + 2 * 32 * F_BST) * (int)sizeof(fp16))

__global__ __launch_bounds__(256, 2) void gemm_f16(
    const fp16* __restrict__ Ah,
    const fp16* __restrict__ Wh, const fp16* __restrict__ Wl,
    const float* __restrict__ bias,
    fp16* __restrict__ Hh, fp16* __restrict__ Hl,
    int M, int N, int K)
{
    extern __shared__ char sm[];
    fp16* Ash = (fp16*)sm;                          // [3][128][F_AST]
    fp16* Bsh = Ash + F_STG * 128 * F_AST;          // [3][32][F_BST]
    fp16* Bsl = Bsh + F_STG * 32 * F_BST;

    int tid = threadIdx.x, lane = tid & 31, wid = tid >> 5;
    int wm = wid & 1, wn = wid >> 1;
    int m0 = blockIdx.y * 128, n0 = blockIdx.x * 128;

    float acc[4][4][4];
#pragma unroll
    for (int i = 0; i < 4; i++)
#pragma unroll
        for (int j = 0; j < 4; j++)
#pragma unroll
            for (int e = 0; e < 4; e++) acc[i][j][e] = 0.0f;

    auto load_tiles = [&](int it, int s) {
        int k0 = it * 32;
#pragma unroll
        for (int x = tid; x < 512; x += 256) {        // A hi: 128 x 32
            int r = x >> 2, kc = (x & 3) * 8;
            cpa16(&Ash[(s * 128 + r) * F_AST + kc],
                  Ah + (size_t)(m0 + r) * K + k0 + kc);
        }
#pragma unroll
        for (int x = tid; x < 1024; x += 256) {       // B hi/lo: 32 x 128
            int mat = x >> 9, i = x & 511;
            int r = i >> 4, nc = (i & 15) * 8;
            const fp16* src = (mat ? Wl : Wh) + (size_t)(k0 + r) * N + n0 + nc;
            fp16* dst = (mat ? Bsl : Bsh) + (s * 32 + r) * F_BST + nc;
            cpa16(dst, src);
        }
    };

    int NIT = K / 32;
    load_tiles(0, 0); cp_commit();
    load_tiles(1, 1); cp_commit();

    int s = 0, s2 = 2;
    for (int it = 0; it < NIT; ++it) {
        if (it + 1 < NIT) cp_wait<1>(); else cp_wait<0>();
        __syncthreads();
        if (it + 2 < NIT) { load_tiles(it + 2, s2); cp_commit(); }

#pragma unroll
        for (int kk = 0; kk < 2; ++kk) {
            uint32_t a[4][4], bh[2][4], bl[2][4];
#pragma unroll
            for (int mt = 0; mt < 4; ++mt) {
                int idx = (s * 128 + wm * 64 + mt * 16 + (lane & 15)) * F_AST
                        + kk * 16 + (lane >> 4) * 8;
                ldm4(a[mt], &Ash[idx]);
            }
#pragma unroll
            for (int g = 0; g < 2; ++g) {
                int idx = (s * 32 + kk * 16 + (lane & 15)) * F_BST
                        + wn * 32 + g * 16 + (lane >> 4) * 8;
                ldm4t(bh[g], &Bsh[idx]);
                ldm4t(bl[g], &Bsl[idx]);
            }
#pragma unroll
            for (int mt = 0; mt < 4; ++mt)
#pragma unroll
                for (int g = 0; g < 2; ++g) {
                    uint32_t bh0[2] = { bh[g][0], bh[g][1] }, bh1[2] = { bh[g][2], bh[g][3] };
                    uint32_t bl0[2] = { bl[g][0], bl[g][1] }, bl1[2] = { bl[g][2], bl[g][3] };
                    mma16816h(acc[mt][2 * g],     a[mt], bh0);
                    mma16816h(acc[mt][2 * g],     a[mt], bl0);
                    mma16816h(acc[mt][2 * g + 1], a[mt], bh1);
                    mma16816h(acc[mt][2 * g + 1], a[mt], bl1);
                }
        }
        s  = (s  == 2) ? 0 : s + 1;
        s2 = (s2 == 2) ? 0 : s2 + 1;
    }

#pragma unroll
    for (int mt = 0; mt < 4; ++mt)
#pragma unroll
        for (int nt = 0; nt < 4; ++nt) {
            int row = m0 + wm * 64 + mt * 16 + (lane >> 2);
            int col = n0 + wn * 32 + nt * 8 + (lane & 3) * 2;
            float b0 = bias[col], b1 = bias[col + 1];
            float v00 = acc[mt][nt][0] + b0, v01 = acc[mt][nt][1] + b1;
            float v10 = acc[mt][nt][2] + b0, v11 = acc[mt][nt][3] + b1;
            size_t i0 = (size_t)row * N + col;
            size_t i1 = (size_t)(row + 8) * N + col;
            __half2 h0 = __floats2half2_rn(v00, v01);
            __half2 h1 = __floats2half2_rn(v10, v11);
            *(uint32_t*)(Hh + i0) = h2u(h0);
            *(uint32_t*)(Hh + i1) = h2u(h1);
            if (Hl) {
                *(uint32_t*)(Hl + i0) = packhf(v00 - __half2float(__low2half(h0)),
                                               v01 - __half2float(__high2half(h0)));
                *(uint32_t*)(Hl + i1) = packhf(v10 - __half2float(__low2half(h1)),
                                               v11 - __half2float(__high2half(h1)));
            }
        }
}

// ---------------- fp16 2-term flash attention (unchanged from R8) ----------------
#define A_QST 72
#define A_KST 72
#define ATTN_SMEM ((128*A_QST + 4*2*64*A_KST) * (int)sizeof(fp16) + 2*64*(int)sizeof(float))

__global__ __launch_bounds__(256) void attn_mma(
    const fp16* __restrict__ Qh, const fp16* __restrict__ Kh,
    const fp16* __restrict__ Kl, const fp16* __restrict__ Vh,
    const fp16* __restrict__ Vl,
    bf16* __restrict__ Ah, bf16* __restrict__ Al)
{
    extern __shared__ char sm[];
    fp16* Qs   = (fp16*)sm;
    fp16* Ks_h = Qs + 128 * A_QST;
    fp16* Ks_l = Ks_h + 2 * 64 * A_KST;
    fp16* Vs_h = Ks_l + 2 * 64 * A_KST;
    fp16* Vs_l = Vs_h + 2 * 64 * A_KST;
    float* mbs = (float*)(Vs_l + 2 * 64 * A_KST);

    int tid = threadIdx.x, lane = tid & 31, wid = tid >> 5;
    int q0 = blockIdx.x * 128, h = blockIdx.y, b = blockIdx.z;

#pragma unroll
    for (int c = tid; c < 1024; c += 256) {
        int r = c >> 3, col = (c & 7) * 8;
        size_t src = (size_t)(b * SQc + q0 + r) * Hc + h * HDc + col;
        cpa16(&Qs[r * A_QST + col], Qh + src);
    }
    cp_commit();

    auto load_kv = [&](int it, int buf) {
        int t0 = it * 64;
#pragma unroll
        for (int c = tid; c < 512; c += 256) {
            int r = c >> 3, col = (c & 7) * 8;
            size_t src = (size_t)(b * SKVc + t0 + r) * Hc + h * HDc + col;
            cpa16(&Ks_h[(buf * 64 + r) * A_KST + col], Kh + src);
            cpa16(&Ks_l[(buf * 64 + r) * A_KST + col], Kl + src);
            cpa16(&Vs_h[(buf * 64 + r) * A_KST + col], Vh + src);
            cpa16(&Vs_l[(buf * 64 + r) * A_KST + col], Vl + src);
        }
        if (tid < 16)
            cpa16(&mbs[buf * 64 + tid * 4], g_maskbias + b * SKVc + t0 + tid * 4);
    };

    load_kv(0, 0);
    cp_commit();
    cp_wait<0>();
    __syncthreads();

    uint32_t qf[4][4];
    {
        int r = wid * 16 + (lane & 15);
#pragma unroll
        for (int kk = 0; kk < 4; ++kk)
            ldm4(qf[kk], &Qs[r * A_QST + kk * 16 + (lane >> 4) * 8]);
    }

    float o[8][4];
#pragma unroll
    for (int i = 0; i < 8; i++)
#pragma unroll
        for (int j = 0; j < 4; j++) o[i][j] = 0.0f;
    float m0r = -CUDART_INF_F, m1r = -CUDART_INF_F;
    float l0r = 0.0f, l1r = 0.0f;

    const int NT = SKVc / 64;
    for (int it = 0; it < NT; ++it) {
        int buf = it & 1;
        if (it + 1 < NT) { load_kv(it + 1, buf ^ 1); cp_commit(); }

        float s[8][4];
#pragma unroll
        for (int i = 0; i < 8; i++)
#pragma unroll
            for (int j = 0; j < 4; j++) s[i][j] = 0.0f;

#pragma unroll
        for (int kk = 0; kk < 4; ++kk) {
#pragma unroll
            for (int g = 0; g < 4; ++g) {
                uint32_t kh[4], kl[4];
                int idx = (buf * 64 + g * 16 + (lane & 15)) * A_KST
                        + kk * 16 + (lane >> 4) * 8;
                ldm4(kh, &Ks_h[idx]);
                ldm4(kl, &Ks_l[idx]);
                uint32_t b0h[2] = { kh[0], kh[2] }, b1h[2] = { kh[1], kh[3] };
                uint32_t b0l[2] = { kl[0], kl[2] }, b1l[2] = { kl[1], kl[3] };
                mma16816h(s[2 * g],     qf[kk], b0h);
                mma16816h(s[2 * g],     qf[kk], b0l);
                mma16816h(s[2 * g + 1], qf[kk], b1h);
                mma16816h(s[2 * g + 1], qf[kk], b1l);
            }
        }

        float tm0 = -CUDART_INF_F, tm1 = -CUDART_INF_F;
#pragma unroll
        for (int nt = 0; nt < 8; ++nt) {
            int cb = nt * 8 + (lane & 3) * 2;
            float mb0 = mbs[buf * 64 + cb], mb1 = mbs[buf * 64 + cb + 1];
            s[nt][0] = s[nt][0] * 0.125f + mb0;
            s[nt][1] = s[nt][1] * 0.125f + mb1;
            s[nt][2] = s[nt][2] * 0.125f + mb0;
            s[nt][3] = s[nt][3] * 0.125f + mb1;
            tm0 = fmaxf(tm0, fmaxf(s[nt][0], s[nt][1]));
            tm1 = fmaxf(tm1, fmaxf(s[nt][2], s[nt][3]));
        }
        tm0 = fmaxf(tm0, __shfl_xor_sync(0xffffffffu, tm0, 1));
        tm0 = fmaxf(tm0, __shfl_xor_sync(0xffffffffu, tm0, 2));
        tm1 = fmaxf(tm1, __shfl_xor_sync(0xffffffffu, tm1, 1));
        tm1 = fmaxf(tm1, __shfl_xor_sync(0xffffffffu, tm1, 2));
        float mn0 = fmaxf(m0r, tm0), mn1 = fmaxf(m1r, tm1);
        float al0 = __expf(m0r - mn0), al1 = __expf(m1r - mn1);
        m0r = mn0; m1r = mn1;

        float rs0 = 0.0f, rs1 = 0.0f;
#pragma unroll
        for (int nt = 0; nt < 8; ++nt) {
            s[nt][0] = __expf(s[nt][0] - mn0);
            s[nt][1] = __expf(s[nt][1] - mn0);
            s[nt][2] = __expf(s[nt][2] - mn1);
            s[nt][3] = __expf(s[nt][3] - mn1);
            rs0 += s[nt][0] + s[nt][1];
            rs1 += s[nt][2] + s[nt][3];
        }
        rs0 += __shfl_xor_sync(0xffffffffu, rs0, 1);
        rs0 += __shfl_xor_sync(0xffffffffu, rs0, 2);
        rs1 += __shfl_xor_sync(0xffffffffu, rs1, 1);
        rs1 += __shfl_xor_sync(0xffffffffu, rs1, 2);
        l0r = l0r * al0 + rs0;
        l1r = l1r * al1 + rs1;

#pragma unroll
        for (int dn = 0; dn < 8; ++dn) {
            o[dn][0] *= al0; o[dn][1] *= al0;
            o[dn][2] *= al1; o[dn][3] *= al1;
        }

#pragma unroll
        for (int kt = 0; kt < 4; ++kt) {
            uint32_t pah[4] = {
                packhf(s[2 * kt][0],     s[2 * kt][1]),
                packhf(s[2 * kt][2],     s[2 * kt][3]),
                packhf(s[2 * kt + 1][0], s[2 * kt + 1][1]),
                packhf(s[2 * kt + 1][2], s[2 * kt + 1][3])
            };
#pragma unroll
            for (int dg = 0; dg < 4; ++dg) {
                uint32_t vh[4], vl[4];
                int idx = (buf * 64 + kt * 16 + (lane & 15)) * A_KST
                        + dg * 16 + (lane >> 4) * 8;
                ldm4t(vh, &Vs_h[idx]);
                ldm4t(vl, &Vs_l[idx]);
                uint32_t b0h[2] = { vh[0], vh[1] }, b1h[2] = { vh[2], vh[3] };
                uint32_t b0l[2] = { vl[0], vl[1] }, b1l[2] = { vl[2], vl[3] };
                mma16816h(o[2 * dg],     pah, b0h);
                mma16816h(o[2 * dg],     pah, b0l);
                mma16816h(o[2 * dg + 1], pah, b1h);
                mma16816h(o[2 * dg + 1], pah, b1l);
            }
        }

        if (it + 1 < NT) {
            cp_wait<0>();
            __syncthreads();
        }
    }

    float inv0 = 1.0f / l0r, inv1 = 1.0f / l1r;
#pragma unroll
    for (int dn = 0; dn < 8; ++dn) {
        int row = q0 + wid * 16 + (lane >> 2);
        int col = h * HDc + dn * 8 + (lane & 3) * 2;
        float v00 = o[dn][0] * inv0, v01 = o[dn][1] * inv0;
        float v10 = o[dn][2] * inv1, v11 = o[dn][3] * inv1;
        size_t i0 = (size_t)(b * SQc + row) * Hc + col;
        size_t i1 = (size_t)(b * SQc + row + 8) * Hc + col;
        __nv_bfloat162 h0 = __floats2bfloat162_rn(v00, v01);
        __nv_bfloat162 h1 = __floats2bfloat162_rn(v10, v11);
        *(uint32_t*)(Ah + i0) = b2u(h0);
        *(uint32_t*)(Ah + i1) = b2u(h1);
        *(uint32_t*)(Al + i0) = packbf(v00 - __low2float(h0), v01 - __high2float(h0));
        *(uint32_t*)(Al + i1) = packbf(v10 - __low2float(h1), v11 - __high2float(h1));
    }
}

// ---------------- launch ----------------
extern "C" void kernel_launch(void* const* d_in, const int* in_sizes, int n_in,
                              void* d_out, int out_size)
{
    (void)in_sizes; (void)n_in; (void)out_size;

    fp16 *Xq16, *Xkv16, *Wq16h, *Wq16l, *Wk16h, *Wk16l, *Wv16h, *Wv16l;
    bf16 *Wo_h, *Wo_l, *A_h, *A_l;
    fp16 *Q16, *K16h, *K16l, *V16h, *V16l;
    cudaGetSymbolAddress((void**)&Xq16, g_Xq16);
    cudaGetSymbolAddress((void**)&Xkv16, g_Xkv16);
    cudaGetSymbolAddress((void**)&Wq16h, g_Wq16h); cudaGetSymbolAddress((void**)&Wq16l, g_Wq16l);
    cudaGetSymbolAddress((void**)&Wk16h, g_Wk16h); cudaGetSymbolAddress((void**)&Wk16l, g_Wk16l);
    cudaGetSymbolAddress((void**)&Wv16h, g_Wv16h); cudaGetSymbolAddress((void**)&Wv16l, g_Wv16l);
    cudaGetSymbolAddress((void**)&Wo_h, g_Wo_h);   cudaGetSymbolAddress((void**)&Wo_l, g_Wo_l);
    cudaGetSymbolAddress((void**)&Q16, g_Q16);
    cudaGetSymbolAddress((void**)&K16h, g_K16h);   cudaGetSymbolAddress((void**)&K16l, g_K16l);
    cudaGetSymbolAddress((void**)&V16h, g_V16h);   cudaGetSymbolAddress((void**)&V16l, g_V16l);
    cudaGetSymbolAddress((void**)&A_h, g_A_h);     cudaGetSymbolAddress((void**)&A_l, g_A_l);

    cudaFuncSetAttribute(gemm_split, cudaFuncAttributeMaxDynamicSharedMemorySize, GEMM_SMEM);
    cudaFuncSetAttribute(gemm_f16,   cudaFuncAttributeMaxDynamicSharedMemorySize, GEMM16_SMEM);
    cudaFuncSetAttribute(attn_mma,   cudaFuncAttributeMaxDynamicSharedMemorySize, ATTN_SMEM);

    // (1) mask
    mask_kernel<<<1, 256>>>((const unsigned char*)d_in[2]);

    // (2) all splits in one launch
    SplitArgs sa;
    sa.src[0] = (const float*)d_in[0]; sa.hi[0] = Xq16;  sa.lo[0] = nullptr; sa.n4[0] = Mrows * Dc / 4; sa.mode[0] = 2;
    sa.src[1] = (const float*)d_in[1]; sa.hi[1] = Xkv16; sa.lo[1] = nullptr; sa.n4[1] = Mrows * Dc / 4; sa.mode[1] = 2;
    sa.src[2] = (const float*)d_in[3]; sa.hi[2] = Wq16h; sa.lo[2] = Wq16l;  sa.n4[2] = Dc * Hc / 4;    sa.mode[2] = 1;
    sa.src[3] = (const float*)d_in[5]; sa.hi[3] = Wk16h; sa.lo[3] = Wk16l;  sa.n4[3] = Dc * Hc / 4;    sa.mode[3] = 1;
    sa.src[4] = (const float*)d_in[7]; sa.hi[4] = Wv16h; sa.lo[4] = Wv16l;  sa.n4[4] = Dc * Hc / 4;    sa.mode[4] = 1;
    sa.src[5] = (const float*)d_in[9]; sa.hi[5] = Wo_h;  sa.lo[5] = Wo_l;   sa.n4[5] = Hc * Dc / 4;    sa.mode[5] = 0;
    split_all<<<dim3((Mrows * Dc / 4 + 255) / 256, 6), 256>>>(sa);

    // (3,4,5) projections: fp16 2-term
    dim3 pg(Hc / 128, Mrows / 128);   // (8, 32)
    gemm_f16<<<pg, 256, GEMM16_SMEM>>>(Xq16, Wq16h, Wq16l, (const float*)d_in[4],
                                       Q16, nullptr, Mrows, Hc, Dc);
    gemm_f16<<<pg, 256, GEMM16_SMEM>>>(Xkv16, Wk16h, Wk16l, (const float*)d_in[6],
                                       K16h, K16l, Mrows, Hc, Dc);
    gemm_f16<<<pg, 256, GEMM16_SMEM>>>(Xkv16, Wv16h, Wv16l, (const float*)d_in[8],
                                       V16h, V16l, Mrows, Hc, Dc);

    // (6) attention (fp16 2-term)
    attn_mma<<<dim3(SQc / 128, NHc, Bc), 256, ATTN_SMEM>>>(Q16, K16h, K16l,
                                                           V16h, V16l, A_h, A_l);

    // (7) output projection (bf16 3-term, fp32 out)
    dim3 og(Dc / 128, Mrows / 128);   // (8, 32)
    gemm_split<<<og, 256, GEMM_SMEM>>>(A_h, A_l, Wo_h, Wo_l, (const float*)d_in[10],
                                       (float*)d_out, Mrows, Dc, Hc);
}

// round 11
// speedup vs baseline: 5.4092x; 1.3168x over previous
#include <cuda_runtime.h>
#include <cuda_fp16.h>
#include <math_constants.h>
#include <cstdint>

#define Bc    2
#define SQc   2048
#define SKVc  2048
#define Dc    1024
#define Hc    1024
#define NHc   16
#define HDc   64
#define Mrows 4096

typedef __half fp16;

// ---------------- scratch (device globals, allocation-free) ----------------
__device__ fp16 g_Xq16[(size_t)Mrows * Dc];                         // hi only
__device__ fp16 g_Xkv16[(size_t)Mrows * Dc];                        // hi only
__device__ fp16 g_Wq16h[(size_t)Dc * Hc], g_Wq16l[(size_t)Dc * Hc];
__device__ fp16 g_Wk16h[(size_t)Dc * Hc], g_Wk16l[(size_t)Dc * Hc];
__device__ fp16 g_Wv16h[(size_t)Dc * Hc], g_Wv16l[(size_t)Dc * Hc];
__device__ fp16 g_Wo16h[(size_t)Hc * Dc], g_Wo16l[(size_t)Hc * Dc];
__device__ fp16 g_Q16[(size_t)Mrows * Hc];                          // hi only
__device__ fp16 g_K16[(size_t)Mrows * Hc];                          // hi only
__device__ fp16 g_V16[(size_t)Mrows * Hc];                          // hi only
__device__ fp16 g_A16[(size_t)Mrows * Hc];                          // hi only
__device__ float g_maskbias[Bc * SKVc];

// ---------------- small helpers ----------------
__device__ __forceinline__ uint32_t smem_u32(const void* p) {
    return (uint32_t)__cvta_generic_to_shared(p);
}
__device__ __forceinline__ void cpa16(void* dst, const void* src) {
    asm volatile("cp.async.cg.shared.global [%0], [%1], 16;\n"
                 :: "r"(smem_u32(dst)), "l"(src));
}
__device__ __forceinline__ void cp_commit() { asm volatile("cp.async.commit_group;\n"); }
template <int N> __device__ __forceinline__ void cp_wait() {
    asm volatile("cp.async.wait_group %0;\n" :: "n"(N) : "memory");
}
__device__ __forceinline__ void ldm4(uint32_t r[4], const void* p) {
    asm volatile("ldmatrix.sync.aligned.m8n8.x4.shared.b16 {%0,%1,%2,%3}, [%4];\n"
                 : "=r"(r[0]), "=r"(r[1]), "=r"(r[2]), "=r"(r[3]) : "r"(smem_u32(p)));
}
__device__ __forceinline__ void ldm4t(uint32_t r[4], const void* p) {
    asm volatile("ldmatrix.sync.aligned.m8n8.x4.trans.shared.b16 {%0,%1,%2,%3}, [%4];\n"
                 : "=r"(r[0]), "=r"(r[1]), "=r"(r[2]), "=r"(r[3]) : "r"(smem_u32(p)));
}
__device__ __forceinline__ void mma16816h(float c[4], const uint32_t a[4], const uint32_t b[2]) {
    asm volatile("mma.sync.aligned.m16n8k16.row.col.f32.f16.f16.f32 "
                 "{%0,%1,%2,%3}, {%4,%5,%6,%7}, {%8,%9}, {%0,%1,%2,%3};\n"
                 : "+f"(c[0]), "+f"(c[1]), "+f"(c[2]), "+f"(c[3])
                 : "r"(a[0]), "r"(a[1]), "r"(a[2]), "r"(a[3]), "r"(b[0]), "r"(b[1]));
}
__device__ __forceinline__ uint32_t h2u(__half2 v) {
    return *reinterpret_cast<uint32_t*>(&v);
}
__device__ __forceinline__ uint32_t packhf(float a, float b) {
    __half2 t = __floats2half2_rn(a, b);
    return h2u(t);
}

// ---------------- fused mask detect + bias build (single block) ----------------
__global__ void mask_kernel(const unsigned char* __restrict__ m) {
    __shared__ int nz[4];
    int tid = threadIdx.x;
    if (tid < 4) nz[tid] = 0;
    __syncthreads();
    for (int p = tid; p < Bc * SKVc; p += blockDim.x)
        if (m[p]) atomicOr(&nz[p & 3], 1);
    __syncthreads();
    int kind = 0;
    if (!nz[1] && !nz[2] && !nz[3]) kind = 1;       // int32 0/1
    else if (!nz[0] && !nz[1])      kind = 2;       // float32 0/1
    for (int i = tid; i < Bc * SKVc; i += blockDim.x) {
        bool mk;
        if (kind == 1)      mk = ((const int*)m)[i] != 0;
        else if (kind == 2) mk = ((const float*)m)[i] != 0.0f;
        else                mk = m[i] != 0;
        g_maskbias[i] = mk ? -1e30f : 0.0f;
    }
}

// ---------------- fused split (z-sliced; mode 1: fp16 hi/lo, 2: hi only) ------
struct SplitArgs {
    const float* src[6];
    fp16* hi[6];
    fp16* lo[6];
    int   n4[6];
    int   mode[6];
};
__global__ __launch_bounds__(256) void split_all(SplitArgs a) {
    int z = blockIdx.y;
    int i4 = blockIdx.x * 256 + threadIdx.x;
    if (i4 >= a.n4[z]) return;
    float4 v = ((const float4*)a.src[z])[i4];
    __half2 h0 = __floats2half2_rn(v.x, v.y);
    __half2 h1 = __floats2half2_rn(v.z, v.w);
    ((uint2*)a.hi[z])[i4] = make_uint2(h2u(h0), h2u(h1));
    if (a.mode[z] == 1) {
        uint32_t l0 = packhf(v.x - __half2float(__low2half(h0)),
                             v.y - __half2float(__high2half(h0)));
        uint32_t l1 = packhf(v.z - __half2float(__low2half(h1)),
                             v.w - __half2float(__high2half(h1)));
        ((uint2*)a.lo[z])[i4] = make_uint2(l0, l1);
    }
}

// ---------------- fp16 2-term GEMM: C = Xh @ (Wh + Wl) + bias ----------------
// BM=128, BN=128, BK=32, 3 stages, 256 threads, 2 CTAs/SM.
// Outputs fp16 hi (Hh) or fp32 (Cf).
#define F_AST 40
#define F_BST 136
#define F_STG 3
#define GEMM16_SMEM (F_STG * (128 * F_AST + 2 * 32 * F_BST) * (int)sizeof(fp16))

__global__ __launch_bounds__(256, 2) void gemm_f16(
    const fp16* __restrict__ Ah,
    const fp16* __restrict__ Wh, const fp16* __restrict__ Wl,
    const float* __restrict__ bias,
    fp16* __restrict__ Hh, float* __restrict__ Cf,
    int M, int N, int K)
{
    extern __shared__ char sm[];
    fp16* Ash = (fp16*)sm;                          // [3][128][F_AST]
    fp16* Bsh = Ash + F_STG * 128 * F_AST;          // [3][32][F_BST]
    fp16* Bsl = Bsh + F_STG * 32 * F_BST;

    int tid = threadIdx.x, lane = tid & 31, wid = tid >> 5;
    int wm = wid & 1, wn = wid >> 1;
    int m0 = blockIdx.y * 128, n0 = blockIdx.x * 128;

    float acc[4][4][4];
#pragma unroll
    for (int i = 0; i < 4; i++)
#pragma unroll
        for (int j = 0; j < 4; j++)
#pragma unroll
            for (int e = 0; e < 4; e++) acc[i][j][e] = 0.0f;

    auto load_tiles = [&](int it, int s) {
        int k0 = it * 32;
#pragma unroll
        for (int x = tid; x < 512; x += 256) {        // A hi: 128 x 32
            int r = x >> 2, kc = (x & 3) * 8;
            cpa16(&Ash[(s * 128 + r) * F_AST + kc],
                  Ah + (size_t)(m0 + r) * K + k0 + kc);
        }
#pragma unroll
        for (int x = tid; x < 1024; x += 256) {       // B hi/lo: 32 x 128
            int mat = x >> 9, i = x & 511;
            int r = i >> 4, nc = (i & 15) * 8;
            const fp16* src = (mat ? Wl : Wh) + (size_t)(k0 + r) * N + n0 + nc;
            fp16* dst = (mat ? Bsl : Bsh) + (s * 32 + r) * F_BST + nc;
            cpa16(dst, src);
        }
    };

    int NIT = K / 32;
    load_tiles(0, 0); cp_commit();
    load_tiles(1, 1); cp_commit();

    int s = 0, s2 = 2;
    for (int it = 0; it < NIT; ++it) {
        if (it + 1 < NIT) cp_wait<1>(); else cp_wait<0>();
        __syncthreads();
        if (it + 2 < NIT) { load_tiles(it + 2, s2); cp_commit(); }

#pragma unroll
        for (int kk = 0; kk < 2; ++kk) {
            uint32_t a[4][4], bh[2][4], bl[2][4];
#pragma unroll
            for (int mt = 0; mt < 4; ++mt) {
                int idx = (s * 128 + wm * 64 + mt * 16 + (lane & 15)) * F_AST
                        + kk * 16 + (lane >> 4) * 8;
                ldm4(a[mt], &Ash[idx]);
            }
#pragma unroll
            for (int g = 0; g < 2; ++g) {
                int idx = (s * 32 + kk * 16 + (lane & 15)) * F_BST
                        + wn * 32 + g * 16 + (lane >> 4) * 8;
                ldm4t(bh[g], &Bsh[idx]);
                ldm4t(bl[g], &Bsl[idx]);
            }
#pragma unroll
            for (int mt = 0; mt < 4; ++mt)
#pragma unroll
                for (int g = 0; g < 2; ++g) {
                    uint32_t bh0[2] = { bh[g][0], bh[g][1] }, bh1[2] = { bh[g][2], bh[g][3] };
                    uint32_t bl0[2] = { bl[g][0], bl[g][1] }, bl1[2] = { bl[g][2], bl[g][3] };
                    mma16816h(acc[mt][2 * g],     a[mt], bh0);
                    mma16816h(acc[mt][2 * g],     a[mt], bl0);
                    mma16816h(acc[mt][2 * g + 1], a[mt], bh1);
                    mma16816h(acc[mt][2 * g + 1], a[mt], bl1);
                }
        }
        s  = (s  == 2) ? 0 : s + 1;
        s2 = (s2 == 2) ? 0 : s2 + 1;
    }

#pragma unroll
    for (int mt = 0; mt < 4; ++mt)
#pragma unroll
        for (int nt = 0; nt < 4; ++nt) {
            int row = m0 + wm * 64 + mt * 16 + (lane >> 2);
            int col = n0 + wn * 32 + nt * 8 + (lane & 3) * 2;
            float b0 = bias[col], b1 = bias[col + 1];
            float v00 = acc[mt][nt][0] + b0, v01 = acc[mt][nt][1] + b1;
            float v10 = acc[mt][nt][2] + b0, v11 = acc[mt][nt][3] + b1;
            size_t i0 = (size_t)row * N + col;
            size_t i1 = (size_t)(row + 8) * N + col;
            if (Cf) {
                *(float2*)(Cf + i0) = make_float2(v00, v01);
                *(float2*)(Cf + i1) = make_float2(v10, v11);
            } else {
                *(uint32_t*)(Hh + i0) = packhf(v00, v01);
                *(uint32_t*)(Hh + i1) = packhf(v10, v11);
            }
        }
}

// ---------------- fp16 hi-only flash attention ----------------
// S = Qh·Kh;  O = Ph·Vh.  fp16 hi output.
#define A_QST 72
#define A_KST 72
#define ATTN_SMEM ((128*A_QST + 2*2*64*A_KST) * (int)sizeof(fp16) + 2*64*(int)sizeof(float))

__global__ __launch_bounds__(256) void attn_mma(
    const fp16* __restrict__ Qh, const fp16* __restrict__ Kh,
    const fp16* __restrict__ Vh, fp16* __restrict__ Ao)
{
    extern __shared__ char sm[];
    fp16* Qs = (fp16*)sm;                         // [128][A_QST]
    fp16* Ks = Qs + 128 * A_QST;                  // [2][64][A_KST]
    fp16* Vs = Ks + 2 * 64 * A_KST;
    float* mbs = (float*)(Vs + 2 * 64 * A_KST);   // [2][64]

    int tid = threadIdx.x, lane = tid & 31, wid = tid >> 5;
    int q0 = blockIdx.x * 128, h = blockIdx.y, b = blockIdx.z;

#pragma unroll
    for (int c = tid; c < 1024; c += 256) {
        int r = c >> 3, col = (c & 7) * 8;
        size_t src = (size_t)(b * SQc + q0 + r) * Hc + h * HDc + col;
        cpa16(&Qs[r * A_QST + col], Qh + src);
    }
    cp_commit();

    auto load_kv = [&](int it, int buf) {
        int t0 = it * 64;
#pragma unroll
        for (int c = tid; c < 512; c += 256) {
            int r = c >> 3, col = (c & 7) * 8;
            size_t src = (size_t)(b * SKVc + t0 + r) * Hc + h * HDc + col;
            cpa16(&Ks[(buf * 64 + r) * A_KST + col], Kh + src);
            cpa16(&Vs[(buf * 64 + r) * A_KST + col], Vh + src);
        }
        if (tid < 16)
            cpa16(&mbs[buf * 64 + tid * 4], g_maskbias + b * SKVc + t0 + tid * 4);
    };

    load_kv(0, 0);
    cp_commit();
    cp_wait<0>();
    __syncthreads();

    uint32_t qf[4][4];
    {
        int r = wid * 16 + (lane & 15);
#pragma unroll
        for (int kk = 0; kk < 4; ++kk)
            ldm4(qf[kk], &Qs[r * A_QST + kk * 16 + (lane >> 4) * 8]);
    }

    float o[8][4];
#pragma unroll
    for (int i = 0; i < 8; i++)
#pragma unroll
        for (int j = 0; j < 4; j++) o[i][j] = 0.0f;
    float m0r = -CUDART_INF_F, m1r = -CUDART_INF_F;
    float l0r = 0.0f, l1r = 0.0f;

    const int NT = SKVc / 64;
    for (int it = 0; it < NT; ++it) {
        int buf = it & 1;
        if (it + 1 < NT) { load_kv(it + 1, buf ^ 1); cp_commit(); }

        float s[8][4];
#pragma unroll
        for (int i = 0; i < 8; i++)
#pragma unroll
            for (int j = 0; j < 4; j++) s[i][j] = 0.0f;

#pragma unroll
        for (int kk = 0; kk < 4; ++kk) {
#pragma unroll
            for (int g = 0; g < 4; ++g) {
                uint32_t kf[4];
                int idx = (buf * 64 + g * 16 + (lane & 15)) * A_KST
                        + kk * 16 + (lane >> 4) * 8;
                ldm4(kf, &Ks[idx]);
                uint32_t b0[2] = { kf[0], kf[2] }, b1[2] = { kf[1], kf[3] };
                mma16816h(s[2 * g],     qf[kk], b0);
                mma16816h(s[2 * g + 1], qf[kk], b1);
            }
        }

        float tm0 = -CUDART_INF_F, tm1 = -CUDART_INF_F;
#pragma unroll
        for (int nt = 0; nt < 8; ++nt) {
            int cb = nt * 8 + (lane & 3) * 2;
            float mb0 = mbs[buf * 64 + cb], mb1 = mbs[buf * 64 + cb + 1];
            s[nt][0] = s[nt][0] * 0.125f + mb0;
            s[nt][1] = s[nt][1] * 0.125f + mb1;
            s[nt][2] = s[nt][2] * 0.125f + mb0;
            s[nt][3] = s[nt][3] * 0.125f + mb1;
            tm0 = fmaxf(tm0, fmaxf(s[nt][0], s[nt][1]));
            tm1 = fmaxf(tm1, fmaxf(s[nt][2], s[nt][3]));
        }
        tm0 = fmaxf(tm0, __shfl_xor_sync(0xffffffffu, tm0, 1));
        tm0 = fmaxf(tm0, __shfl_xor_sync(0xffffffffu, tm0, 2));
        tm1 = fmaxf(tm1, __shfl_xor_sync(0xffffffffu, tm1, 1));
        tm1 = fmaxf(tm1, __shfl_xor_sync(0xffffffffu, tm1, 2));
        float mn0 = fmaxf(m0r, tm0), mn1 = fmaxf(m1r, tm1);
        float al0 = __expf(m0r - mn0), al1 = __expf(m1r - mn1);
        m0r = mn0; m1r = mn1;

        float rs0 = 0.0f, rs1 = 0.0f;
#pragma unroll
        for (int nt = 0; nt < 8; ++nt) {
            s[nt][0] = __expf(s[nt][0] - mn0);
            s[nt][1] = __expf(s[nt][1] - mn0);
            s[nt][2] = __expf(s[nt][2] - mn1);
            s[nt][3] = __expf(s[nt][3] - mn1);
            rs0 += s[nt][0] + s[nt][1];
            rs1 += s[nt][2] + s[nt][3];
        }
        rs0 += __shfl_xor_sync(0xffffffffu, rs0, 1);
        rs0 += __shfl_xor_sync(0xffffffffu, rs0, 2);
        rs1 += __shfl_xor_sync(0xffffffffu, rs1, 1);
        rs1 += __shfl_xor_sync(0xffffffffu, rs1, 2);
        l0r = l0r * al0 + rs0;
        l1r = l1r * al1 + rs1;

#pragma unroll
        for (int dn = 0; dn < 8; ++dn) {
            o[dn][0] *= al0; o[dn][1] *= al0;
            o[dn][2] *= al1; o[dn][3] *= al1;
        }

#pragma unroll
        for (int kt = 0; kt < 4; ++kt) {
            uint32_t pah[4] = {
                packhf(s[2 * kt][0],     s[2 * kt][1]),
                packhf(s[2 * kt][2],     s[2 * kt][3]),
                packhf(s[2 * kt + 1][0], s[2 * kt + 1][1]),
                packhf(s[2 * kt + 1][2], s[2 * kt + 1][3])
            };
#pragma unroll
            for (int dg = 0; dg < 4; ++dg) {
                uint32_t vf[4];
                int idx = (buf * 64 + kt * 16 + (lane & 15)) * A_KST
                        + dg * 16 + (lane >> 4) * 8;
                ldm4t(vf, &Vs[idx]);
                uint32_t b0[2] = { vf[0], vf[1] }, b1[2] = { vf[2], vf[3] };
                mma16816h(o[2 * dg],     pah, b0);
                mma16816h(o[2 * dg + 1], pah, b1);
            }
        }

        if (it + 1 < NT) {
            cp_wait<0>();
            __syncthreads();
        }
    }

    float inv0 = 1.0f / l0r, inv1 = 1.0f / l1r;
#pragma unroll
    for (int dn = 0; dn < 8; ++dn) {
        int row = q0 + wid * 16 + (lane >> 2);
        int col = h * HDc + dn * 8 + (lane & 3) * 2;
        size_t i0 = (size_t)(b * SQc + row) * Hc + col;
        size_t i1 = (size_t)(b * SQc + row + 8) * Hc + col;
        *(uint32_t*)(Ao + i0) = packhf(o[dn][0] * inv0, o[dn][1] * inv0);
        *(uint32_t*)(Ao + i1) = packhf(o[dn][2] * inv1, o[dn][3] * inv1);
    }
}

// ---------------- launch ----------------
// Order: mask(1), split(2), gemm Q(3) K(4) V(5), attn(6 <- ncu slot), gemm O(7)
extern "C" void kernel_launch(void* const* d_in, const int* in_sizes, int n_in,
                              void* d_out, int out_size)
{
    (void)in_sizes; (void)n_in; (void)out_size;

    fp16 *Xq16, *Xkv16, *Wq16h, *Wq16l, *Wk16h, *Wk16l, *Wv16h, *Wv16l;
    fp16 *Wo16h, *Wo16l, *Q16, *K16, *V16, *A16;
    cudaGetSymbolAddress((void**)&Xq16, g_Xq16);
    cudaGetSymbolAddress((void**)&Xkv16, g_Xkv16);
    cudaGetSymbolAddress((void**)&Wq16h, g_Wq16h); cudaGetSymbolAddress((void**)&Wq16l, g_Wq16l);
    cudaGetSymbolAddress((void**)&Wk16h, g_Wk16h); cudaGetSymbolAddress((void**)&Wk16l, g_Wk16l);
    cudaGetSymbolAddress((void**)&Wv16h, g_Wv16h); cudaGetSymbolAddress((void**)&Wv16l, g_Wv16l);
    cudaGetSymbolAddress((void**)&Wo16h, g_Wo16h); cudaGetSymbolAddress((void**)&Wo16l, g_Wo16l);
    cudaGetSymbolAddress((void**)&Q16, g_Q16);
    cudaGetSymbolAddress((void**)&K16, g_K16);
    cudaGetSymbolAddress((void**)&V16, g_V16);
    cudaGetSymbolAddress((void**)&A16, g_A16);

    cudaFuncSetAttribute(gemm_f16, cudaFuncAttributeMaxDynamicSharedMemorySize, GEMM16_SMEM);
    cudaFuncSetAttribute(attn_mma, cudaFuncAttributeMaxDynamicSharedMemorySize, ATTN_SMEM);

    // (1) mask
    mask_kernel<<<1, 256>>>((const unsigned char*)d_in[2]);

    // (2) all splits in one launch
    SplitArgs sa;
    sa.src[0] = (const float*)d_in[0]; sa.hi[0] = Xq16;  sa.lo[0] = nullptr; sa.n4[0] = Mrows * Dc / 4; sa.mode[0] = 2;
    sa.src[1] = (const float*)d_in[1]; sa.hi[1] = Xkv16; sa.lo[1] = nullptr; sa.n4[1] = Mrows * Dc / 4; sa.mode[1] = 2;
    sa.src[2] = (const float*)d_in[3]; sa.hi[2] = Wq16h; sa.lo[2] = Wq16l;  sa.n4[2] = Dc * Hc / 4;    sa.mode[2] = 1;
    sa.src[3] = (const float*)d_in[5]; sa.hi[3] = Wk16h; sa.lo[3] = Wk16l;  sa.n4[3] = Dc * Hc / 4;    sa.mode[3] = 1;
    sa.src[4] = (const float*)d_in[7]; sa.hi[4] = Wv16h; sa.lo[4] = Wv16l;  sa.n4[4] = Dc * Hc / 4;    sa.mode[4] = 1;
    sa.src[5] = (const float*)d_in[9]; sa.hi[5] = Wo16h; sa.lo[5] = Wo16l;  sa.n4[5] = Hc * Dc / 4;    sa.mode[5] = 1;
    split_all<<<dim3((Mrows * Dc / 4 + 255) / 256, 6), 256>>>(sa);

    // (3,4,5) projections: fp16 2-term, hi-only outputs
    dim3 pg(Hc / 128, Mrows / 128);   // (8, 32)
    gemm_f16<<<pg, 256, GEMM16_SMEM>>>(Xq16, Wq16h, Wq16l, (const float*)d_in[4],
                                       Q16, nullptr, Mrows, Hc, Dc);
    gemm_f16<<<pg, 256, GEMM16_SMEM>>>(Xkv16, Wk16h, Wk16l, (const float*)d_in[6],
                                       K16, nullptr, Mrows, Hc, Dc);
    gemm_f16<<<pg, 256, GEMM16_SMEM>>>(Xkv16, Wv16h, Wv16l, (const float*)d_in[8],
                                       V16, nullptr, Mrows, Hc, Dc);

    // (6) attention (fp16 hi-only)
    attn_mma<<<dim3(SQc / 128, NHc, Bc), 256, ATTN_SMEM>>>(Q16, K16, V16, A16);

    // (7) output projection: fp16 2-term, fp32 out
    dim3 og(Dc / 128, Mrows / 128);   // (8, 32)
    gemm_f16<<<og, 256, GEMM16_SMEM>>>(A16, Wo16h, Wo16l, (const float*)d_in[10],
                                       nullptr, (float*)d_out, Mrows, Dc, Hc);
}

// round 12
// speedup vs baseline: 6.3809x; 1.1796x over previous
#include <cuda_runtime.h>
#include <cuda_fp16.h>
#include <math_constants.h>
#include <cstdint>

#define Bc    2
#define SQc   2048
#define SKVc  2048
#define Dc    1024
#define Hc    1024
#define NHc   16
#define HDc   64
#define Mrows 4096

typedef __half fp16;

// ---------------- scratch (device globals, allocation-free) ----------------
__device__ fp16 g_Xq16[(size_t)Mrows * Dc];                         // hi only
__device__ fp16 g_Xkv16[(size_t)Mrows * Dc];                        // hi only
__device__ fp16 g_Wq16h[(size_t)Dc * Hc], g_Wq16l[(size_t)Dc * Hc];
__device__ fp16 g_Wk16h[(size_t)Dc * Hc], g_Wk16l[(size_t)Dc * Hc];
__device__ fp16 g_Wv16h[(size_t)Dc * Hc], g_Wv16l[(size_t)Dc * Hc];
__device__ fp16 g_Wo16h[(size_t)Hc * Dc], g_Wo16l[(size_t)Hc * Dc];
__device__ fp16 g_Q16[(size_t)Mrows * Hc];                          // hi only
__device__ fp16 g_K16[(size_t)Mrows * Hc];                          // compacted
__device__ fp16 g_V16[(size_t)Mrows * Hc];                          // compacted
__device__ fp16 g_A16[(size_t)Mrows * Hc];                          // hi only
__device__ int   g_cnt[Bc];                  // unmasked count per batch
__device__ int   g_idx[Bc * SKVc];           // compacted -> original row (absolute)
__device__ float g_cbias[Bc * SKVc];         // 0 below cnt, -1e30 padding

// ---------------- small helpers ----------------
__device__ __forceinline__ uint32_t smem_u32(const void* p) {
    return (uint32_t)__cvta_generic_to_shared(p);
}
__device__ __forceinline__ void cpa16(void* dst, const void* src) {
    asm volatile("cp.async.cg.shared.global [%0], [%1], 16;\n"
                 :: "r"(smem_u32(dst)), "l"(src));
}
__device__ __forceinline__ void cp_commit() { asm volatile("cp.async.commit_group;\n"); }
template <int N> __device__ __forceinline__ void cp_wait() {
    asm volatile("cp.async.wait_group %0;\n" :: "n"(N) : "memory");
}
__device__ __forceinline__ void ldm4(uint32_t r[4], const void* p) {
    asm volatile("ldmatrix.sync.aligned.m8n8.x4.shared.b16 {%0,%1,%2,%3}, [%4];\n"
                 : "=r"(r[0]), "=r"(r[1]), "=r"(r[2]), "=r"(r[3]) : "r"(smem_u32(p)));
}
__device__ __forceinline__ void ldm4t(uint32_t r[4], const void* p) {
    asm volatile("ldmatrix.sync.aligned.m8n8.x4.trans.shared.b16 {%0,%1,%2,%3}, [%4];\n"
                 : "=r"(r[0]), "=r"(r[1]), "=r"(r[2]), "=r"(r[3]) : "r"(smem_u32(p)));
}
__device__ __forceinline__ void mma16816h(float c[4], const uint32_t a[4], const uint32_t b[2]) {
    asm volatile("mma.sync.aligned.m16n8k16.row.col.f32.f16.f16.f32 "
                 "{%0,%1,%2,%3}, {%4,%5,%6,%7}, {%8,%9}, {%0,%1,%2,%3};\n"
                 : "+f"(c[0]), "+f"(c[1]), "+f"(c[2]), "+f"(c[3])
                 : "r"(a[0]), "r"(a[1]), "r"(a[2]), "r"(a[3]), "r"(b[0]), "r"(b[1]));
}
__device__ __forceinline__ uint32_t h2u(__half2 v) {
    return *reinterpret_cast<uint32_t*>(&v);
}
__device__ __forceinline__ uint32_t packhf(float a, float b) {
    __half2 t = __floats2half2_rn(a, b);
    return h2u(t);
}

// ---------------- mask detect + key compaction (single block) ----------------
__global__ void mask_kernel(const unsigned char* __restrict__ m) {
    __shared__ int nz[4];
    __shared__ int sums[256];
    __shared__ int offs[257];
    int tid = threadIdx.x;
    if (tid < 4) nz[tid] = 0;
    __syncthreads();
    for (int p = tid; p < Bc * SKVc; p += 256)
        if (m[p]) atomicOr(&nz[p & 3], 1);
    __syncthreads();
    int kind = 0;
    if (!nz[1] && !nz[2] && !nz[3]) kind = 1;       // int32 0/1
    else if (!nz[0] && !nz[1])      kind = 2;       // float32 0/1

    auto masked = [&](int i) -> bool {
        if (kind == 1) return ((const int*)m)[i] != 0;
        if (kind == 2) return ((const float*)m)[i] != 0.0f;
        return m[i] != 0;
    };

    const int CH = SKVc / 256;   // 8 positions per thread
    for (int b = 0; b < Bc; ++b) {
        int base = b * SKVc + tid * CH;
        int c = 0;
#pragma unroll
        for (int k = 0; k < CH; ++k)
            if (!masked(base + k)) c++;
        sums[tid] = c;
        __syncthreads();
        if (tid == 0) {
            int a = 0;
            for (int i = 0; i < 256; ++i) { offs[i] = a; a += sums[i]; }
            offs[256] = a;
            g_cnt[b] = a;
        }
        __syncthreads();
        int o = b * SKVc + offs[tid];
#pragma unroll
        for (int k = 0; k < CH; ++k) {
            if (!masked(base + k)) {
                g_idx[o] = base + k;      // absolute row in [0, 4096)
                g_cbias[o] = 0.0f;
                o++;
            }
        }
        int total = offs[256];
        for (int j = total + tid; j < SKVc; j += 256) {
            g_idx[b * SKVc + j] = b * SKVc;   // safe duplicate row
            g_cbias[b * SKVc + j] = -1e30f;
        }
        __syncthreads();
    }
}

// ---------------- fused split (z-sliced; mode 1: fp16 hi/lo, 2: hi only) ------
struct SplitArgs {
    const float* src[6];
    fp16* hi[6];
    fp16* lo[6];
    int   n4[6];
    int   mode[6];
};
__global__ __launch_bounds__(256) void split_all(SplitArgs a) {
    int z = blockIdx.y;
    int i4 = blockIdx.x * 256 + threadIdx.x;
    if (i4 >= a.n4[z]) return;
    float4 v = ((const float4*)a.src[z])[i4];
    __half2 h0 = __floats2half2_rn(v.x, v.y);
    __half2 h1 = __floats2half2_rn(v.z, v.w);
    ((uint2*)a.hi[z])[i4] = make_uint2(h2u(h0), h2u(h1));
    if (a.mode[z] == 1) {
        uint32_t l0 = packhf(v.x - __half2float(__low2half(h0)),
                             v.y - __half2float(__high2half(h0)));
        uint32_t l1 = packhf(v.z - __half2float(__low2half(h1)),
                             v.w - __half2float(__high2half(h1)));
        ((uint2*)a.lo[z])[i4] = make_uint2(l0, l1);
    }
}

// ---------------- fp16 2-term GEMM: C = Xh @ (Wh + Wl) + bias ----------------
// Optional A-row indirection (rowidx) + per-batch early exit (cntp; 2048 rows/batch).
#define F_AST 40
#define F_BST 136
#define F_STG 3
#define GEMM16_SMEM (F_STG * (128 * F_AST + 2 * 32 * F_BST) * (int)sizeof(fp16))

__global__ __launch_bounds__(256, 2) void gemm_f16(
    const fp16* __restrict__ Ah,
    const fp16* __restrict__ Wh, const fp16* __restrict__ Wl,
    const float* __restrict__ bias,
    fp16* __restrict__ Hh, float* __restrict__ Cf,
    const int* __restrict__ rowidx, const int* __restrict__ cntp,
    int M, int N, int K)
{
    extern __shared__ char sm[];
    fp16* Ash = (fp16*)sm;                          // [3][128][F_AST]
    fp16* Bsh = Ash + F_STG * 128 * F_AST;          // [3][32][F_BST]
    fp16* Bsl = Bsh + F_STG * 32 * F_BST;

    int tid = threadIdx.x, lane = tid & 31, wid = tid >> 5;
    int wm = wid & 1, wn = wid >> 1;
    int m0 = blockIdx.y * 128, n0 = blockIdx.x * 128;

    if (cntp && (m0 & (SKVc - 1)) >= cntp[m0 >> 11]) return;  // whole tile past count

    // loop-invariant A source rows (2 per thread)
    int r0 = tid >> 2, r1 = (tid + 256) >> 2;
    int grow0 = rowidx ? rowidx[m0 + r0] : (m0 + r0);
    int grow1 = rowidx ? rowidx[m0 + r1] : (m0 + r1);

    float acc[4][4][4];
#pragma unroll
    for (int i = 0; i < 4; i++)
#pragma unroll
        for (int j = 0; j < 4; j++)
#pragma unroll
            for (int e = 0; e < 4; e++) acc[i][j][e] = 0.0f;

    auto load_tiles = [&](int it, int s) {
        int k0 = it * 32;
        {   // A hi: 128 x 32, two 16B chunks per thread
            int kc0 = (tid & 3) * 8;
            cpa16(&Ash[(s * 128 + r0) * F_AST + kc0],
                  Ah + (size_t)grow0 * K + k0 + kc0);
            cpa16(&Ash[(s * 128 + r1) * F_AST + kc0],
                  Ah + (size_t)grow1 * K + k0 + kc0);
        }
#pragma unroll
        for (int x = tid; x < 1024; x += 256) {       // B hi/lo: 32 x 128
            int mat = x >> 9, i = x & 511;
            int r = i >> 4, nc = (i & 15) * 8;
            const fp16* src = (mat ? Wl : Wh) + (size_t)(k0 + r) * N + n0 + nc;
            fp16* dst = (mat ? Bsl : Bsh) + (s * 32 + r) * F_BST + nc;
            cpa16(dst, src);
        }
    };

    int NIT = K / 32;
    load_tiles(0, 0); cp_commit();
    load_tiles(1, 1); cp_commit();

    int s = 0, s2 = 2;
    for (int it = 0; it < NIT; ++it) {
        if (it + 1 < NIT) cp_wait<1>(); else cp_wait<0>();
        __syncthreads();
        if (it + 2 < NIT) { load_tiles(it + 2, s2); cp_commit(); }

#pragma unroll
        for (int kk = 0; kk < 2; ++kk) {
            uint32_t a[4][4], bh[2][4], bl[2][4];
#pragma unroll
            for (int mt = 0; mt < 4; ++mt) {
                int idx = (s * 128 + wm * 64 + mt * 16 + (lane & 15)) * F_AST
                        + kk * 16 + (lane >> 4) * 8;
                ldm4(a[mt], &Ash[idx]);
            }
#pragma unroll
            for (int g = 0; g < 2; ++g) {
                int idx = (s * 32 + kk * 16 + (lane & 15)) * F_BST
                        + wn * 32 + g * 16 + (lane >> 4) * 8;
                ldm4t(bh[g], &Bsh[idx]);
                ldm4t(bl[g], &Bsl[idx]);
            }
#pragma unroll
            for (int mt = 0; mt < 4; ++mt)
#pragma unroll
                for (int g = 0; g < 2; ++g) {
                    uint32_t bh0[2] = { bh[g][0], bh[g][1] }, bh1[2] = { bh[g][2], bh[g][3] };
                    uint32_t bl0[2] = { bl[g][0], bl[g][1] }, bl1[2] = { bl[g][2], bl[g][3] };
                    mma16816h(acc[mt][2 * g],     a[mt], bh0);
                    mma16816h(acc[mt][2 * g],     a[mt], bl0);
                    mma16816h(acc[mt][2 * g + 1], a[mt], bh1);
                    mma16816h(acc[mt][2 * g + 1], a[mt], bl1);
                }
        }
        s  = (s  == 2) ? 0 : s + 1;
        s2 = (s2 == 2) ? 0 : s2 + 1;
    }

#pragma unroll
    for (int mt = 0; mt < 4; ++mt)
#pragma unroll
        for (int nt = 0; nt < 4; ++nt) {
            int row = m0 + wm * 64 + mt * 16 + (lane >> 2);
            int col = n0 + wn * 32 + nt * 8 + (lane & 3) * 2;
            float b0 = bias[col], b1 = bias[col + 1];
            float v00 = acc[mt][nt][0] + b0, v01 = acc[mt][nt][1] + b1;
            float v10 = acc[mt][nt][2] + b0, v11 = acc[mt][nt][3] + b1;
            size_t i0 = (size_t)row * N + col;
            size_t i1 = (size_t)(row + 8) * N + col;
            if (Cf) {
                *(float2*)(Cf + i0) = make_float2(v00, v01);
                *(float2*)(Cf + i1) = make_float2(v10, v11);
            } else {
                *(uint32_t*)(Hh + i0) = packhf(v00, v01);
                *(uint32_t*)(Hh + i1) = packhf(v10, v11);
            }
        }
}

// ---------------- fp16 hi-only flash attention over COMPACTED keys ------------
#define A_QST 72
#define A_KST 72
#define ATTN_SMEM ((128*A_QST + 2*2*64*A_KST) * (int)sizeof(fp16) + 2*64*(int)sizeof(float))

__global__ __launch_bounds__(256) void attn_mma(
    const fp16* __restrict__ Qh, const fp16* __restrict__ Kh,
    const fp16* __restrict__ Vh, fp16* __restrict__ Ao)
{
    extern __shared__ char sm[];
    fp16* Qs = (fp16*)sm;                         // [128][A_QST]
    fp16* Ks = Qs + 128 * A_QST;                  // [2][64][A_KST]
    fp16* Vs = Ks + 2 * 64 * A_KST;
    float* mbs = (float*)(Vs + 2 * 64 * A_KST);   // [2][64]

    int tid = threadIdx.x, lane = tid & 31, wid = tid >> 5;
    int q0 = blockIdx.x * 128, h = blockIdx.y, b = blockIdx.z;

    int cnt = g_cnt[b];
    int NT = (cnt + 63) >> 6;                      // >=1 (mask not all-true)

#pragma unroll
    for (int c = tid; c < 1024; c += 256) {
        int r = c >> 3, col = (c & 7) * 8;
        size_t src = (size_t)(b * SQc + q0 + r) * Hc + h * HDc + col;
        cpa16(&Qs[r * A_QST + col], Qh + src);
    }
    cp_commit();

    auto load_kv = [&](int it, int buf) {
        int t0 = it * 64;
#pragma unroll
        for (int c = tid; c < 512; c += 256) {
            int r = c >> 3, col = (c & 7) * 8;
            size_t src = (size_t)(b * SKVc + t0 + r) * Hc + h * HDc + col;
            cpa16(&Ks[(buf * 64 + r) * A_KST + col], Kh + src);
            cpa16(&Vs[(buf * 64 + r) * A_KST + col], Vh + src);
        }
        if (tid < 16)
            cpa16(&mbs[buf * 64 + tid * 4], g_cbias + b * SKVc + t0 + tid * 4);
    };

    load_kv(0, 0);
    cp_commit();
    cp_wait<0>();
    __syncthreads();

    uint32_t qf[4][4];
    {
        int r = wid * 16 + (lane & 15);
#pragma unroll
        for (int kk = 0; kk < 4; ++kk)
            ldm4(qf[kk], &Qs[r * A_QST + kk * 16 + (lane >> 4) * 8]);
    }

    float o[8][4];
#pragma unroll
    for (int i = 0; i < 8; i++)
#pragma unroll
        for (int j = 0; j < 4; j++) o[i][j] = 0.0f;
    float m0r = -CUDART_INF_F, m1r = -CUDART_INF_F;
    float l0r = 0.0f, l1r = 0.0f;

    for (int it = 0; it < NT; ++it) {
        int buf = it & 1;
        if (it + 1 < NT) { load_kv(it + 1, buf ^ 1); cp_commit(); }

        float s[8][4];
#pragma unroll
        for (int i = 0; i < 8; i++)
#pragma unroll
            for (int j = 0; j < 4; j++) s[i][j] = 0.0f;

#pragma unroll
        for (int kk = 0; kk < 4; ++kk) {
#pragma unroll
            for (int g = 0; g < 4; ++g) {
                uint32_t kf[4];
                int idx = (buf * 64 + g * 16 + (lane & 15)) * A_KST
                        + kk * 16 + (lane >> 4) * 8;
                ldm4(kf, &Ks[idx]);
                uint32_t b0[2] = { kf[0], kf[2] }, b1[2] = { kf[1], kf[3] };
                mma16816h(s[2 * g],     qf[kk], b0);
                mma16816h(s[2 * g + 1], qf[kk], b1);
            }
        }

        float tm0 = -CUDART_INF_F, tm1 = -CUDART_INF_F;
#pragma unroll
        for (int nt = 0; nt < 8; ++nt) {
            int cb = nt * 8 + (lane & 3) * 2;
            float mb0 = mbs[buf * 64 + cb], mb1 = mbs[buf * 64 + cb + 1];
            s[nt][0] = s[nt][0] * 0.125f + mb0;
            s[nt][1] = s[nt][1] * 0.125f + mb1;
            s[nt][2] = s[nt][2] * 0.125f + mb0;
            s[nt][3] = s[nt][3] * 0.125f + mb1;
            tm0 = fmaxf(tm0, fmaxf(s[nt][0], s[nt][1]));
            tm1 = fmaxf(tm1, fmaxf(s[nt][2], s[nt][3]));
        }
        tm0 = fmaxf(tm0, __shfl_xor_sync(0xffffffffu, tm0, 1));
        tm0 = fmaxf(tm0, __shfl_xor_sync(0xffffffffu, tm0, 2));
        tm1 = fmaxf(tm1, __shfl_xor_sync(0xffffffffu, tm1, 1));
        tm1 = fmaxf(tm1, __shfl_xor_sync(0xffffffffu, tm1, 2));
        float mn0 = fmaxf(m0r, tm0), mn1 = fmaxf(m1r, tm1);
        float al0 = __expf(m0r - mn0), al1 = __expf(m1r - mn1);
        m0r = mn0; m1r = mn1;

        float rs0 = 0.0f, rs1 = 0.0f;
#pragma unroll
        for (int nt = 0; nt < 8; ++nt) {
            s[nt][0] = __expf(s[nt][0] - mn0);
            s[nt][1] = __expf(s[nt][1] - mn0);
            s[nt][2] = __expf(s[nt][2] - mn1);
            s[nt][3] = __expf(s[nt][3] - mn1);
            rs0 += s[nt][0] + s[nt][1];
            rs1 += s[nt][2] + s[nt][3];
        }
        rs0 += __shfl_xor_sync(0xffffffffu, rs0, 1);
        rs0 += __shfl_xor_sync(0xffffffffu, rs0, 2);
        rs1 += __shfl_xor_sync(0xffffffffu, rs1, 1);
        rs1 += __shfl_xor_sync(0xffffffffu, rs1, 2);
        l0r = l0r * al0 + rs0;
        l1r = l1r * al1 + rs1;

#pragma unroll
        for (int dn = 0; dn < 8; ++dn) {
            o[dn][0] *= al0; o[dn][1] *= al0;
            o[dn][2] *= al1; o[dn][3] *= al1;
        }

#pragma unroll
        for (int kt = 0; kt < 4; ++kt) {
            uint32_t pah[4] = {
                packhf(s[2 * kt][0],     s[2 * kt][1]),
                packhf(s[2 * kt][2],     s[2 * kt][3]),
                packhf(s[2 * kt + 1][0], s[2 * kt + 1][1]),
                packhf(s[2 * kt + 1][2], s[2 * kt + 1][3])
            };
#pragma unroll
            for (int dg = 0; dg < 4; ++dg) {
                uint32_t vf[4];
                int idx = (buf * 64 + kt * 16 + (lane & 15)) * A_KST
                        + dg * 16 + (lane >> 4) * 8;
                ldm4t(vf, &Vs[idx]);
                uint32_t b0[2] = { vf[0], vf[1] }, b1[2] = { vf[2], vf[3] };
                mma16816h(o[2 * dg],     pah, b0);
                mma16816h(o[2 * dg + 1], pah, b1);
            }
        }

        if (it + 1 < NT) {
            cp_wait<0>();
            __syncthreads();
        }
    }

    float inv0 = 1.0f / l0r, inv1 = 1.0f / l1r;
#pragma unroll
    for (int dn = 0; dn < 8; ++dn) {
        int row = q0 + wid * 16 + (lane >> 2);
        int col = h * HDc + dn * 8 + (lane & 3) * 2;
        size_t i0 = (size_t)(b * SQc + row) * Hc + col;
        size_t i1 = (size_t)(b * SQc + row + 8) * Hc + col;
        *(uint32_t*)(Ao + i0) = packhf(o[dn][0] * inv0, o[dn][1] * inv0);
        *(uint32_t*)(Ao + i1) = packhf(o[dn][2] * inv1, o[dn][3] * inv1);
    }
}

// ---------------- launch ----------------
// Order: mask(1), split(2), gemm Q(3) K(4) V(5), attn(6 <- ncu slot), gemm O(7)
extern "C" void kernel_launch(void* const* d_in, const int* in_sizes, int n_in,
                              void* d_out, int out_size)
{
    (void)in_sizes; (void)n_in; (void)out_size;

    fp16 *Xq16, *Xkv16, *Wq16h, *Wq16l, *Wk16h, *Wk16l, *Wv16h, *Wv16l;
    fp16 *Wo16h, *Wo16l, *Q16, *K16, *V16, *A16;
    int *idxp, *cntp;
    cudaGetSymbolAddress((void**)&Xq16, g_Xq16);
    cudaGetSymbolAddress((void**)&Xkv16, g_Xkv16);
    cudaGetSymbolAddress((void**)&Wq16h, g_Wq16h); cudaGetSymbolAddress((void**)&Wq16l, g_Wq16l);
    cudaGetSymbolAddress((void**)&Wk16h, g_Wk16h); cudaGetSymbolAddress((void**)&Wk16l, g_Wk16l);
    cudaGetSymbolAddress((void**)&Wv16h, g_Wv16h); cudaGetSymbolAddress((void**)&Wv16l, g_Wv16l);
    cudaGetSymbolAddress((void**)&Wo16h, g_Wo16h); cudaGetSymbolAddress((void**)&Wo16l, g_Wo16l);
    cudaGetSymbolAddress((void**)&Q16, g_Q16);
    cudaGetSymbolAddress((void**)&K16, g_K16);
    cudaGetSymbolAddress((void**)&V16, g_V16);
    cudaGetSymbolAddress((void**)&A16, g_A16);
    cudaGetSymbolAddress((void**)&idxp, g_idx);
    cudaGetSymbolAddress((void**)&cntp, g_cnt);

    cudaFuncSetAttribute(gemm_f16, cudaFuncAttributeMaxDynamicSharedMemorySize, GEMM16_SMEM);
    cudaFuncSetAttribute(attn_mma, cudaFuncAttributeMaxDynamicSharedMemorySize, ATTN_SMEM);

    // (1) mask + compaction
    mask_kernel<<<1, 256>>>((const unsigned char*)d_in[2]);

    // (2) all splits in one launch
    SplitArgs sa;
    sa.src[0] = (const float*)d_in[0]; sa.hi[0] = Xq16;  sa.lo[0] = nullptr; sa.n4[0] = Mrows * Dc / 4; sa.mode[0] = 2;
    sa.src[1] = (const float*)d_in[1]; sa.hi[1] = Xkv16; sa.lo[1] = nullptr; sa.n4[1] = Mrows * Dc / 4; sa.mode[1] = 2;
    sa.src[2] = (const float*)d_in[3]; sa.hi[2] = Wq16h; sa.lo[2] = Wq16l;  sa.n4[2] = Dc * Hc / 4;    sa.mode[2] = 1;
    sa.src[3] = (const float*)d_in[5]; sa.hi[3] = Wk16h; sa.lo[3] = Wk16l;  sa.n4[3] = Dc * Hc / 4;    sa.mode[3] = 1;
    sa.src[4] = (const float*)d_in[7]; sa.hi[4] = Wv16h; sa.lo[4] = Wv16l;  sa.n4[4] = Dc * Hc / 4;    sa.mode[4] = 1;
    sa.src[5] = (const float*)d_in[9]; sa.hi[5] = Wo16h; sa.lo[5] = Wo16l;  sa.n4[5] = Hc * Dc / 4;    sa.mode[5] = 1;
    split_all<<<dim3((Mrows * Dc / 4 + 255) / 256, 6), 256>>>(sa);

    // (3) Q projection: all rows
    dim3 pg(Hc / 128, Mrows / 128);   // (8, 32)
    gemm_f16<<<pg, 256, GEMM16_SMEM>>>(Xq16, Wq16h, Wq16l, (const float*)d_in[4],
                                       Q16, nullptr, nullptr, nullptr, Mrows, Hc, Dc);
    // (4,5) K/V projections: compacted rows only (early exit past count)
    gemm_f16<<<pg, 256, GEMM16_SMEM>>>(Xkv16, Wk16h, Wk16l, (const float*)d_in[6],
                                       K16, nullptr, idxp, cntp, Mrows, Hc, Dc);
    gemm_f16<<<pg, 256, GEMM16_SMEM>>>(Xkv16, Wv16h, Wv16l, (const float*)d_in[8],
                                       V16, nullptr, idxp, cntp, Mrows, Hc, Dc);

    // (6) attention over compacted keys
    attn_mma<<<dim3(SQc / 128, NHc, Bc), 256, ATTN_SMEM>>>(Q16, K16, V16, A16);

    // (7) output projection: fp16 2-term, fp32 out
    dim3 og(Dc / 128, Mrows / 128);   // (8, 32)
    gemm_f16<<<og, 256, GEMM16_SMEM>>>(A16, Wo16h, Wo16l, (const float*)d_in[10],
                                       nullptr, (float*)d_out, nullptr, nullptr, Mrows, Dc, Hc);
}

// round 14
// speedup vs baseline: 7.5011x; 1.1755x over previous
#include <cuda_runtime.h>
#include <cuda_fp16.h>
#include <math_constants.h>
#include <cstdint>

#define Bc    2
#define SQc   2048
#define SKVc  2048
#define Dc    1024
#define Hc    1024
#define NHc   16
#define HDc   64
#define Mrows 4096

typedef __half fp16;

// ---------------- scratch (device globals, allocation-free) ----------------
__device__ fp16 g_Xq16[(size_t)Mrows * Dc];                         // hi only
__device__ fp16 g_Xkv16[(size_t)Mrows * Dc];                        // hi only
__device__ fp16 g_Wq16h[(size_t)Dc * Hc], g_Wq16l[(size_t)Dc * Hc];
__device__ fp16 g_Wk16h[(size_t)Dc * Hc], g_Wk16l[(size_t)Dc * Hc];
__device__ fp16 g_Wv16h[(size_t)Dc * Hc], g_Wv16l[(size_t)Dc * Hc];
__device__ fp16 g_Wo16h[(size_t)Hc * Dc], g_Wo16l[(size_t)Hc * Dc];
__device__ fp16 g_Q16[(size_t)Mrows * Hc];                          // hi only
__device__ fp16 g_K16[(size_t)Mrows * Hc];                          // compacted
__device__ fp16 g_V16[(size_t)Mrows * Hc];                          // compacted
__device__ fp16 g_A16[(size_t)Mrows * Hc];                          // hi only
__device__ int   g_cnt[Bc];                  // unmasked count per batch
__device__ int   g_idx[Bc * SKVc];           // compacted -> original row (absolute)
__device__ float g_cbias[Bc * SKVc];         // 0 below cnt, -1e30 padding

// ---------------- small helpers ----------------
__device__ __forceinline__ uint32_t smem_u32(const void* p) {
    return (uint32_t)__cvta_generic_to_shared(p);
}
__device__ __forceinline__ void cpa16(void* dst, const void* src) {
    asm volatile("cp.async.cg.shared.global [%0], [%1], 16;\n"
                 :: "r"(smem_u32(dst)), "l"(src));
}
__device__ __forceinline__ void cp_commit() { asm volatile("cp.async.commit_group;\n"); }
template <int N> __device__ __forceinline__ void cp_wait() {
    asm volatile("cp.async.wait_group %0;\n" :: "n"(N) : "memory");
}
__device__ __forceinline__ void ldm4(uint32_t r[4], const void* p) {
    asm volatile("ldmatrix.sync.aligned.m8n8.x4.shared.b16 {%0,%1,%2,%3}, [%4];\n"
                 : "=r"(r[0]), "=r"(r[1]), "=r"(r[2]), "=r"(r[3]) : "r"(smem_u32(p)));
}
__device__ __forceinline__ void ldm4t(uint32_t r[4], const void* p) {
    asm volatile("ldmatrix.sync.aligned.m8n8.x4.trans.shared.b16 {%0,%1,%2,%3}, [%4];\n"
                 : "=r"(r[0]), "=r"(r[1]), "=r"(r[2]), "=r"(r[3]) : "r"(smem_u32(p)));
}
__device__ __forceinline__ void mma16816h(float c[4], const uint32_t a[4], const uint32_t b[2]) {
    asm volatile("mma.sync.aligned.m16n8k16.row.col.f32.f16.f16.f32 "
                 "{%0,%1,%2,%3}, {%4,%5,%6,%7}, {%8,%9}, {%0,%1,%2,%3};\n"
                 : "+f"(c[0]), "+f"(c[1]), "+f"(c[2]), "+f"(c[3])
                 : "r"(a[0]), "r"(a[1]), "r"(a[2]), "r"(a[3]), "r"(b[0]), "r"(b[1]));
}
__device__ __forceinline__ uint32_t h2u(__half2 v) {
    return *reinterpret_cast<uint32_t*>(&v);
}
__device__ __forceinline__ uint32_t packhf(float a, float b) {
    __half2 t = __floats2half2_rn(a, b);
    return h2u(t);
}

// ---------------- mask detect + key compaction (single block) ----------------
__global__ void mask_kernel(const unsigned char* __restrict__ m) {
    __shared__ int nz[4];
    __shared__ int sums[256];
    __shared__ int offs[257];
    int tid = threadIdx.x;
    if (tid < 4) nz[tid] = 0;
    __syncthreads();
    for (int p = tid; p < Bc * SKVc; p += 256)
        if (m[p]) atomicOr(&nz[p & 3], 1);
    __syncthreads();
    int kind = 0;
    if (!nz[1] && !nz[2] && !nz[3]) kind = 1;       // int32 0/1
    else if (!nz[0] && !nz[1])      kind = 2;       // float32 0/1

    auto masked = [&](int i) -> bool {
        if (kind == 1) return ((const int*)m)[i] != 0;
        if (kind == 2) return ((const float*)m)[i] != 0.0f;
        return m[i] != 0;
    };

    const int CH = SKVc / 256;   // 8 positions per thread
    for (int b = 0; b < Bc; ++b) {
        int base = b * SKVc + tid * CH;
        int c = 0;
#pragma unroll
        for (int k = 0; k < CH; ++k)
            if (!masked(base + k)) c++;
        sums[tid] = c;
        __syncthreads();
        if (tid == 0) {
            int a = 0;
            for (int i = 0; i < 256; ++i) { offs[i] = a; a += sums[i]; }
            offs[256] = a;
            g_cnt[b] = a;
        }
        __syncthreads();
        int o = b * SKVc + offs[tid];
#pragma unroll
        for (int k = 0; k < CH; ++k) {
            if (!masked(base + k)) {
                g_idx[o] = base + k;      // absolute row in [0, 4096)
                g_cbias[o] = 0.0f;
                o++;
            }
        }
        int total = offs[256];
        for (int j = total + tid; j < SKVc; j += 256) {
            g_idx[b * SKVc + j] = b * SKVc;   // safe duplicate row
            g_cbias[b * SKVc + j] = -1e30f;
        }
        __syncthreads();
    }
}

// ---------------- fused split (z-sliced; mode 1: fp16 hi/lo, 2: hi only) ------
struct SplitArgs {
    const float* src[6];
    fp16* hi[6];
    fp16* lo[6];
    int   n4[6];
    int   mode[6];
};
__global__ __launch_bounds__(256) void split_all(SplitArgs a) {
    int z = blockIdx.y;
    int i4 = blockIdx.x * 256 + threadIdx.x;
    if (i4 >= a.n4[z]) return;
    float4 v = ((const float4*)a.src[z])[i4];
    __half2 h0 = __floats2half2_rn(v.x, v.y);
    __half2 h1 = __floats2half2_rn(v.z, v.w);
    ((uint2*)a.hi[z])[i4] = make_uint2(h2u(h0), h2u(h1));
    if (a.mode[z] == 1) {
        uint32_t l0 = packhf(v.x - __half2float(__low2half(h0)),
                             v.y - __half2float(__high2half(h0)));
        uint32_t l1 = packhf(v.z - __half2float(__low2half(h1)),
                             v.w - __half2float(__high2half(h1)));
        ((uint2*)a.lo[z])[i4] = make_uint2(l0, l1);
    }
}

// ---------------- shared fp16 2-term GEMM body ----------------
#define F_AST 40
#define F_BST 136
#define F_STG 3
#define GEMM16_SMEM (F_STG * (128 * F_AST + 2 * 32 * F_BST) * (int)sizeof(fp16))

__device__ __forceinline__ void gemm_body(
    const fp16* __restrict__ Ah,
    const fp16* __restrict__ Wh, const fp16* __restrict__ Wl,
    const float* __restrict__ bias,
    fp16* __restrict__ Hh, float* __restrict__ Cf,
    int grow0, int grow1, int m0, int n0, int N, int K, char* sm)
{
    fp16* Ash = (fp16*)sm;                          // [3][128][F_AST]
    fp16* Bsh = Ash + F_STG * 128 * F_AST;          // [3][32][F_BST]
    fp16* Bsl = Bsh + F_STG * 32 * F_BST;

    int tid = threadIdx.x, lane = tid & 31, wid = tid >> 5;
    int wm = wid & 1, wn = wid >> 1;
    int r0 = tid >> 2, r1 = (tid + 256) >> 2;

    float acc[4][4][4];
#pragma unroll
    for (int i = 0; i < 4; i++)
#pragma unroll
        for (int j = 0; j < 4; j++)
#pragma unroll
            for (int e = 0; e < 4; e++) acc[i][j][e] = 0.0f;

    auto load_tiles = [&](int it, int s) {
        int k0 = it * 32;
        int kc0 = (tid & 3) * 8;
        cpa16(&Ash[(s * 128 + r0) * F_AST + kc0], Ah + (size_t)grow0 * K + k0 + kc0);
        cpa16(&Ash[(s * 128 + r1) * F_AST + kc0], Ah + (size_t)grow1 * K + k0 + kc0);
#pragma unroll
        for (int x = tid; x < 1024; x += 256) {       // B hi/lo: 32 x 128
            int mat = x >> 9, i = x & 511;
            int r = i >> 4, nc = (i & 15) * 8;
            const fp16* src = (mat ? Wl : Wh) + (size_t)(k0 + r) * N + n0 + nc;
            fp16* dst = (mat ? Bsl : Bsh) + (s * 32 + r) * F_BST + nc;
            cpa16(dst, src);
        }
    };

    int NIT = K / 32;
    load_tiles(0, 0); cp_commit();
    load_tiles(1, 1); cp_commit();

    int s = 0, s2 = 2;
    for (int it = 0; it < NIT; ++it) {
        if (it + 1 < NIT) cp_wait<1>(); else cp_wait<0>();
        __syncthreads();
        if (it + 2 < NIT) { load_tiles(it + 2, s2); cp_commit(); }

#pragma unroll
        for (int kk = 0; kk < 2; ++kk) {
            uint32_t a[4][4], bh[2][4], bl[2][4];
#pragma unroll
            for (int mt = 0; mt < 4; ++mt) {
                int idx = (s * 128 + wm * 64 + mt * 16 + (lane & 15)) * F_AST
                        + kk * 16 + (lane >> 4) * 8;
                ldm4(a[mt], &Ash[idx]);
            }
#pragma unroll
            for (int g = 0; g < 2; ++g) {
                int idx = (s * 32 + kk * 16 + (lane & 15)) * F_BST
                        + wn * 32 + g * 16 + (lane >> 4) * 8;
                ldm4t(bh[g], &Bsh[idx]);
                ldm4t(bl[g], &Bsl[idx]);
            }
#pragma unroll
            for (int mt = 0; mt < 4; ++mt)
#pragma unroll
                for (int g = 0; g < 2; ++g) {
                    uint32_t bh0[2] = { bh[g][0], bh[g][1] }, bh1[2] = { bh[g][2], bh[g][3] };
                    uint32_t bl0[2] = { bl[g][0], bl[g][1] }, bl1[2] = { bl[g][2], bl[g][3] };
                    mma16816h(acc[mt][2 * g],     a[mt], bh0);
                    mma16816h(acc[mt][2 * g],     a[mt], bl0);
                    mma16816h(acc[mt][2 * g + 1], a[mt], bh1);
                    mma16816h(acc[mt][2 * g + 1], a[mt], bl1);
                }
        }
        s  = (s  == 2) ? 0 : s + 1;
        s2 = (s2 == 2) ? 0 : s2 + 1;
    }

#pragma unroll
    for (int mt = 0; mt < 4; ++mt)
#pragma unroll
        for (int nt = 0; nt < 4; ++nt) {
            int row = m0 + wm * 64 + mt * 16 + (lane >> 2);
            int col = n0 + wn * 32 + nt * 8 + (lane & 3) * 2;
            float b0 = bias[col], b1 = bias[col + 1];
            float v00 = acc[mt][nt][0] + b0, v01 = acc[mt][nt][1] + b1;
            float v10 = acc[mt][nt][2] + b0, v11 = acc[mt][nt][3] + b1;
            size_t i0 = (size_t)row * N + col;
            size_t i1 = (size_t)(row + 8) * N + col;
            if (Cf) {
                *(float2*)(Cf + i0) = make_float2(v00, v01);
                *(float2*)(Cf + i1) = make_float2(v10, v11);
            } else {
                *(uint32_t*)(Hh + i0) = packhf(v00, v01);
                *(uint32_t*)(Hh + i1) = packhf(v10, v11);
            }
        }
}

// ---------------- fused Q/K/V projection (one launch, 3 segments) -------------
struct QKVArgs {
    const fp16* Wh[3];
    const fp16* Wl[3];
    const float* bias[3];
    fp16* out[3];
};
__global__ __launch_bounds__(256, 2) void qkv_gemm(QKVArgs a) {
    extern __shared__ char sm[];
    int seg = blockIdx.y >> 5;            // 0=Q, 1=K, 2=V
    int m0  = (blockIdx.y & 31) * 128;
    int n0  = blockIdx.x * 128;

    const fp16* Ah = (seg == 0) ? g_Xq16 : g_Xkv16;
    int grow0, grow1;
    int r0 = threadIdx.x >> 2, r1 = (threadIdx.x + 256) >> 2;
    if (seg == 0) {
        grow0 = m0 + r0; grow1 = m0 + r1;
    } else {
        if ((m0 & (SKVc - 1)) >= g_cnt[m0 >> 11]) return;   // tile past count
        grow0 = g_idx[m0 + r0]; grow1 = g_idx[m0 + r1];
    }
    gemm_body(Ah, a.Wh[seg], a.Wl[seg], a.bias[seg], a.out[seg], nullptr,
              grow0, grow1, m0, n0, Hc, Dc, sm);
}

// ---------------- O projection (fp32 out) ----------------
__global__ __launch_bounds__(256, 2) void gemm_f16(
    const fp16* __restrict__ Ah,
    const fp16* __restrict__ Wh, const fp16* __restrict__ Wl,
    const float* __restrict__ bias, float* __restrict__ Cf,
    int M, int N, int K)
{
    extern __shared__ char sm[];
    int m0 = blockIdx.y * 128, n0 = blockIdx.x * 128;
    int grow0 = m0 + (threadIdx.x >> 2), grow1 = m0 + ((threadIdx.x + 256) >> 2);
    gemm_body(Ah, Wh, Wl, bias, nullptr, Cf, grow0, grow1, m0, n0, N, K, sm);
}

// ---------------- fp16 hi-only flash attention over COMPACTED keys ------------
#define A_QST 72
#define A_KST 72
#define ATTN_SMEM ((128*A_QST + 2*2*64*A_KST) * (int)sizeof(fp16) + 2*64*(int)sizeof(float))

__global__ __launch_bounds__(256) void attn_mma(
    const fp16* __restrict__ Qh, const fp16* __restrict__ Kh,
    const fp16* __restrict__ Vh, fp16* __restrict__ Ao)
{
    extern __shared__ char sm[];
    fp16* Qs = (fp16*)sm;                         // [128][A_QST]
    fp16* Ks = Qs + 128 * A_QST;                  // [2][64][A_KST]
    fp16* Vs = Ks + 2 * 64 * A_KST;
    float* mbs = (float*)(Vs + 2 * 64 * A_KST);   // [2][64]

    int tid = threadIdx.x, lane = tid & 31, wid = tid >> 5;
    int q0 = blockIdx.x * 128, h = blockIdx.y, b = blockIdx.z;

    int cnt = g_cnt[b];
    int NT = (cnt + 63) >> 6;                      // >=1

#pragma unroll
    for (int c = tid; c < 1024; c += 256) {
        int r = c >> 3, col = (c & 7) * 8;
        size_t src = (size_t)(b * SQc + q0 + r) * Hc + h * HDc + col;
        cpa16(&Qs[r * A_QST + col], Qh + src);
    }
    cp_commit();

    auto load_kv = [&](int it, int buf) {
        int t0 = it * 64;
#pragma unroll
        for (int c = tid; c < 512; c += 256) {
            int r = c >> 3, col = (c & 7) * 8;
            size_t src = (size_t)(b * SKVc + t0 + r) * Hc + h * HDc + col;
            cpa16(&Ks[(buf * 64 + r) * A_KST + col], Kh + src);
            cpa16(&Vs[(buf * 64 + r) * A_KST + col], Vh + src);
        }
        if (tid < 16)
            cpa16(&mbs[buf * 64 + tid * 4], g_cbias + b * SKVc + t0 + tid * 4);
    };

    load_kv(0, 0);
    cp_commit();
    cp_wait<0>();
    __syncthreads();

    uint32_t qf[4][4];
    {
        int r = wid * 16 + (lane & 15);
#pragma unroll
        for (int kk = 0; kk < 4; ++kk)
            ldm4(qf[kk], &Qs[r * A_QST + kk * 16 + (lane >> 4) * 8]);
    }

    float o[8][4];
#pragma unroll
    for (int i = 0; i < 8; i++)
#pragma unroll
        for (int j = 0; j < 4; j++) o[i][j] = 0.0f;
    float m0r = -CUDART_INF_F, m1r = -CUDART_INF_F;
    float l0r = 0.0f, l1r = 0.0f;

    for (int it = 0; it < NT; ++it) {
        int buf = it & 1;
        if (it + 1 < NT) { load_kv(it + 1, buf ^ 1); cp_commit(); }

        float s[8][4];
#pragma unroll
        for (int i = 0; i < 8; i++)
#pragma unroll
            for (int j = 0; j < 4; j++) s[i][j] = 0.0f;

#pragma unroll
        for (int kk = 0; kk < 4; ++kk) {
#pragma unroll
            for (int g = 0; g < 4; ++g) {
                uint32_t kf[4];
                int idx = (buf * 64 + g * 16 + (lane & 15)) * A_KST
                        + kk * 16 + (lane >> 4) * 8;
                ldm4(kf, &Ks[idx]);
                uint32_t b0[2] = { kf[0], kf[2] }, b1[2] = { kf[1], kf[3] };
                mma16816h(s[2 * g],     qf[kk], b0);
                mma16816h(s[2 * g + 1], qf[kk], b1);
            }
        }

        float tm0 = -CUDART_INF_F, tm1 = -CUDART_INF_F;
#pragma unroll
        for (int nt = 0; nt < 8; ++nt) {
            int cb = nt * 8 + (lane & 3) * 2;
            float mb0 = mbs[buf * 64 + cb], mb1 = mbs[buf * 64 + cb + 1];
            s[nt][0] = s[nt][0] * 0.125f + mb0;
            s[nt][1] = s[nt][1] * 0.125f + mb1;
            s[nt][2] = s[nt][2] * 0.125f + mb0;
            s[nt][3] = s[nt][3] * 0.125f + mb1;
            tm0 = fmaxf(tm0, fmaxf(s[nt][0], s[nt][1]));
            tm1 = fmaxf(tm1, fmaxf(s[nt][2], s[nt][3]));
        }
        tm0 = fmaxf(tm0, __shfl_xor_sync(0xffffffffu, tm0, 1));
        tm0 = fmaxf(tm0, __shfl_xor_sync(0xffffffffu, tm0, 2));
        tm1 = fmaxf(tm1, __shfl_xor_sync(0xffffffffu, tm1, 1));
        tm1 = fmaxf(tm1, __shfl_xor_sync(0xffffffffu, tm1, 2));
        float mn0 = fmaxf(m0r, tm0), mn1 = fmaxf(m1r, tm1);
        float al0 = __expf(m0r - mn0), al1 = __expf(m1r - mn1);
        m0r = mn0; m1r = mn1;

        float rs0 = 0.0f, rs1 = 0.0f;
#pragma unroll
        for (int nt = 0; nt < 8; ++nt) {
            s[nt][0] = __expf(s[nt][0] - mn0);
            s[nt][1] = __expf(s[nt][1] - mn0);
            s[nt][2] = __expf(s[nt][2] - mn1);
            s[nt][3] = __expf(s[nt][3] - mn1);
            rs0 += s[nt][0] + s[nt][1];
            rs1 += s[nt][2] + s[nt][3];
        }
        rs0 += __shfl_xor_sync(0xffffffffu, rs0, 1);
        rs0 += __shfl_xor_sync(0xffffffffu, rs0, 2);
        rs1 += __shfl_xor_sync(0xffffffffu, rs1, 1);
        rs1 += __shfl_xor_sync(0xffffffffu, rs1, 2);
        l0r = l0r * al0 + rs0;
        l1r = l1r * al1 + rs1;

#pragma unroll
        for (int dn = 0; dn < 8; ++dn) {
            o[dn][0] *= al0; o[dn][1] *= al0;
            o[dn][2] *= al1; o[dn][3] *= al1;
        }

#pragma unroll
        for (int kt = 0; kt < 4; ++kt) {
            uint32_t pah[4] = {
                packhf(s[2 * kt][0],     s[2 * kt][1]),
                packhf(s[2 * kt][2],     s[2 * kt][3]),
                packhf(s[2 * kt + 1][0], s[2 * kt + 1][1]),
                packhf(s[2 * kt + 1][2], s[2 * kt + 1][3])
            };
#pragma unroll
            for (int dg = 0; dg < 4; ++dg) {
                uint32_t vf[4];
                int idx = (buf * 64 + kt * 16 + (lane & 15)) * A_KST
                        + dg * 16 + (lane >> 4) * 8;
                ldm4t(vf, &Vs[idx]);
                uint32_t b0[2] = { vf[0], vf[1] }, b1[2] = { vf[2], vf[3] };
                mma16816h(o[2 * dg],     pah, b0);
                mma16816h(o[2 * dg + 1], pah, b1);
            }
        }

        if (it + 1 < NT) {
            cp_wait<0>();
            __syncthreads();
        }
    }

    float inv0 = 1.0f / l0r, inv1 = 1.0f / l1r;
#pragma unroll
    for (int dn = 0; dn < 8; ++dn) {
        int row = q0 + wid * 16 + (lane >> 2);
        int col = h * HDc + dn * 8 + (lane & 3) * 2;
        size_t i0 = (size_t)(b * SQc + row) * Hc + col;
        size_t i1 = (size_t)(b * SQc + row + 8) * Hc + col;
        *(uint32_t*)(Ao + i0) = packhf(o[dn][0] * inv0, o[dn][1] * inv0);
        *(uint32_t*)(Ao + i1) = packhf(o[dn][2] * inv1, o[dn][3] * inv1);
    }
}

// ---------------- launch ----------------
// Order: mask(1), split(2), qkv(3), attn(4), O(5)
extern "C" void kernel_launch(void* const* d_in, const int* in_sizes, int n_in,
                              void* d_out, int out_size)
{
    (void)in_sizes; (void)n_in; (void)out_size;

    fp16 *Xq16, *Xkv16, *Wq16h, *Wq16l, *Wk16h, *Wk16l, *Wv16h, *Wv16l;
    fp16 *Wo16h, *Wo16l, *Q16, *K16, *V16, *A16;
    cudaGetSymbolAddress((void**)&Xq16, g_Xq16);
    cudaGetSymbolAddress((void**)&Xkv16, g_Xkv16);
    cudaGetSymbolAddress((void**)&Wq16h, g_Wq16h); cudaGetSymbolAddress((void**)&Wq16l, g_Wq16l);
    cudaGetSymbolAddress((void**)&Wk16h, g_Wk16h); cudaGetSymbolAddress((void**)&Wk16l, g_Wk16l);
    cudaGetSymbolAddress((void**)&Wv16h, g_Wv16h); cudaGetSymbolAddress((void**)&Wv16l, g_Wv16l);
    cudaGetSymbolAddress((void**)&Wo16h, g_Wo16h); cudaGetSymbolAddress((void**)&Wo16l, g_Wo16l);
    cudaGetSymbolAddress((void**)&Q16, g_Q16);
    cudaGetSymbolAddress((void**)&K16, g_K16);
    cudaGetSymbolAddress((void**)&V16, g_V16);
    cudaGetSymbolAddress((void**)&A16, g_A16);

    cudaFuncSetAttribute(qkv_gemm, cudaFuncAttributeMaxDynamicSharedMemorySize, GEMM16_SMEM);
    cudaFuncSetAttribute(gemm_f16, cudaFuncAttributeMaxDynamicSharedMemorySize, GEMM16_SMEM);
    cudaFuncSetAttribute(attn_mma, cudaFuncAttributeMaxDynamicSharedMemorySize, ATTN_SMEM);

    // (1) mask + compaction
    mask_kernel<<<1, 256>>>((const unsigned char*)d_in[2]);

    // (2) all splits in one launch
    SplitArgs sa;
    sa.src[0] = (const float*)d_in[0]; sa.hi[0] = Xq16;  sa.lo[0] = nullptr; sa.n4[0] = Mrows * Dc / 4; sa.mode[0] = 2;
    sa.src[1] = (const float*)d_in[1]; sa.hi[1] = Xkv16; sa.lo[1] = nullptr; sa.n4[1] = Mrows * Dc / 4; sa.mode[1] = 2;
    sa.src[2] = (const float*)d_in[3]; sa.hi[2] = Wq16h; sa.lo[2] = Wq16l;  sa.n4[2] = Dc * Hc / 4;    sa.mode[2] = 1;
    sa.src[3] = (const float*)d_in[5]; sa.hi[3] = Wk16h; sa.lo[3] = Wk16l;  sa.n4[3] = Dc * Hc / 4;    sa.mode[3] = 1;
    sa.src[4] = (const float*)d_in[7]; sa.hi[4] = Wv16h; sa.lo[4] = Wv16l;  sa.n4[4] = Dc * Hc / 4;    sa.mode[4] = 1;
    sa.src[5] = (const float*)d_in[9]; sa.hi[5] = Wo16h; sa.lo[5] = Wo16l;  sa.n4[5] = Hc * Dc / 4;    sa.mode[5] = 1;
    split_all<<<dim3((Mrows * Dc / 4 + 255) / 256, 6), 256>>>(sa);

    // (3) fused Q/K/V projections (K/V segments early-exit past count)
    QKVArgs qa;
    qa.Wh[0] = Wq16h; qa.Wl[0] = Wq16l; qa.bias[0] = (const float*)d_in[4];  qa.out[0] = Q16;
    qa.Wh[1] = Wk16h; qa.Wl[1] = Wk16l; qa.bias[1] = (const float*)d_in[6];  qa.out[1] = K16;
    qa.Wh[2] = Wv16h; qa.Wl[2] = Wv16l; qa.bias[2] = (const float*)d_in[8];  qa.out[2] = V16;
    qkv_gemm<<<dim3(Hc / 128, 96), 256, GEMM16_SMEM>>>(qa);

    // (4) attention over compacted keys
    attn_mma<<<dim3(SQc / 128, NHc, Bc), 256, ATTN_SMEM>>>(Q16, K16, V16, A16);

    // (5) output projection: fp16 2-term, fp32 out
    dim3 og(Dc / 128, Mrows / 128);   // (8, 32)
    gemm_f16<<<og, 256, GEMM16_SMEM>>>(A16, Wo16h, Wo16l, (const float*)d_in[10],
                                       (float*)d_out, Mrows, Dc, Hc);
}